// round 9
// baseline (speedup 1.0000x reference)
#include <cuda_runtime.h>
#include <cuda_fp16.h>
#include <math.h>
#include <stdint.h>

// Problem constants
#define BB 2
#define TT 2048
#define CC 2048
#define HH 16
#define KEY_DIM 2048
#define VALUE_DIM 2048
#define CONV_DIM 6144
#define QKVZ_N 8192
#define BT 4096   // B*T

// ---------------- scratch (static device globals; no allocation) -------------
__device__ float g_qkvz[(size_t)BT * QKVZ_N];   // 128 MiB
__device__ float g_y[(size_t)BT * CONV_DIM];    // 96 MiB
__device__ float g_beta[(size_t)BT * HH];
__device__ float g_alpha[(size_t)BT * HH];
__device__ float g_att[(size_t)BT * VALUE_DIM]; // 32 MiB
__device__ __half g_xh[(size_t)BT * CC];        // x in fp16
__device__ __half g_wqt[(size_t)QKVZ_N * CC];   // W_qkvz^T fp16 [N][K]
__device__ __half g_wot[(size_t)CC * CC];       // W_out^T fp16 [N][K]
__device__ __half g_goh[(size_t)BT * CC];       // gated output fp16

// ---------------- PTX helpers ------------------------------------------------
__device__ __forceinline__ uint32_t s2u(const void* p) {
    uint32_t a;
    asm("{ .reg .u64 t; cvta.to.shared.u64 t, %1; cvt.u32.u64 %0, t; }"
        : "=r"(a) : "l"(p));
    return a;
}
__device__ __forceinline__ void ldsm4(uint32_t* r, uint32_t addr) {
    asm volatile("ldmatrix.sync.aligned.m8n8.x4.shared.b16 {%0,%1,%2,%3}, [%4];"
                 : "=r"(r[0]), "=r"(r[1]), "=r"(r[2]), "=r"(r[3]) : "r"(addr));
}
__device__ __forceinline__ void mma168f16(float* d, const uint32_t* a,
                                          const uint32_t* b) {
    asm volatile(
        "mma.sync.aligned.m16n8k16.row.col.f32.f16.f16.f32 "
        "{%0,%1,%2,%3}, {%4,%5,%6,%7}, {%8,%9}, {%0,%1,%2,%3};\n"
        : "+f"(d[0]), "+f"(d[1]), "+f"(d[2]), "+f"(d[3])
        : "r"(a[0]), "r"(a[1]), "r"(a[2]), "r"(a[3]),
          "r"(b[0]), "r"(b[1]));
}
__device__ __forceinline__ void cpasync16(uint32_t dst, const void* src) {
    asm volatile("cp.async.ca.shared.global [%0], [%1], 16;"
                 :: "r"(dst), "l"(src));
}
__device__ __forceinline__ void cpasync4(uint32_t dst, const void* src) {
    asm volatile("cp.async.ca.shared.global [%0], [%1], 4;"
                 :: "r"(dst), "l"(src));
}
__device__ __forceinline__ void cp_commit() {
    asm volatile("cp.async.commit_group;");
}
__device__ __forceinline__ void cp_wait4() {
    asm volatile("cp.async.wait_group 4;" ::: "memory");
}

// ---------------- fp16 tensor-core GEMM --------------------------------------
// C[M,N] = A[M,K] * B^T, A fp16 row-major [M][K], B fp16 [N][K].
// CTA tile 128x256, BK=32, 256 threads, 8 warps (2x4), warp tile 64x64.
#define STAGE_B 30720
#define GEMM_SMEM (2 * STAGE_B)

__global__ void __launch_bounds__(256)
h16gemm(const __half* __restrict__ A, const __half* __restrict__ Bt,
        float* __restrict__ Cm, int M, int N, int Kd)
{
    extern __shared__ char smem[];
    const uint32_t sb = s2u(smem);
    const int tid  = threadIdx.x;
    const int bm   = blockIdx.y * 128;
    const int bn   = blockIdx.x * 256;
    const int lane = tid & 31;
    const int warp = tid >> 5;
    const int wm   = (warp >> 2) * 64;
    const int wn   = (warp & 3) * 64;
    const int gid  = lane >> 2;
    const int tig  = lane & 3;

    const int lr = tid >> 2;
    const int lc = tid & 3;

    const __half* Ap = A  + (size_t)(bm + lr) * Kd + lc * 8;
    const __half* Bp = Bt + (size_t)(bn + lr) * Kd + lc * 8;
    const size_t a64 = (size_t)64 * Kd;

    float acc[4][8][4];
    #pragma unroll
    for (int i = 0; i < 4; i++)
        #pragma unroll
        for (int j = 0; j < 8; j++)
            #pragma unroll
            for (int r = 0; r < 4; r++) acc[i][j][r] = 0.f;

    {
        uint4 ra0 = *(const uint4*)Ap;
        uint4 ra1 = *(const uint4*)(Ap + a64);
        uint4 rb0 = *(const uint4*)Bp;
        uint4 rb1 = *(const uint4*)(Bp + a64);
        uint4 rb2 = *(const uint4*)(Bp + 2 * a64);
        uint4 rb3 = *(const uint4*)(Bp + 3 * a64);
        char* s0 = smem;
        *(uint4*)(s0 + lr * 80 + lc * 16)        = ra0;
        *(uint4*)(s0 + (lr + 64) * 80 + lc * 16) = ra1;
        char* s0b = s0 + 10240;
        *(uint4*)(s0b + lr * 80 + lc * 16)         = rb0;
        *(uint4*)(s0b + (lr + 64) * 80 + lc * 16)  = rb1;
        *(uint4*)(s0b + (lr + 128) * 80 + lc * 16) = rb2;
        *(uint4*)(s0b + (lr + 192) * 80 + lc * 16) = rb3;
    }
    __syncthreads();

    const int at = lane >> 3;
    const int arow = wm + (at & 1) * 8 + (lane & 7);
    const int akoff = (lane >> 4) * 16;
    const int brow = wn + (lane >> 4) * 8 + (lane & 7);
    const int bkoff = ((lane >> 3) & 1) * 16;

    const int nst = Kd / 32;
    for (int s = 0; s < nst; s++) {
        const bool more = (s + 1) < nst;
        uint4 ra0, ra1, rb0, rb1, rb2, rb3;
        if (more) {
            Ap += 32; Bp += 32;
            ra0 = *(const uint4*)Ap;
            ra1 = *(const uint4*)(Ap + a64);
            rb0 = *(const uint4*)Bp;
            rb1 = *(const uint4*)(Bp + a64);
            rb2 = *(const uint4*)(Bp + 2 * a64);
            rb3 = *(const uint4*)(Bp + 3 * a64);
        }

        const uint32_t base = sb + (uint32_t)(s & 1) * STAGE_B;
        #pragma unroll
        for (int ks = 0; ks < 2; ks++) {
            uint32_t aF[4][4], bF[4][4];
            const uint32_t ak = base + (uint32_t)(ks * 32 + akoff);
            #pragma unroll
            for (int mt = 0; mt < 4; mt++)
                ldsm4(aF[mt], ak + (uint32_t)(arow + mt * 16) * 80);
            const uint32_t bk = base + 10240u + (uint32_t)(ks * 32 + bkoff);
            #pragma unroll
            for (int np = 0; np < 4; np++)
                ldsm4(bF[np], bk + (uint32_t)(brow + np * 16) * 80);
            #pragma unroll
            for (int mt = 0; mt < 4; mt++)
                #pragma unroll
                for (int nt = 0; nt < 8; nt++)
                    mma168f16(acc[mt][nt], aF[mt], &bF[nt >> 1][(nt & 1) * 2]);
        }

        if (more) {
            char* sn = smem + ((s + 1) & 1) * STAGE_B;
            *(uint4*)(sn + lr * 80 + lc * 16)        = ra0;
            *(uint4*)(sn + (lr + 64) * 80 + lc * 16) = ra1;
            char* snb = sn + 10240;
            *(uint4*)(snb + lr * 80 + lc * 16)         = rb0;
            *(uint4*)(snb + (lr + 64) * 80 + lc * 16)  = rb1;
            *(uint4*)(snb + (lr + 128) * 80 + lc * 16) = rb2;
            *(uint4*)(snb + (lr + 192) * 80 + lc * 16) = rb3;
        }
        __syncthreads();
    }

    #pragma unroll
    for (int mt = 0; mt < 4; mt++) {
        const int row = bm + wm + mt * 16 + gid;
        #pragma unroll
        for (int nt = 0; nt < 8; nt++) {
            const int col = bn + wn + nt * 8 + 2 * tig;
            *(float2*)&Cm[(size_t)row * N + col]       = make_float2(acc[mt][nt][0], acc[mt][nt][1]);
            *(float2*)&Cm[(size_t)(row + 8) * N + col] = make_float2(acc[mt][nt][2], acc[mt][nt][3]);
        }
    }
}

// ---------------- f32 -> f16 convert -----------------------------------------
__global__ void __launch_bounds__(256)
to_half(const float* __restrict__ X, __half* __restrict__ Y, int n8)
{
    int i = blockIdx.x * 256 + threadIdx.x;
    if (i >= n8) return;
    float4 v0 = ((const float4*)X)[i * 2];
    float4 v1 = ((const float4*)X)[i * 2 + 1];
    __half2* H = (__half2*)Y;
    H[i * 4 + 0] = __floats2half2_rn(v0.x, v0.y);
    H[i * 4 + 1] = __floats2half2_rn(v0.z, v0.w);
    H[i * 4 + 2] = __floats2half2_rn(v1.x, v1.y);
    H[i * 4 + 3] = __floats2half2_rn(v1.z, v1.w);
}

// ---------------- transpose: W[K][N] f32 -> Wt[N][K] f16 ---------------------
__global__ void __launch_bounds__(256)
transpose_half(const float* __restrict__ W, __half* __restrict__ Th, int K, int N)
{
    __shared__ float tile[32][33];
    const int k0 = blockIdx.y * 32, n0 = blockIdx.x * 32;
    const int tx = threadIdx.x & 31, ty = threadIdx.x >> 5;
    #pragma unroll
    for (int r = 0; r < 32; r += 8)
        tile[ty + r][tx] = W[(size_t)(k0 + ty + r) * N + n0 + tx];
    __syncthreads();
    #pragma unroll
    for (int r = 0; r < 32; r += 8)
        Th[(size_t)(n0 + ty + r) * K + k0 + tx] = __float2half(tile[tx][ty + r]);
}

// ---------------- beta/alpha: sigmoid(x @ W_b), sigmoid(x @ W_a) -------------
__global__ void __launch_bounds__(128)
ba_kernel(const float* __restrict__ x, const float* __restrict__ Wb,
          const float* __restrict__ Wa, float* __restrict__ beta,
          float* __restrict__ alpha)
{
    __shared__ float xs[CC];
    const int row = blockIdx.x;
    const float* xr = x + (size_t)row * CC;
    for (int i = threadIdx.x; i < CC; i += 128) xs[i] = xr[i];
    __syncthreads();

    const int g = threadIdx.x >> 2;
    const int l = threadIdx.x & 3;
    const float* W = (g < 16) ? Wb : Wa;
    const int h = g & 15;
    float s = 0.f;
    for (int cidx = l; cidx < CC; cidx += 4)
        s = fmaf(xs[cidx], W[cidx * HH + h], s);
    s += __shfl_down_sync(0xffffffffu, s, 2);
    s += __shfl_down_sync(0xffffffffu, s, 1);
    if (l == 0) {
        float v = 1.f / (1.f + expf(-s));
        if (g < 16) beta[(size_t)row * HH + h] = v;
        else        alpha[(size_t)row * HH + h] = v;
    }
}

// ---------------- causal depthwise conv(K=4) + silu + l2norm of q,k ----------
__global__ void __launch_bounds__(256)
conv_kernel(const float* __restrict__ qkvz, const float* __restrict__ conv_w,
            const float* __restrict__ conv_state, const int* __restrict__ input_pos,
            float* __restrict__ y_out)
{
    __shared__ float ybuf[CONV_DIM];
    __shared__ float norms[32];

    const int bt = blockIdx.x;
    const int b = bt >> 11;
    const int t = bt & 2047;
    const float keep = (input_pos[0] == 0) ? 0.f : 1.f;

    for (int c = threadIdx.x; c < CONV_DIM; c += 256) {
        float4 w = *(const float4*)&conv_w[c * 4];
        float in[4];
        #pragma unroll
        for (int j = 0; j < 4; j++) {
            int tau = t + j - 3;
            float v;
            if (tau >= 0) v = qkvz[((size_t)(b * TT + tau)) * QKVZ_N + c];
            else          v = keep * conv_state[((size_t)b * CONV_DIM + c) * 4 + (t + 1 + j)];
            in[j] = v;
        }
        float acc = in[0] * w.x + in[1] * w.y + in[2] * w.z + in[3] * w.w;
        float sig = 1.f / (1.f + expf(-acc));
        ybuf[c] = acc * sig;
    }
    __syncthreads();

    const int wid = threadIdx.x >> 5;
    const int lane = threadIdx.x & 31;
    for (int hh = wid; hh < 32; hh += 8) {
        int base = (hh < 16) ? hh * 128 : KEY_DIM + (hh - 16) * 128;
        float ss = 0.f;
        #pragma unroll
        for (int i = 0; i < 4; i++) {
            float v = ybuf[base + lane + i * 32];
            ss = fmaf(v, v, ss);
        }
        #pragma unroll
        for (int off = 16; off > 0; off >>= 1)
            ss += __shfl_xor_sync(0xffffffffu, ss, off);
        if (lane == 0) norms[hh] = fmaxf(sqrtf(ss), 1e-12f);
    }
    __syncthreads();

    float* yr = y_out + (size_t)bt * CONV_DIM;
    for (int c = threadIdx.x; c < CONV_DIM; c += 256) {
        float v = ybuf[c];
        if (c < 2 * KEY_DIM) v /= norms[c >> 7];
        yr[c] = v;
    }
}

// ---------------- gated linear-attention recurrence --------------------------
// grid (4, 32). 8-slot cp.async ring, prefetch t+4, wait_group 4.
// Thread layout: warp w owns dv = w*4 + oct (oct = lane>>3); each thread holds
// dk = ol*4 + 32*j + c (ol = lane&7, j=0..3, c=0..3) -> 16 state values.
// dk-reduction of output is within an 8-lane octet via shfl (no smem, 1 bar/step).
__global__ void __launch_bounds__(256)
recur_kernel(const float* __restrict__ y, const float* __restrict__ beta,
             const float* __restrict__ alpha, const float* __restrict__ rstate,
             const int* __restrict__ input_pos, float* __restrict__ att)
{
    // per slot: q[0..127], k[128..255], v[256..287], a@288, b@289 (stride 296)
    __shared__ float buf[8][296];

    const int bh = blockIdx.y;
    const int b = bh >> 4, h = bh & 15;
    const int dvb = blockIdx.x * 32;
    const int tid = threadIdx.x;
    const int lane = tid & 31;
    const int w   = tid >> 5;
    const int oct = lane >> 3;      // 0..3
    const int ol  = lane & 7;       // 0..7
    const int dvl = w * 4 + oct;    // 0..31
    const int dv  = dvb + dvl;
    const float keep = (input_pos[0] == 0) ? 0.f : 1.f;
    const uint32_t sb = s2u(&buf[0][0]);

    float s[16];
    #pragma unroll
    for (int j = 0; j < 4; j++)
        #pragma unroll
        for (int c = 0; c < 4; c++) {
            int dk = ol * 4 + 32 * j + c;
            s[j * 4 + c] = keep * rstate[((size_t)bh * 128 + dk) * 128 + dv];
        }

    const float* ybase = y + (size_t)b * TT * CONV_DIM + h * 128;
    const float* arow = alpha + (size_t)b * TT * HH + h;
    const float* brow = beta  + (size_t)b * TT * HH + h;

    // prefetch: threads 0..31 q, 32..63 k, 64..71 v, 72 a, 73 b
    auto issue = [&](int t) {
        if (t < TT) {
            const uint32_t dst = sb + (uint32_t)(t & 7) * (296 * 4);
            const float* yr = ybase + (size_t)t * CONV_DIM;
            if (tid < 32) {
                cpasync16(dst + tid * 16, yr + tid * 4);
            } else if (tid < 64) {
                cpasync16(dst + tid * 16, yr + KEY_DIM + (tid - 32) * 4);
            } else if (tid < 72) {
                cpasync16(dst + 256 * 4 + (tid - 64) * 16, yr + 2 * KEY_DIM + dvb + (tid - 64) * 4);
            } else if (tid == 72) {
                cpasync4(dst + 288 * 4, arow + (size_t)t * HH);
            } else if (tid == 73) {
                cpasync4(dst + 289 * 4, brow + (size_t)t * HH);
            }
        }
        cp_commit();
    };

    issue(0); issue(1); issue(2); issue(3);

    for (int t = 0; t < TT; t++) {
        issue(t + 4);
        cp_wait4();
        __syncthreads();

        const float* bp = &buf[t & 7][0];
        const float a   = bp[288];
        const float bta = bp[289];
        const float bv  = bta * bp[256 + dvl];
        float po = 0.f;
        #pragma unroll
        for (int j = 0; j < 4; j++) {
            const float4 kv = *(const float4*)(bp + 128 + ol * 4 + 32 * j);
            const float4 qv = *(const float4*)(bp + ol * 4 + 32 * j);
            float* sj = &s[j * 4];
            sj[0] = fmaf(a, sj[0], bv * kv.x);  po = fmaf(qv.x, sj[0], po);
            sj[1] = fmaf(a, sj[1], bv * kv.y);  po = fmaf(qv.y, sj[1], po);
            sj[2] = fmaf(a, sj[2], bv * kv.z);  po = fmaf(qv.z, sj[2], po);
            sj[3] = fmaf(a, sj[3], bv * kv.w);  po = fmaf(qv.w, sj[3], po);
        }
        // reduce over the 8-lane octet (same dv)
        po += __shfl_xor_sync(0xffffffffu, po, 1);
        po += __shfl_xor_sync(0xffffffffu, po, 2);
        po += __shfl_xor_sync(0xffffffffu, po, 4);
        if (ol == 0)
            att[((size_t)(b * TT + t)) * VALUE_DIM + h * 128 + dv] = po;
    }
}

// ---------------- rmsnorm * norm_w * sigmoid(z) -> fp16 ----------------------
__global__ void __launch_bounds__(256)
gate_kernel(const float* __restrict__ att, const float* __restrict__ qkvz,
            const float* __restrict__ norm_w, __half* __restrict__ goh)
{
    const int bt = blockIdx.x;
    const int wid = threadIdx.x >> 5;
    const int lane = threadIdx.x & 31;

    #pragma unroll
    for (int k = 0; k < 2; k++) {
        const int hh = wid * 2 + k;
        const float* ar = att + (size_t)bt * VALUE_DIM + hh * 128;
        float v[4];
        float ss = 0.f;
        #pragma unroll
        for (int i = 0; i < 4; i++) {
            v[i] = ar[lane + i * 32];
            ss = fmaf(v[i], v[i], ss);
        }
        #pragma unroll
        for (int off = 16; off > 0; off >>= 1)
            ss += __shfl_xor_sync(0xffffffffu, ss, off);
        float scale = rsqrtf(ss * (1.f / 128.f) + 1e-6f);
        const float* zr = qkvz + (size_t)bt * QKVZ_N + CONV_DIM + hh * 128;
        __half* gr = goh + (size_t)bt * VALUE_DIM + hh * 128;
        #pragma unroll
        for (int i = 0; i < 4; i++) {
            int dvi = lane + i * 32;
            float z = zr[dvi];
            float sig = 1.f / (1.f + expf(-z));
            gr[dvi] = __float2half(v[i] * scale * norm_w[dvi] * sig);
        }
    }
}

// ---------------- launch -----------------------------------------------------
extern "C" void kernel_launch(void* const* d_in, const int* in_sizes, int n_in,
                              void* d_out, int out_size)
{
    const float* x          = (const float*)d_in[0];
    const int*   input_pos  = (const int*)  d_in[1];
    const float* W_qkvz     = (const float*)d_in[2];
    const float* W_b        = (const float*)d_in[3];
    const float* W_a        = (const float*)d_in[4];
    const float* conv_w     = (const float*)d_in[5];
    const float* norm_w     = (const float*)d_in[6];
    const float* W_out      = (const float*)d_in[7];
    const float* conv_state = (const float*)d_in[8];
    const float* rec_state  = (const float*)d_in[9];
    float* out = (float*)d_out;

    float *qkvz, *y, *beta, *alpha, *attb;
    __half *xh, *wqt, *wot, *goh;
    cudaGetSymbolAddress((void**)&qkvz, g_qkvz);
    cudaGetSymbolAddress((void**)&y,    g_y);
    cudaGetSymbolAddress((void**)&beta, g_beta);
    cudaGetSymbolAddress((void**)&alpha,g_alpha);
    cudaGetSymbolAddress((void**)&attb, g_att);
    cudaGetSymbolAddress((void**)&xh,  g_xh);
    cudaGetSymbolAddress((void**)&wqt, g_wqt);
    cudaGetSymbolAddress((void**)&wot, g_wot);
    cudaGetSymbolAddress((void**)&goh, g_goh);

    cudaFuncSetAttribute(h16gemm, cudaFuncAttributeMaxDynamicSharedMemorySize,
                         GEMM_SMEM);

    // 0) operand prep
    to_half<<<(BT * CC / 8 + 255) / 256, 256>>>(x, xh, BT * CC / 8);
    transpose_half<<<dim3(QKVZ_N / 32, CC / 32), 256>>>(W_qkvz, wqt, CC, QKVZ_N);
    transpose_half<<<dim3(CC / 32, CC / 32), 256>>>(W_out, wot, CC, CC);

    // 1) qkvz = x @ W_qkvz  (fp16 mma.m16n8k16)
    h16gemm<<<dim3(QKVZ_N / 256, BT / 128), 256, GEMM_SMEM>>>(
        xh, wqt, qkvz, BT, QKVZ_N, CC);
    // 2) beta/alpha
    ba_kernel<<<BT, 128>>>(x, W_b, W_a, beta, alpha);
    // 3) conv + silu + l2norm
    conv_kernel<<<BT, 256>>>(qkvz, conv_w, conv_state, input_pos, y);
    // 4) recurrence (deep cp.async ring + shfl reduction)
    recur_kernel<<<dim3(4, 32), 256>>>(y, beta, alpha, rec_state, input_pos, attb);
    // 5) rmsnorm + gate -> fp16
    gate_kernel<<<BT, 256>>>(attb, qkvz, norm_w, goh);
    // 6) out = gated @ W_out  (fp16 mma.m16n8k16)
    h16gemm<<<dim3(CC / 256, BT / 128), 256, GEMM_SMEM>>>(
        goh, wot, out, BT, CC, CC);
}

// round 10
// speedup vs baseline: 1.2523x; 1.2523x over previous
#include <cuda_runtime.h>
#include <cuda_fp16.h>
#include <math.h>
#include <stdint.h>

// Problem constants
#define BB 2
#define TT 2048
#define CC 2048
#define HH 16
#define KEY_DIM 2048
#define VALUE_DIM 2048
#define CONV_DIM 6144
#define QKVZ_N 8192
#define BT 4096   // B*T
#define LCH 64
#define NCH (TT / LCH)   // 32 chunks
#define BH 32            // B*H

// ---------------- scratch (static device globals; no allocation) -------------
__device__ float g_qkvz[(size_t)BT * QKVZ_N];   // 128 MiB
__device__ float g_y[(size_t)BT * CONV_DIM];    // 96 MiB
__device__ float g_beta[(size_t)BT * HH];
__device__ float g_alpha[(size_t)BT * HH];
__device__ float g_att[(size_t)BT * VALUE_DIM]; // 32 MiB
__device__ __half g_xh[(size_t)BT * CC];
__device__ __half g_wqt[(size_t)QKVZ_N * CC];
__device__ __half g_wot[(size_t)CC * CC];
__device__ __half g_goh[(size_t)BT * CC];
__device__ float g_sinc[(size_t)BH * NCH * 16384]; // 64 MiB per-chunk state increments
__device__ float g_spre[(size_t)BH * NCH * 16384]; // 64 MiB chunk-entry states
__device__ float g_cc[(size_t)BH * TT];            // cumsum log2(a), chunk-local

// ---------------- PTX helpers ------------------------------------------------
__device__ __forceinline__ uint32_t s2u(const void* p) {
    uint32_t a;
    asm("{ .reg .u64 t; cvta.to.shared.u64 t, %1; cvt.u32.u64 %0, t; }"
        : "=r"(a) : "l"(p));
    return a;
}
__device__ __forceinline__ void ldsm4(uint32_t* r, uint32_t addr) {
    asm volatile("ldmatrix.sync.aligned.m8n8.x4.shared.b16 {%0,%1,%2,%3}, [%4];"
                 : "=r"(r[0]), "=r"(r[1]), "=r"(r[2]), "=r"(r[3]) : "r"(addr));
}
__device__ __forceinline__ void mma168f16(float* d, const uint32_t* a,
                                          const uint32_t* b) {
    asm volatile(
        "mma.sync.aligned.m16n8k16.row.col.f32.f16.f16.f32 "
        "{%0,%1,%2,%3}, {%4,%5,%6,%7}, {%8,%9}, {%0,%1,%2,%3};\n"
        : "+f"(d[0]), "+f"(d[1]), "+f"(d[2]), "+f"(d[3])
        : "r"(a[0]), "r"(a[1]), "r"(a[2]), "r"(a[3]),
          "r"(b[0]), "r"(b[1]));
}

// ---------------- fp16 tensor-core GEMM (unchanged from R8) ------------------
#define STAGE_B 30720
#define GEMM_SMEM (2 * STAGE_B)

__global__ void __launch_bounds__(256)
h16gemm(const __half* __restrict__ A, const __half* __restrict__ Bt,
        float* __restrict__ Cm, int M, int N, int Kd)
{
    extern __shared__ char smem[];
    const uint32_t sb = s2u(smem);
    const int tid  = threadIdx.x;
    const int bm   = blockIdx.y * 128;
    const int bn   = blockIdx.x * 256;
    const int lane = tid & 31;
    const int warp = tid >> 5;
    const int wm   = (warp >> 2) * 64;
    const int wn   = (warp & 3) * 64;
    const int gid  = lane >> 2;
    const int tig  = lane & 3;

    const int lr = tid >> 2;
    const int lc = tid & 3;

    const __half* Ap = A  + (size_t)(bm + lr) * Kd + lc * 8;
    const __half* Bp = Bt + (size_t)(bn + lr) * Kd + lc * 8;
    const size_t a64 = (size_t)64 * Kd;

    float acc[4][8][4];
    #pragma unroll
    for (int i = 0; i < 4; i++)
        #pragma unroll
        for (int j = 0; j < 8; j++)
            #pragma unroll
            for (int r = 0; r < 4; r++) acc[i][j][r] = 0.f;

    {
        uint4 ra0 = *(const uint4*)Ap;
        uint4 ra1 = *(const uint4*)(Ap + a64);
        uint4 rb0 = *(const uint4*)Bp;
        uint4 rb1 = *(const uint4*)(Bp + a64);
        uint4 rb2 = *(const uint4*)(Bp + 2 * a64);
        uint4 rb3 = *(const uint4*)(Bp + 3 * a64);
        char* s0 = smem;
        *(uint4*)(s0 + lr * 80 + lc * 16)        = ra0;
        *(uint4*)(s0 + (lr + 64) * 80 + lc * 16) = ra1;
        char* s0b = s0 + 10240;
        *(uint4*)(s0b + lr * 80 + lc * 16)         = rb0;
        *(uint4*)(s0b + (lr + 64) * 80 + lc * 16)  = rb1;
        *(uint4*)(s0b + (lr + 128) * 80 + lc * 16) = rb2;
        *(uint4*)(s0b + (lr + 192) * 80 + lc * 16) = rb3;
    }
    __syncthreads();

    const int at = lane >> 3;
    const int arow = wm + (at & 1) * 8 + (lane & 7);
    const int akoff = (lane >> 4) * 16;
    const int brow = wn + (lane >> 4) * 8 + (lane & 7);
    const int bkoff = ((lane >> 3) & 1) * 16;

    const int nst = Kd / 32;
    for (int s = 0; s < nst; s++) {
        const bool more = (s + 1) < nst;
        uint4 ra0, ra1, rb0, rb1, rb2, rb3;
        if (more) {
            Ap += 32; Bp += 32;
            ra0 = *(const uint4*)Ap;
            ra1 = *(const uint4*)(Ap + a64);
            rb0 = *(const uint4*)Bp;
            rb1 = *(const uint4*)(Bp + a64);
            rb2 = *(const uint4*)(Bp + 2 * a64);
            rb3 = *(const uint4*)(Bp + 3 * a64);
        }

        const uint32_t base = sb + (uint32_t)(s & 1) * STAGE_B;
        #pragma unroll
        for (int ks = 0; ks < 2; ks++) {
            uint32_t aF[4][4], bF[4][4];
            const uint32_t ak = base + (uint32_t)(ks * 32 + akoff);
            #pragma unroll
            for (int mt = 0; mt < 4; mt++)
                ldsm4(aF[mt], ak + (uint32_t)(arow + mt * 16) * 80);
            const uint32_t bk = base + 10240u + (uint32_t)(ks * 32 + bkoff);
            #pragma unroll
            for (int np = 0; np < 4; np++)
                ldsm4(bF[np], bk + (uint32_t)(brow + np * 16) * 80);
            #pragma unroll
            for (int mt = 0; mt < 4; mt++)
                #pragma unroll
                for (int nt = 0; nt < 8; nt++)
                    mma168f16(acc[mt][nt], aF[mt], &bF[nt >> 1][(nt & 1) * 2]);
        }

        if (more) {
            char* sn = smem + ((s + 1) & 1) * STAGE_B;
            *(uint4*)(sn + lr * 80 + lc * 16)        = ra0;
            *(uint4*)(sn + (lr + 64) * 80 + lc * 16) = ra1;
            char* snb = sn + 10240;
            *(uint4*)(snb + lr * 80 + lc * 16)         = rb0;
            *(uint4*)(snb + (lr + 64) * 80 + lc * 16)  = rb1;
            *(uint4*)(snb + (lr + 128) * 80 + lc * 16) = rb2;
            *(uint4*)(snb + (lr + 192) * 80 + lc * 16) = rb3;
        }
        __syncthreads();
    }

    #pragma unroll
    for (int mt = 0; mt < 4; mt++) {
        const int row = bm + wm + mt * 16 + gid;
        #pragma unroll
        for (int nt = 0; nt < 8; nt++) {
            const int col = bn + wn + nt * 8 + 2 * tig;
            *(float2*)&Cm[(size_t)row * N + col]       = make_float2(acc[mt][nt][0], acc[mt][nt][1]);
            *(float2*)&Cm[(size_t)(row + 8) * N + col] = make_float2(acc[mt][nt][2], acc[mt][nt][3]);
        }
    }
}

// ---------------- f32 -> f16 convert -----------------------------------------
__global__ void __launch_bounds__(256)
to_half(const float* __restrict__ X, __half* __restrict__ Y, int n8)
{
    int i = blockIdx.x * 256 + threadIdx.x;
    if (i >= n8) return;
    float4 v0 = ((const float4*)X)[i * 2];
    float4 v1 = ((const float4*)X)[i * 2 + 1];
    __half2* H = (__half2*)Y;
    H[i * 4 + 0] = __floats2half2_rn(v0.x, v0.y);
    H[i * 4 + 1] = __floats2half2_rn(v0.z, v0.w);
    H[i * 4 + 2] = __floats2half2_rn(v1.x, v1.y);
    H[i * 4 + 3] = __floats2half2_rn(v1.z, v1.w);
}

// ---------------- transpose: W[K][N] f32 -> Wt[N][K] f16 ---------------------
__global__ void __launch_bounds__(256)
transpose_half(const float* __restrict__ W, __half* __restrict__ Th, int K, int N)
{
    __shared__ float tile[32][33];
    const int k0 = blockIdx.y * 32, n0 = blockIdx.x * 32;
    const int tx = threadIdx.x & 31, ty = threadIdx.x >> 5;
    #pragma unroll
    for (int r = 0; r < 32; r += 8)
        tile[ty + r][tx] = W[(size_t)(k0 + ty + r) * N + n0 + tx];
    __syncthreads();
    #pragma unroll
    for (int r = 0; r < 32; r += 8)
        Th[(size_t)(n0 + ty + r) * K + k0 + tx] = __float2half(tile[tx][ty + r]);
}

// ---------------- beta/alpha -------------------------------------------------
__global__ void __launch_bounds__(128)
ba_kernel(const float* __restrict__ x, const float* __restrict__ Wb,
          const float* __restrict__ Wa, float* __restrict__ beta,
          float* __restrict__ alpha)
{
    __shared__ float xs[CC];
    const int row = blockIdx.x;
    const float* xr = x + (size_t)row * CC;
    for (int i = threadIdx.x; i < CC; i += 128) xs[i] = xr[i];
    __syncthreads();

    const int g = threadIdx.x >> 2;
    const int l = threadIdx.x & 3;
    const float* W = (g < 16) ? Wb : Wa;
    const int h = g & 15;
    float s = 0.f;
    for (int cidx = l; cidx < CC; cidx += 4)
        s = fmaf(xs[cidx], W[cidx * HH + h], s);
    s += __shfl_down_sync(0xffffffffu, s, 2);
    s += __shfl_down_sync(0xffffffffu, s, 1);
    if (l == 0) {
        float v = 1.f / (1.f + expf(-s));
        if (g < 16) beta[(size_t)row * HH + h] = v;
        else        alpha[(size_t)row * HH + h] = v;
    }
}

// ---------------- causal depthwise conv(K=4) + silu + l2norm of q,k ----------
__global__ void __launch_bounds__(256)
conv_kernel(const float* __restrict__ qkvz, const float* __restrict__ conv_w,
            const float* __restrict__ conv_state, const int* __restrict__ input_pos,
            float* __restrict__ y_out)
{
    __shared__ float ybuf[CONV_DIM];
    __shared__ float norms[32];

    const int bt = blockIdx.x;
    const int b = bt >> 11;
    const int t = bt & 2047;
    const float keep = (input_pos[0] == 0) ? 0.f : 1.f;

    for (int c = threadIdx.x; c < CONV_DIM; c += 256) {
        float4 w = *(const float4*)&conv_w[c * 4];
        float in[4];
        #pragma unroll
        for (int j = 0; j < 4; j++) {
            int tau = t + j - 3;
            float v;
            if (tau >= 0) v = qkvz[((size_t)(b * TT + tau)) * QKVZ_N + c];
            else          v = keep * conv_state[((size_t)b * CONV_DIM + c) * 4 + (t + 1 + j)];
            in[j] = v;
        }
        float acc = in[0] * w.x + in[1] * w.y + in[2] * w.z + in[3] * w.w;
        float sig = 1.f / (1.f + expf(-acc));
        ybuf[c] = acc * sig;
    }
    __syncthreads();

    const int wid = threadIdx.x >> 5;
    const int lane = threadIdx.x & 31;
    for (int hh = wid; hh < 32; hh += 8) {
        int base = (hh < 16) ? hh * 128 : KEY_DIM + (hh - 16) * 128;
        float ss = 0.f;
        #pragma unroll
        for (int i = 0; i < 4; i++) {
            float v = ybuf[base + lane + i * 32];
            ss = fmaf(v, v, ss);
        }
        #pragma unroll
        for (int off = 16; off > 0; off >>= 1)
            ss += __shfl_xor_sync(0xffffffffu, ss, off);
        if (lane == 0) norms[hh] = fmaxf(sqrtf(ss), 1e-12f);
    }
    __syncthreads();

    float* yr = y_out + (size_t)bt * CONV_DIM;
    for (int c = threadIdx.x; c < CONV_DIM; c += 256) {
        float v = ybuf[c];
        if (c < 2 * KEY_DIM) v /= norms[c >> 7];
        yr[c] = v;
    }
}

// ---------------- chunked recurrence: phase A (intra + state increment) ------
// grid (NCH, BH). smem: qs[64][129], ks[64][129], vs[64][128], P[64][65],
// cs[64], bs[64]  -> 28992 floats = 113.25 KB dynamic.
#define SMA_QS 0
#define SMA_KS 8256
#define SMA_VS 16512
#define SMA_P  24704
#define SMA_CS 28864
#define SMA_BS 28928
#define SMA_BYTES (28992 * 4)

__global__ void __launch_bounds__(256)
chunkA(const float* __restrict__ y, const float* __restrict__ beta,
       const float* __restrict__ alpha, float* __restrict__ att,
       float* __restrict__ sinc, float* __restrict__ cbuf)
{
    extern __shared__ float sm[];
    float* qs = sm + SMA_QS;
    float* ks = sm + SMA_KS;
    float* vs = sm + SMA_VS;
    float* P  = sm + SMA_P;
    float* cs = sm + SMA_CS;
    float* bs = sm + SMA_BS;

    const int bh = blockIdx.y, j = blockIdx.x;
    const int b = bh >> 4, h = bh & 15;
    const int t0 = j * LCH;
    const int tid = threadIdx.x;

    for (int i = tid; i < 2048; i += 256) {
        const int row = i >> 5, c4 = (i & 31) * 4;
        const float* yr = y + ((size_t)(b * TT + t0 + row)) * CONV_DIM + h * 128;
        float4 q4 = *(const float4*)(yr + c4);
        float4 k4 = *(const float4*)(yr + KEY_DIM + c4);
        float4 v4 = *(const float4*)(yr + 2 * KEY_DIM + c4);
        qs[row * 129 + c4 + 0] = q4.x; qs[row * 129 + c4 + 1] = q4.y;
        qs[row * 129 + c4 + 2] = q4.z; qs[row * 129 + c4 + 3] = q4.w;
        ks[row * 129 + c4 + 0] = k4.x; ks[row * 129 + c4 + 1] = k4.y;
        ks[row * 129 + c4 + 2] = k4.z; ks[row * 129 + c4 + 3] = k4.w;
        *(float4*)(vs + row * 128 + c4) = v4;
    }
    if (tid < 64) {
        cs[tid] = log2f(alpha[((size_t)(b * TT + t0 + tid)) * HH + h]);
        bs[tid] = beta[((size_t)(b * TT + t0 + tid)) * HH + h];
    }
    __syncthreads();
    if (tid == 0) {
        float run = 0.f;
        for (int t = 0; t < LCH; t++) { run += cs[t]; cs[t] = run; }
    }
    __syncthreads();
    if (tid < 64) cbuf[(size_t)bh * TT + t0 + tid] = cs[tid];

    // ---- P[t][tau] = (q_t . k_tau) * b_tau * 2^(c_t - c_tau), tau <= t ----
    {
        const int rt = tid >> 4, ct = tid & 15;
        float acc[4][4];
        #pragma unroll
        for (int i = 0; i < 4; i++)
            #pragma unroll
            for (int j2 = 0; j2 < 4; j2++) acc[i][j2] = 0.f;
        if (ct <= rt) {
            for (int kk = 0; kk < 128; kk++) {
                float qv[4], kv[4];
                #pragma unroll
                for (int i = 0; i < 4; i++) qv[i] = qs[(rt * 4 + i) * 129 + kk];
                #pragma unroll
                for (int i = 0; i < 4; i++) kv[i] = ks[(ct * 4 + i) * 129 + kk];
                #pragma unroll
                for (int i = 0; i < 4; i++)
                    #pragma unroll
                    for (int j2 = 0; j2 < 4; j2++)
                        acc[i][j2] = fmaf(qv[i], kv[j2], acc[i][j2]);
            }
        }
        #pragma unroll
        for (int i = 0; i < 4; i++)
            #pragma unroll
            for (int j2 = 0; j2 < 4; j2++) {
                const int t = rt * 4 + i, tau = ct * 4 + j2;
                float val = 0.f;
                if (tau <= t)
                    val = acc[i][j2] * bs[tau] * exp2f(cs[t] - cs[tau]);
                P[t * 65 + tau] = val;
            }
    }
    __syncthreads();

    // ---- o_intra = P @ v ; thread owns t pair (tg) x dv set {dvg + 8d} ----
    {
        const int tg = tid >> 3, dvg = tid & 7;
        const int ta = tg * 2, tb = ta + 1;
        float o0[16], o1[16];
        #pragma unroll
        for (int d = 0; d < 16; d++) { o0[d] = 0.f; o1[d] = 0.f; }
        for (int tau = 0; tau < LCH; tau++) {
            const float p0 = P[ta * 65 + tau];
            const float p1 = P[tb * 65 + tau];
            const float* vr = vs + tau * 128;
            #pragma unroll
            for (int d = 0; d < 16; d++) {
                const float vv = vr[dvg + 8 * d];
                o0[d] = fmaf(p0, vv, o0[d]);
                o1[d] = fmaf(p1, vv, o1[d]);
            }
        }
        float* ar0 = att + ((size_t)(b * TT + t0 + ta)) * VALUE_DIM + h * 128;
        float* ar1 = att + ((size_t)(b * TT + t0 + tb)) * VALUE_DIM + h * 128;
        #pragma unroll
        for (int d = 0; d < 16; d++) {
            ar0[dvg + 8 * d] = o0[d];
            ar1[dvg + 8 * d] = o1[d];
        }
    }

    // ---- Sinc[dk][dv] = sum_tau b_tau 2^(cL - c_tau) k[tau][dk] v[tau][dv] --
    {
        const int dkt = tid >> 4, dvt = tid & 15;   // dk = dkt+16i, dv = dvt+16jj
        float sacc[8][8];
        #pragma unroll
        for (int i = 0; i < 8; i++)
            #pragma unroll
            for (int jj = 0; jj < 8; jj++) sacc[i][jj] = 0.f;
        const float cL = cs[63];
        for (int tau = 0; tau < LCH; tau++) {
            const float w = bs[tau] * exp2f(cL - cs[tau]);
            float kw[8], vv[8];
            #pragma unroll
            for (int i = 0; i < 8; i++) kw[i] = ks[tau * 129 + dkt + 16 * i] * w;
            #pragma unroll
            for (int jj = 0; jj < 8; jj++) vv[jj] = vs[tau * 128 + dvt + 16 * jj];
            #pragma unroll
            for (int i = 0; i < 8; i++)
                #pragma unroll
                for (int jj = 0; jj < 8; jj++)
                    sacc[i][jj] = fmaf(kw[i], vv[jj], sacc[i][jj]);
        }
        float* sp = sinc + ((size_t)(bh * NCH + j)) * 16384;
        #pragma unroll
        for (int i = 0; i < 8; i++)
            #pragma unroll
            for (int jj = 0; jj < 8; jj++)
                sp[(dkt + 16 * i) * 128 + dvt + 16 * jj] = sacc[i][jj];
    }
}

// ---------------- chunked recurrence: phase B (state scan over chunks) -------
__global__ void __launch_bounds__(256)
chunkB(const float* __restrict__ sinc, float* __restrict__ spre,
       const float* __restrict__ cbuf, const float* __restrict__ rstate,
       const int* __restrict__ input_pos)
{
    const int bh = blockIdx.x;
    const int tid = threadIdx.x;
    const float keep = (input_pos[0] == 0) ? 0.f : 1.f;

    float s[64];
    #pragma unroll
    for (int i = 0; i < 64; i++)
        s[i] = keep * rstate[(size_t)bh * 16384 + tid + i * 256];

    for (int j = 0; j < NCH; j++) {
        const size_t base = ((size_t)(bh * NCH + j)) * 16384;
        #pragma unroll
        for (int i = 0; i < 64; i++)
            spre[base + tid + i * 256] = s[i];
        const float dec = exp2f(cbuf[(size_t)bh * TT + j * LCH + 63]);
        #pragma unroll
        for (int i = 0; i < 64; i++)
            s[i] = fmaf(dec, s[i], sinc[base + tid + i * 256]);
    }
}

// ---------------- chunked recurrence: phase C (inter: q @ S_in) --------------
// smem: S[16384] + qs[64][129] + cs[64] = 24704 floats = 98816 B
#define SMC_BYTES (24704 * 4)
__global__ void __launch_bounds__(256)
chunkC(const float* __restrict__ y, const float* __restrict__ cbuf,
       const float* __restrict__ spre, float* __restrict__ att)
{
    extern __shared__ float sm[];
    float* S  = sm;
    float* qs = sm + 16384;
    float* cs = sm + 16384 + 8256;

    const int bh = blockIdx.y, j = blockIdx.x;
    const int b = bh >> 4, h = bh & 15;
    const int t0 = j * LCH;
    const int tid = threadIdx.x;

    const float* sp = spre + ((size_t)(bh * NCH + j)) * 16384;
    for (int i = tid; i < 4096; i += 256)
        *(float4*)(S + i * 4) = *(const float4*)(sp + i * 4);
    for (int i = tid; i < 2048; i += 256) {
        const int row = i >> 5, c4 = (i & 31) * 4;
        const float* yr = y + ((size_t)(b * TT + t0 + row)) * CONV_DIM + h * 128;
        float4 q4 = *(const float4*)(yr + c4);
        qs[row * 129 + c4 + 0] = q4.x; qs[row * 129 + c4 + 1] = q4.y;
        qs[row * 129 + c4 + 2] = q4.z; qs[row * 129 + c4 + 3] = q4.w;
    }
    if (tid < 64) cs[tid] = cbuf[(size_t)bh * TT + t0 + tid];
    __syncthreads();

    const int tg = tid >> 3, dvg = tid & 7;
    const int ta = tg * 2, tb = ta + 1;
    float o0[16], o1[16];
    #pragma unroll
    for (int d = 0; d < 16; d++) { o0[d] = 0.f; o1[d] = 0.f; }
    for (int dk = 0; dk < 128; dk++) {
        const float q0 = qs[ta * 129 + dk];
        const float q1 = qs[tb * 129 + dk];
        const float* srow = S + dk * 128;
        #pragma unroll
        for (int d = 0; d < 16; d++) {
            const float sv = srow[dvg + 8 * d];
            o0[d] = fmaf(q0, sv, o0[d]);
            o1[d] = fmaf(q1, sv, o1[d]);
        }
    }
    const float e0 = exp2f(cs[ta]);
    const float e1 = exp2f(cs[tb]);
    float* ar0 = att + ((size_t)(b * TT + t0 + ta)) * VALUE_DIM + h * 128;
    float* ar1 = att + ((size_t)(b * TT + t0 + tb)) * VALUE_DIM + h * 128;
    #pragma unroll
    for (int d = 0; d < 16; d++) {
        ar0[dvg + 8 * d] += e0 * o0[d];
        ar1[dvg + 8 * d] += e1 * o1[d];
    }
}

// ---------------- rmsnorm * norm_w * sigmoid(z) -> fp16 ----------------------
__global__ void __launch_bounds__(256)
gate_kernel(const float* __restrict__ att, const float* __restrict__ qkvz,
            const float* __restrict__ norm_w, __half* __restrict__ goh)
{
    const int bt = blockIdx.x;
    const int wid = threadIdx.x >> 5;
    const int lane = threadIdx.x & 31;

    #pragma unroll
    for (int k = 0; k < 2; k++) {
        const int hh = wid * 2 + k;
        const float* ar = att + (size_t)bt * VALUE_DIM + hh * 128;
        float v[4];
        float ss = 0.f;
        #pragma unroll
        for (int i = 0; i < 4; i++) {
            v[i] = ar[lane + i * 32];
            ss = fmaf(v[i], v[i], ss);
        }
        #pragma unroll
        for (int off = 16; off > 0; off >>= 1)
            ss += __shfl_xor_sync(0xffffffffu, ss, off);
        float scale = rsqrtf(ss * (1.f / 128.f) + 1e-6f);
        const float* zr = qkvz + (size_t)bt * QKVZ_N + CONV_DIM + hh * 128;
        __half* gr = goh + (size_t)bt * VALUE_DIM + hh * 128;
        #pragma unroll
        for (int i = 0; i < 4; i++) {
            int dvi = lane + i * 32;
            float z = zr[dvi];
            float sig = 1.f / (1.f + expf(-z));
            gr[dvi] = __float2half(v[i] * scale * norm_w[dvi] * sig);
        }
    }
}

// ---------------- launch -----------------------------------------------------
extern "C" void kernel_launch(void* const* d_in, const int* in_sizes, int n_in,
                              void* d_out, int out_size)
{
    const float* x          = (const float*)d_in[0];
    const int*   input_pos  = (const int*)  d_in[1];
    const float* W_qkvz     = (const float*)d_in[2];
    const float* W_b        = (const float*)d_in[3];
    const float* W_a        = (const float*)d_in[4];
    const float* conv_w     = (const float*)d_in[5];
    const float* norm_w     = (const float*)d_in[6];
    const float* W_out      = (const float*)d_in[7];
    const float* conv_state = (const float*)d_in[8];
    const float* rec_state  = (const float*)d_in[9];
    float* out = (float*)d_out;

    float *qkvz, *y, *beta, *alpha, *attb, *sinc, *spre, *cbuf;
    __half *xh, *wqt, *wot, *goh;
    cudaGetSymbolAddress((void**)&qkvz, g_qkvz);
    cudaGetSymbolAddress((void**)&y,    g_y);
    cudaGetSymbolAddress((void**)&beta, g_beta);
    cudaGetSymbolAddress((void**)&alpha,g_alpha);
    cudaGetSymbolAddress((void**)&attb, g_att);
    cudaGetSymbolAddress((void**)&sinc, g_sinc);
    cudaGetSymbolAddress((void**)&spre, g_spre);
    cudaGetSymbolAddress((void**)&cbuf, g_cc);
    cudaGetSymbolAddress((void**)&xh,  g_xh);
    cudaGetSymbolAddress((void**)&wqt, g_wqt);
    cudaGetSymbolAddress((void**)&wot, g_wot);
    cudaGetSymbolAddress((void**)&goh, g_goh);

    cudaFuncSetAttribute(h16gemm, cudaFuncAttributeMaxDynamicSharedMemorySize,
                         GEMM_SMEM);
    cudaFuncSetAttribute(chunkA, cudaFuncAttributeMaxDynamicSharedMemorySize,
                         SMA_BYTES);
    cudaFuncSetAttribute(chunkC, cudaFuncAttributeMaxDynamicSharedMemorySize,
                         SMC_BYTES);

    // 0) operand prep
    to_half<<<(BT * CC / 8 + 255) / 256, 256>>>(x, xh, BT * CC / 8);
    transpose_half<<<dim3(QKVZ_N / 32, CC / 32), 256>>>(W_qkvz, wqt, CC, QKVZ_N);
    transpose_half<<<dim3(CC / 32, CC / 32), 256>>>(W_out, wot, CC, CC);

    // 1) qkvz = x @ W_qkvz  (fp16 mma.m16n8k16)
    h16gemm<<<dim3(QKVZ_N / 256, BT / 128), 256, GEMM_SMEM>>>(
        xh, wqt, qkvz, BT, QKVZ_N, CC);
    // 2) beta/alpha
    ba_kernel<<<BT, 128>>>(x, W_b, W_a, beta, alpha);
    // 3) conv + silu + l2norm
    conv_kernel<<<BT, 256>>>(qkvz, conv_w, conv_state, input_pos, y);
    // 4) chunked recurrence: intra -> scan -> inter
    chunkA<<<dim3(NCH, BH), 256, SMA_BYTES>>>(y, beta, alpha, attb, sinc, cbuf);
    chunkB<<<BH, 256>>>(sinc, spre, cbuf, rec_state, input_pos);
    chunkC<<<dim3(NCH, BH), 256, SMC_BYTES>>>(y, cbuf, spre, attb);
    // 5) rmsnorm + gate -> fp16
    gate_kernel<<<BT, 256>>>(attb, qkvz, norm_w, goh);
    // 6) out = gated @ W_out  (fp16 mma.m16n8k16)
    h16gemm<<<dim3(CC / 256, BT / 128), 256, GEMM_SMEM>>>(
        goh, wot, out, BT, CC, CC);
}

// round 11
// speedup vs baseline: 1.3347x; 1.0658x over previous
#include <cuda_runtime.h>
#include <cuda_fp16.h>
#include <math.h>
#include <stdint.h>

// Problem constants
#define BB 2
#define TT 2048
#define CC 2048
#define HH 16
#define KEY_DIM 2048
#define VALUE_DIM 2048
#define CONV_DIM 6144
#define QKVZ_N 8192
#define BT 4096   // B*T
#define LCH 64
#define NCH (TT / LCH)   // 32 chunks
#define BH 32            // B*H

// ---------------- scratch (static device globals; no allocation) -------------
__device__ float g_qkvz[(size_t)BT * QKVZ_N];   // 128 MiB
__device__ float g_y[(size_t)BT * CONV_DIM];    // 96 MiB
__device__ float g_beta[(size_t)BT * HH];
__device__ float g_alpha[(size_t)BT * HH];
__device__ float g_att[(size_t)BT * VALUE_DIM]; // intra-chunk partial
__device__ __half g_xh[(size_t)BT * CC];
__device__ __half g_wqt[(size_t)QKVZ_N * CC];
__device__ __half g_wot[(size_t)CC * CC];
__device__ __half g_goh[(size_t)BT * CC];
__device__ float g_sinc[(size_t)BH * NCH * 16384];
__device__ float g_spre[(size_t)BH * NCH * 16384];
__device__ float g_cc[(size_t)BH * TT];

// ---------------- PTX helpers ------------------------------------------------
__device__ __forceinline__ uint32_t s2u(const void* p) {
    uint32_t a;
    asm("{ .reg .u64 t; cvta.to.shared.u64 t, %1; cvt.u32.u64 %0, t; }"
        : "=r"(a) : "l"(p));
    return a;
}
__device__ __forceinline__ void ldsm4(uint32_t* r, uint32_t addr) {
    asm volatile("ldmatrix.sync.aligned.m8n8.x4.shared.b16 {%0,%1,%2,%3}, [%4];"
                 : "=r"(r[0]), "=r"(r[1]), "=r"(r[2]), "=r"(r[3]) : "r"(addr));
}
__device__ __forceinline__ void mma168f16(float* d, const uint32_t* a,
                                          const uint32_t* b) {
    asm volatile(
        "mma.sync.aligned.m16n8k16.row.col.f32.f16.f16.f32 "
        "{%0,%1,%2,%3}, {%4,%5,%6,%7}, {%8,%9}, {%0,%1,%2,%3};\n"
        : "+f"(d[0]), "+f"(d[1]), "+f"(d[2]), "+f"(d[3])
        : "r"(a[0]), "r"(a[1]), "r"(a[2]), "r"(a[3]),
          "r"(b[0]), "r"(b[1]));
}

// ---------------- fp16 tensor-core GEMM (unchanged) --------------------------
#define STAGE_B 30720
#define GEMM_SMEM (2 * STAGE_B)

__global__ void __launch_bounds__(256)
h16gemm(const __half* __restrict__ A, const __half* __restrict__ Bt,
        float* __restrict__ Cm, int M, int N, int Kd)
{
    extern __shared__ char smem[];
    const uint32_t sb = s2u(smem);
    const int tid  = threadIdx.x;
    const int bm   = blockIdx.y * 128;
    const int bn   = blockIdx.x * 256;
    const int lane = tid & 31;
    const int warp = tid >> 5;
    const int wm   = (warp >> 2) * 64;
    const int wn   = (warp & 3) * 64;
    const int gid  = lane >> 2;
    const int tig  = lane & 3;

    const int lr = tid >> 2;
    const int lc = tid & 3;

    const __half* Ap = A  + (size_t)(bm + lr) * Kd + lc * 8;
    const __half* Bp = Bt + (size_t)(bn + lr) * Kd + lc * 8;
    const size_t a64 = (size_t)64 * Kd;

    float acc[4][8][4];
    #pragma unroll
    for (int i = 0; i < 4; i++)
        #pragma unroll
        for (int j = 0; j < 8; j++)
            #pragma unroll
            for (int r = 0; r < 4; r++) acc[i][j][r] = 0.f;

    {
        uint4 ra0 = *(const uint4*)Ap;
        uint4 ra1 = *(const uint4*)(Ap + a64);
        uint4 rb0 = *(const uint4*)Bp;
        uint4 rb1 = *(const uint4*)(Bp + a64);
        uint4 rb2 = *(const uint4*)(Bp + 2 * a64);
        uint4 rb3 = *(const uint4*)(Bp + 3 * a64);
        char* s0 = smem;
        *(uint4*)(s0 + lr * 80 + lc * 16)        = ra0;
        *(uint4*)(s0 + (lr + 64) * 80 + lc * 16) = ra1;
        char* s0b = s0 + 10240;
        *(uint4*)(s0b + lr * 80 + lc * 16)         = rb0;
        *(uint4*)(s0b + (lr + 64) * 80 + lc * 16)  = rb1;
        *(uint4*)(s0b + (lr + 128) * 80 + lc * 16) = rb2;
        *(uint4*)(s0b + (lr + 192) * 80 + lc * 16) = rb3;
    }
    __syncthreads();

    const int at = lane >> 3;
    const int arow = wm + (at & 1) * 8 + (lane & 7);
    const int akoff = (lane >> 4) * 16;
    const int brow = wn + (lane >> 4) * 8 + (lane & 7);
    const int bkoff = ((lane >> 3) & 1) * 16;

    const int nst = Kd / 32;
    for (int s = 0; s < nst; s++) {
        const bool more = (s + 1) < nst;
        uint4 ra0, ra1, rb0, rb1, rb2, rb3;
        if (more) {
            Ap += 32; Bp += 32;
            ra0 = *(const uint4*)Ap;
            ra1 = *(const uint4*)(Ap + a64);
            rb0 = *(const uint4*)Bp;
            rb1 = *(const uint4*)(Bp + a64);
            rb2 = *(const uint4*)(Bp + 2 * a64);
            rb3 = *(const uint4*)(Bp + 3 * a64);
        }

        const uint32_t base = sb + (uint32_t)(s & 1) * STAGE_B;
        #pragma unroll
        for (int ks = 0; ks < 2; ks++) {
            uint32_t aF[4][4], bF[4][4];
            const uint32_t ak = base + (uint32_t)(ks * 32 + akoff);
            #pragma unroll
            for (int mt = 0; mt < 4; mt++)
                ldsm4(aF[mt], ak + (uint32_t)(arow + mt * 16) * 80);
            const uint32_t bk = base + 10240u + (uint32_t)(ks * 32 + bkoff);
            #pragma unroll
            for (int np = 0; np < 4; np++)
                ldsm4(bF[np], bk + (uint32_t)(brow + np * 16) * 80);
            #pragma unroll
            for (int mt = 0; mt < 4; mt++)
                #pragma unroll
                for (int nt = 0; nt < 8; nt++)
                    mma168f16(acc[mt][nt], aF[mt], &bF[nt >> 1][(nt & 1) * 2]);
        }

        if (more) {
            char* sn = smem + ((s + 1) & 1) * STAGE_B;
            *(uint4*)(sn + lr * 80 + lc * 16)        = ra0;
            *(uint4*)(sn + (lr + 64) * 80 + lc * 16) = ra1;
            char* snb = sn + 10240;
            *(uint4*)(snb + lr * 80 + lc * 16)         = rb0;
            *(uint4*)(snb + (lr + 64) * 80 + lc * 16)  = rb1;
            *(uint4*)(snb + (lr + 128) * 80 + lc * 16) = rb2;
            *(uint4*)(snb + (lr + 192) * 80 + lc * 16) = rb3;
        }
        __syncthreads();
    }

    #pragma unroll
    for (int mt = 0; mt < 4; mt++) {
        const int row = bm + wm + mt * 16 + gid;
        #pragma unroll
        for (int nt = 0; nt < 8; nt++) {
            const int col = bn + wn + nt * 8 + 2 * tig;
            *(float2*)&Cm[(size_t)row * N + col]       = make_float2(acc[mt][nt][0], acc[mt][nt][1]);
            *(float2*)&Cm[(size_t)(row + 8) * N + col] = make_float2(acc[mt][nt][2], acc[mt][nt][3]);
        }
    }
}

// ---------------- f32 -> f16 convert -----------------------------------------
__global__ void __launch_bounds__(256)
to_half(const float* __restrict__ X, __half* __restrict__ Y, int n8)
{
    int i = blockIdx.x * 256 + threadIdx.x;
    if (i >= n8) return;
    float4 v0 = ((const float4*)X)[i * 2];
    float4 v1 = ((const float4*)X)[i * 2 + 1];
    __half2* H = (__half2*)Y;
    H[i * 4 + 0] = __floats2half2_rn(v0.x, v0.y);
    H[i * 4 + 1] = __floats2half2_rn(v0.z, v0.w);
    H[i * 4 + 2] = __floats2half2_rn(v1.x, v1.y);
    H[i * 4 + 3] = __floats2half2_rn(v1.z, v1.w);
}

// ---------------- transpose: W[K][N] f32 -> Wt[N][K] f16 ---------------------
__global__ void __launch_bounds__(256)
transpose_half(const float* __restrict__ W, __half* __restrict__ Th, int K, int N)
{
    __shared__ float tile[32][33];
    const int k0 = blockIdx.y * 32, n0 = blockIdx.x * 32;
    const int tx = threadIdx.x & 31, ty = threadIdx.x >> 5;
    #pragma unroll
    for (int r = 0; r < 32; r += 8)
        tile[ty + r][tx] = W[(size_t)(k0 + ty + r) * N + n0 + tx];
    __syncthreads();
    #pragma unroll
    for (int r = 0; r < 32; r += 8)
        Th[(size_t)(n0 + ty + r) * K + k0 + tx] = __float2half(tile[tx][ty + r]);
}

// ---------------- beta/alpha: tiled fp32 GEMM (64 rows x 32 cols / CTA) ------
// smem: xs[64][132] + ws[128][32]  -> 50176 B dynamic
#define BA_SMEM (64 * 132 * 4 + 128 * 32 * 4)
__global__ void __launch_bounds__(256)
ba2_kernel(const float* __restrict__ x, const float* __restrict__ Wb,
           const float* __restrict__ Wa, float* __restrict__ beta,
           float* __restrict__ alpha)
{
    extern __shared__ float sm[];
    float* xs = sm;                 // [64][132]
    float* ws = sm + 64 * 132;      // [128][32]

    const int tid = threadIdx.x;
    const int r0 = blockIdx.x * 64;
    const int tr = tid >> 4;        // 0..15 -> 4 rows each
    const int tc = tid & 15;        // 0..15 -> 2 cols each

    float acc[4][2];
    #pragma unroll
    for (int i = 0; i < 4; i++) { acc[i][0] = 0.f; acc[i][1] = 0.f; }

    for (int k0 = 0; k0 < CC; k0 += 128) {
        // load x tile 64x128
        #pragma unroll
        for (int i = 0; i < 8; i++) {
            const int idx = tid + i * 256;
            const int row = idx >> 5, c4 = (idx & 31) * 4;
            *(float4*)&xs[row * 132 + c4] =
                *(const float4*)&x[(size_t)(r0 + row) * CC + k0 + c4];
        }
        // load W tiles 128x16 each
        #pragma unroll
        for (int i = 0; i < 2; i++) {
            const int idx = tid + i * 256;
            const int kk = idx >> 2, q = (idx & 3) * 4;
            *(float4*)&ws[kk * 32 + q]      = *(const float4*)&Wb[(size_t)(k0 + kk) * HH + q];
            *(float4*)&ws[kk * 32 + 16 + q] = *(const float4*)&Wa[(size_t)(k0 + kk) * HH + q];
        }
        __syncthreads();

        for (int kk = 0; kk < 128; kk++) {
            const float2 wv = *(const float2*)&ws[kk * 32 + tc * 2];
            #pragma unroll
            for (int i = 0; i < 4; i++) {
                const float xv = xs[(tr * 4 + i) * 132 + kk];
                acc[i][0] = fmaf(xv, wv.x, acc[i][0]);
                acc[i][1] = fmaf(xv, wv.y, acc[i][1]);
            }
        }
        __syncthreads();
    }

    #pragma unroll
    for (int i = 0; i < 4; i++) {
        const int row = r0 + tr * 4 + i;
        #pragma unroll
        for (int j = 0; j < 2; j++) {
            const int c = tc * 2 + j;
            const float v = 1.f / (1.f + expf(-acc[i][j]));
            if (c < 16) beta[(size_t)row * HH + c] = v;
            else        alpha[(size_t)row * HH + (c - 16)] = v;
        }
    }
}

// ---------------- conv: time-tiled (8 t x 768 ch per block) ------------------
// smem: in[11][768] + yb[8][768] + nrm[48] = 14640 floats = 58560 B dynamic
#define CONV_SMEM ((11 * 768 + 8 * 768 + 48) * 4)
__global__ void __launch_bounds__(256)
conv2_kernel(const float* __restrict__ qkvz, const float* __restrict__ conv_w,
             const float* __restrict__ conv_state, const int* __restrict__ input_pos,
             float* __restrict__ y_out)
{
    extern __shared__ float sm[];
    float* in  = sm;                    // [11][768]
    float* yb  = sm + 11 * 768;         // [8][768]
    float* nrm = sm + 19 * 768;         // [8][6] inverse norms

    const int cg = blockIdx.x;          // 0..7
    const int c0 = cg * 768;
    const int tgl = blockIdx.y;         // 0..511
    const int b = tgl >> 8;
    const int t0 = (tgl & 255) * 8;
    const int tid = threadIdx.x;
    const float keep = (input_pos[0] == 0) ? 0.f : 1.f;

    // load 11 rows x 768 ch
    for (int idx = tid; idx < 11 * 192; idx += 256) {
        const int r = idx / 192, c4 = (idx % 192) * 4;
        const int tau = t0 - 3 + r;
        float4 v;
        if (tau >= 0) {
            v = *(const float4*)&qkvz[((size_t)(b * TT + tau)) * QKVZ_N + c0 + c4];
        } else {
            const int slot = tau + 4;   // 1..3
            v.x = keep * conv_state[((size_t)b * CONV_DIM + c0 + c4 + 0) * 4 + slot];
            v.y = keep * conv_state[((size_t)b * CONV_DIM + c0 + c4 + 1) * 4 + slot];
            v.z = keep * conv_state[((size_t)b * CONV_DIM + c0 + c4 + 2) * 4 + slot];
            v.w = keep * conv_state[((size_t)b * CONV_DIM + c0 + c4 + 3) * 4 + slot];
        }
        *(float4*)&in[r * 768 + c4] = v;
    }
    __syncthreads();

    // conv + silu
    for (int idx = tid; idx < 1536; idx += 256) {
        const int t = idx / 192, c4 = (idx % 192) * 4;
        float4 o;
        float* op = (float*)&o;
        #pragma unroll
        for (int e = 0; e < 4; e++) {
            const int c = c4 + e;
            const float4 w = *(const float4*)&conv_w[(size_t)(c0 + c) * 4];
            float acc = in[(t + 0) * 768 + c] * w.x + in[(t + 1) * 768 + c] * w.y
                      + in[(t + 2) * 768 + c] * w.z + in[(t + 3) * 768 + c] * w.w;
            op[e] = acc / (1.f + expf(-acc));
        }
        *(float4*)&yb[t * 768 + c4] = o;
    }
    __syncthreads();

    // per-(t, local-head) inverse norms; normalize iff global head < 32
    {
        const int w = tid >> 5, lane = tid & 31;
        for (int p = w; p < 48; p += 8) {
            const int t = p / 6, hl = p % 6;
            const int hg = (c0 >> 7) + hl;
            float ss = 0.f;
            #pragma unroll
            for (int i = 0; i < 4; i++) {
                const float v = yb[t * 768 + hl * 128 + lane + i * 32];
                ss = fmaf(v, v, ss);
            }
            #pragma unroll
            for (int off = 16; off > 0; off >>= 1)
                ss += __shfl_xor_sync(0xffffffffu, ss, off);
            if (lane == 0)
                nrm[t * 6 + hl] = (hg < 32) ? (1.f / fmaxf(sqrtf(ss), 1e-12f)) : 1.f;
        }
    }
    __syncthreads();

    for (int idx = tid; idx < 1536; idx += 256) {
        const int t = idx / 192, c4 = (idx % 192) * 4;
        const float inv = nrm[t * 6 + (c4 >> 7)];
        float4 v = *(const float4*)&yb[t * 768 + c4];
        v.x *= inv; v.y *= inv; v.z *= inv; v.w *= inv;
        *(float4*)&y_out[((size_t)(b * TT + t0 + t)) * CONV_DIM + c0 + c4] = v;
    }
}

// ---------------- chunked recurrence: phase A (unchanged) --------------------
#define SMA_QS 0
#define SMA_KS 8256
#define SMA_VS 16512
#define SMA_P  24704
#define SMA_CS 28864
#define SMA_BS 28928
#define SMA_BYTES (28992 * 4)

__global__ void __launch_bounds__(256)
chunkA(const float* __restrict__ y, const float* __restrict__ beta,
       const float* __restrict__ alpha, float* __restrict__ att,
       float* __restrict__ sinc, float* __restrict__ cbuf)
{
    extern __shared__ float sm[];
    float* qs = sm + SMA_QS;
    float* ks = sm + SMA_KS;
    float* vs = sm + SMA_VS;
    float* P  = sm + SMA_P;
    float* cs = sm + SMA_CS;
    float* bs = sm + SMA_BS;

    const int bh = blockIdx.y, j = blockIdx.x;
    const int b = bh >> 4, h = bh & 15;
    const int t0 = j * LCH;
    const int tid = threadIdx.x;

    for (int i = tid; i < 2048; i += 256) {
        const int row = i >> 5, c4 = (i & 31) * 4;
        const float* yr = y + ((size_t)(b * TT + t0 + row)) * CONV_DIM + h * 128;
        float4 q4 = *(const float4*)(yr + c4);
        float4 k4 = *(const float4*)(yr + KEY_DIM + c4);
        float4 v4 = *(const float4*)(yr + 2 * KEY_DIM + c4);
        qs[row * 129 + c4 + 0] = q4.x; qs[row * 129 + c4 + 1] = q4.y;
        qs[row * 129 + c4 + 2] = q4.z; qs[row * 129 + c4 + 3] = q4.w;
        ks[row * 129 + c4 + 0] = k4.x; ks[row * 129 + c4 + 1] = k4.y;
        ks[row * 129 + c4 + 2] = k4.z; ks[row * 129 + c4 + 3] = k4.w;
        *(float4*)(vs + row * 128 + c4) = v4;
    }
    if (tid < 64) {
        cs[tid] = log2f(alpha[((size_t)(b * TT + t0 + tid)) * HH + h]);
        bs[tid] = beta[((size_t)(b * TT + t0 + tid)) * HH + h];
    }
    __syncthreads();
    if (tid == 0) {
        float run = 0.f;
        for (int t = 0; t < LCH; t++) { run += cs[t]; cs[t] = run; }
    }
    __syncthreads();
    if (tid < 64) cbuf[(size_t)bh * TT + t0 + tid] = cs[tid];

    {
        const int rt = tid >> 4, ct = tid & 15;
        float acc[4][4];
        #pragma unroll
        for (int i = 0; i < 4; i++)
            #pragma unroll
            for (int j2 = 0; j2 < 4; j2++) acc[i][j2] = 0.f;
        if (ct <= rt) {
            for (int kk = 0; kk < 128; kk++) {
                float qv[4], kv[4];
                #pragma unroll
                for (int i = 0; i < 4; i++) qv[i] = qs[(rt * 4 + i) * 129 + kk];
                #pragma unroll
                for (int i = 0; i < 4; i++) kv[i] = ks[(ct * 4 + i) * 129 + kk];
                #pragma unroll
                for (int i = 0; i < 4; i++)
                    #pragma unroll
                    for (int j2 = 0; j2 < 4; j2++)
                        acc[i][j2] = fmaf(qv[i], kv[j2], acc[i][j2]);
            }
        }
        #pragma unroll
        for (int i = 0; i < 4; i++)
            #pragma unroll
            for (int j2 = 0; j2 < 4; j2++) {
                const int t = rt * 4 + i, tau = ct * 4 + j2;
                float val = 0.f;
                if (tau <= t)
                    val = acc[i][j2] * bs[tau] * exp2f(cs[t] - cs[tau]);
                P[t * 65 + tau] = val;
            }
    }
    __syncthreads();

    {
        const int tg = tid >> 3, dvg = tid & 7;
        const int ta = tg * 2, tb = ta + 1;
        float o0[16], o1[16];
        #pragma unroll
        for (int d = 0; d < 16; d++) { o0[d] = 0.f; o1[d] = 0.f; }
        for (int tau = 0; tau < LCH; tau++) {
            const float p0 = P[ta * 65 + tau];
            const float p1 = P[tb * 65 + tau];
            const float* vr = vs + tau * 128;
            #pragma unroll
            for (int d = 0; d < 16; d++) {
                const float vv = vr[dvg + 8 * d];
                o0[d] = fmaf(p0, vv, o0[d]);
                o1[d] = fmaf(p1, vv, o1[d]);
            }
        }
        float* ar0 = att + ((size_t)(b * TT + t0 + ta)) * VALUE_DIM + h * 128;
        float* ar1 = att + ((size_t)(b * TT + t0 + tb)) * VALUE_DIM + h * 128;
        #pragma unroll
        for (int d = 0; d < 16; d++) {
            ar0[dvg + 8 * d] = o0[d];
            ar1[dvg + 8 * d] = o1[d];
        }
    }

    {
        const int dkt = tid >> 4, dvt = tid & 15;
        float sacc[8][8];
        #pragma unroll
        for (int i = 0; i < 8; i++)
            #pragma unroll
            for (int jj = 0; jj < 8; jj++) sacc[i][jj] = 0.f;
        const float cL = cs[63];
        for (int tau = 0; tau < LCH; tau++) {
            const float w = bs[tau] * exp2f(cL - cs[tau]);
            float kw[8], vv[8];
            #pragma unroll
            for (int i = 0; i < 8; i++) kw[i] = ks[tau * 129 + dkt + 16 * i] * w;
            #pragma unroll
            for (int jj = 0; jj < 8; jj++) vv[jj] = vs[tau * 128 + dvt + 16 * jj];
            #pragma unroll
            for (int i = 0; i < 8; i++)
                #pragma unroll
                for (int jj = 0; jj < 8; jj++)
                    sacc[i][jj] = fmaf(kw[i], vv[jj], sacc[i][jj]);
        }
        float* sp = sinc + ((size_t)(bh * NCH + j)) * 16384;
        #pragma unroll
        for (int i = 0; i < 8; i++)
            #pragma unroll
            for (int jj = 0; jj < 8; jj++)
                sp[(dkt + 16 * i) * 128 + dvt + 16 * jj] = sacc[i][jj];
    }
}

// ---------------- phase B (unchanged) ----------------------------------------
__global__ void __launch_bounds__(256)
chunkB(const float* __restrict__ sinc, float* __restrict__ spre,
       const float* __restrict__ cbuf, const float* __restrict__ rstate,
       const int* __restrict__ input_pos)
{
    const int bh = blockIdx.x;
    const int tid = threadIdx.x;
    const float keep = (input_pos[0] == 0) ? 0.f : 1.f;

    float s[64];
    #pragma unroll
    for (int i = 0; i < 64; i++)
        s[i] = keep * rstate[(size_t)bh * 16384 + tid + i * 256];

    for (int j = 0; j < NCH; j++) {
        const size_t base = ((size_t)(bh * NCH + j)) * 16384;
        #pragma unroll
        for (int i = 0; i < 64; i++)
            spre[base + tid + i * 256] = s[i];
        const float dec = exp2f(cbuf[(size_t)bh * TT + j * LCH + 63]);
        #pragma unroll
        for (int i = 0; i < 64; i++)
            s[i] = fmaf(dec, s[i], sinc[base + tid + i * 256]);
    }
}

// ---------------- phase C fused with rmsnorm+gate -> fp16 --------------------
// smem: S[16384] + qs[64][129] + cs[64] + nws[128] = 24832 floats
#define SMC_BYTES (24832 * 4)
__global__ void __launch_bounds__(256)
chunkC(const float* __restrict__ y, const float* __restrict__ cbuf,
       const float* __restrict__ spre, const float* __restrict__ att,
       const float* __restrict__ qkvz, const float* __restrict__ norm_w,
       __half* __restrict__ goh)
{
    extern __shared__ float sm[];
    float* S   = sm;
    float* qs  = sm + 16384;
    float* cs  = sm + 16384 + 8256;
    float* nws = cs + 64;

    const int bh = blockIdx.y, j = blockIdx.x;
    const int b = bh >> 4, h = bh & 15;
    const int t0 = j * LCH;
    const int tid = threadIdx.x;

    const float* sp = spre + ((size_t)(bh * NCH + j)) * 16384;
    for (int i = tid; i < 4096; i += 256)
        *(float4*)(S + i * 4) = *(const float4*)(sp + i * 4);
    for (int i = tid; i < 2048; i += 256) {
        const int row = i >> 5, c4 = (i & 31) * 4;
        const float* yr = y + ((size_t)(b * TT + t0 + row)) * CONV_DIM + h * 128;
        float4 q4 = *(const float4*)(yr + c4);
        qs[row * 129 + c4 + 0] = q4.x; qs[row * 129 + c4 + 1] = q4.y;
        qs[row * 129 + c4 + 2] = q4.z; qs[row * 129 + c4 + 3] = q4.w;
    }
    if (tid < 64) cs[tid] = cbuf[(size_t)bh * TT + t0 + tid];
    if (tid < 128) nws[tid] = norm_w[tid];
    __syncthreads();

    const int tg = tid >> 3, dvg = tid & 7;
    const int ta = tg * 2, tb = ta + 1;
    float o0[16], o1[16];
    #pragma unroll
    for (int d = 0; d < 16; d++) { o0[d] = 0.f; o1[d] = 0.f; }
    for (int dk = 0; dk < 128; dk++) {
        const float q0 = qs[ta * 129 + dk];
        const float q1 = qs[tb * 129 + dk];
        const float* srow = S + dk * 128;
        #pragma unroll
        for (int d = 0; d < 16; d++) {
            const float sv = srow[dvg + 8 * d];
            o0[d] = fmaf(q0, sv, o0[d]);
            o1[d] = fmaf(q1, sv, o1[d]);
        }
    }
    const float e0 = exp2f(cs[ta]);
    const float e1 = exp2f(cs[tb]);

    // total = intra (from att) + e * inter
    const float* ar0 = att + ((size_t)(b * TT + t0 + ta)) * VALUE_DIM + h * 128;
    const float* ar1 = att + ((size_t)(b * TT + t0 + tb)) * VALUE_DIM + h * 128;
    float ss0 = 0.f, ss1 = 0.f;
    #pragma unroll
    for (int d = 0; d < 16; d++) {
        o0[d] = ar0[dvg + 8 * d] + e0 * o0[d];
        o1[d] = ar1[dvg + 8 * d] + e1 * o1[d];
        ss0 = fmaf(o0[d], o0[d], ss0);
        ss1 = fmaf(o1[d], o1[d], ss1);
    }
    // reduce squares across the 8-lane octet (bits 0..2 of lane)
    #pragma unroll
    for (int off = 1; off < 8; off <<= 1) {
        ss0 += __shfl_xor_sync(0xffffffffu, ss0, off);
        ss1 += __shfl_xor_sync(0xffffffffu, ss1, off);
    }
    const float sc0 = rsqrtf(ss0 * (1.f / 128.f) + 1e-6f);
    const float sc1 = rsqrtf(ss1 * (1.f / 128.f) + 1e-6f);

    const float* zr0 = qkvz + ((size_t)(b * TT + t0 + ta)) * QKVZ_N + CONV_DIM + h * 128;
    const float* zr1 = qkvz + ((size_t)(b * TT + t0 + tb)) * QKVZ_N + CONV_DIM + h * 128;
    __half* gr0 = goh + ((size_t)(b * TT + t0 + ta)) * VALUE_DIM + h * 128;
    __half* gr1 = goh + ((size_t)(b * TT + t0 + tb)) * VALUE_DIM + h * 128;
    #pragma unroll
    for (int d = 0; d < 16; d++) {
        const int dvi = dvg + 8 * d;
        const float z0 = zr0[dvi], z1 = zr1[dvi];
        const float g0 = o0[d] * sc0 * nws[dvi] * (1.f / (1.f + expf(-z0)));
        const float g1 = o1[d] * sc1 * nws[dvi] * (1.f / (1.f + expf(-z1)));
        gr0[dvi] = __float2half(g0);
        gr1[dvi] = __float2half(g1);
    }
}

// ---------------- launch -----------------------------------------------------
extern "C" void kernel_launch(void* const* d_in, const int* in_sizes, int n_in,
                              void* d_out, int out_size)
{
    const float* x          = (const float*)d_in[0];
    const int*   input_pos  = (const int*)  d_in[1];
    const float* W_qkvz     = (const float*)d_in[2];
    const float* W_b        = (const float*)d_in[3];
    const float* W_a        = (const float*)d_in[4];
    const float* conv_w     = (const float*)d_in[5];
    const float* norm_w     = (const float*)d_in[6];
    const float* W_out      = (const float*)d_in[7];
    const float* conv_state = (const float*)d_in[8];
    const float* rec_state  = (const float*)d_in[9];
    float* out = (float*)d_out;

    float *qkvz, *y, *beta, *alpha, *attb, *sinc, *spre, *cbuf;
    __half *xh, *wqt, *wot, *goh;
    cudaGetSymbolAddress((void**)&qkvz, g_qkvz);
    cudaGetSymbolAddress((void**)&y,    g_y);
    cudaGetSymbolAddress((void**)&beta, g_beta);
    cudaGetSymbolAddress((void**)&alpha,g_alpha);
    cudaGetSymbolAddress((void**)&attb, g_att);
    cudaGetSymbolAddress((void**)&sinc, g_sinc);
    cudaGetSymbolAddress((void**)&spre, g_spre);
    cudaGetSymbolAddress((void**)&cbuf, g_cc);
    cudaGetSymbolAddress((void**)&xh,  g_xh);
    cudaGetSymbolAddress((void**)&wqt, g_wqt);
    cudaGetSymbolAddress((void**)&wot, g_wot);
    cudaGetSymbolAddress((void**)&goh, g_goh);

    cudaFuncSetAttribute(h16gemm, cudaFuncAttributeMaxDynamicSharedMemorySize,
                         GEMM_SMEM);
    cudaFuncSetAttribute(chunkA, cudaFuncAttributeMaxDynamicSharedMemorySize,
                         SMA_BYTES);
    cudaFuncSetAttribute(chunkC, cudaFuncAttributeMaxDynamicSharedMemorySize,
                         SMC_BYTES);
    cudaFuncSetAttribute(ba2_kernel, cudaFuncAttributeMaxDynamicSharedMemorySize,
                         BA_SMEM);
    cudaFuncSetAttribute(conv2_kernel, cudaFuncAttributeMaxDynamicSharedMemorySize,
                         CONV_SMEM);

    // 0) operand prep
    to_half<<<(BT * CC / 8 + 255) / 256, 256>>>(x, xh, BT * CC / 8);
    transpose_half<<<dim3(QKVZ_N / 32, CC / 32), 256>>>(W_qkvz, wqt, CC, QKVZ_N);
    transpose_half<<<dim3(CC / 32, CC / 32), 256>>>(W_out, wot, CC, CC);

    // 1) qkvz = x @ W_qkvz
    h16gemm<<<dim3(QKVZ_N / 256, BT / 128), 256, GEMM_SMEM>>>(
        xh, wqt, qkvz, BT, QKVZ_N, CC);
    // 2) beta/alpha (tiled fp32 GEMM)
    ba2_kernel<<<BT / 64, 256, BA_SMEM>>>(x, W_b, W_a, beta, alpha);
    // 3) conv + silu + l2norm (time-tiled)
    conv2_kernel<<<dim3(8, BT / 8), 256, CONV_SMEM>>>(
        qkvz, conv_w, conv_state, input_pos, y);
    // 4) chunked recurrence: intra -> scan -> inter (+fused gate)
    chunkA<<<dim3(NCH, BH), 256, SMA_BYTES>>>(y, beta, alpha, attb, sinc, cbuf);
    chunkB<<<BH, 256>>>(sinc, spre, cbuf, rec_state, input_pos);
    chunkC<<<dim3(NCH, BH), 256, SMC_BYTES>>>(y, cbuf, spre, attb, qkvz,
                                              norm_w, goh);
    // 5) out = gated @ W_out
    h16gemm<<<dim3(CC / 256, BT / 128), 256, GEMM_SMEM>>>(
        goh, wot, out, BT, CC, CC);
}

// round 12
// speedup vs baseline: 1.3432x; 1.0063x over previous
#include <cuda_runtime.h>
#include <cuda_fp16.h>
#include <math.h>
#include <stdint.h>

// Problem constants
#define BB 2
#define TT 2048
#define CC 2048
#define HH 16
#define KEY_DIM 2048
#define VALUE_DIM 2048
#define CONV_DIM 6144
#define QKVZ_N 8192
#define BT 4096   // B*T
#define LCH 64
#define NCH (TT / LCH)   // 32 chunks
#define BH 32            // B*H

// ---------------- scratch (static device globals; no allocation) -------------
__device__ float g_qkvz[(size_t)BT * QKVZ_N];
__device__ float g_y[(size_t)BT * CONV_DIM];
__device__ float g_beta[(size_t)BT * HH];
__device__ float g_alpha[(size_t)BT * HH];
__device__ float g_att[(size_t)BT * VALUE_DIM];
__device__ __half g_xh[(size_t)BT * CC];
__device__ __half g_wqt[(size_t)QKVZ_N * CC];
__device__ __half g_wot[(size_t)CC * CC];
__device__ __half g_goh[(size_t)BT * CC];
__device__ float g_sinc[(size_t)BH * NCH * 16384];
__device__ float g_spre[(size_t)BH * NCH * 16384];
__device__ float g_cc[(size_t)BH * TT];

// ---------------- PTX helpers ------------------------------------------------
__device__ __forceinline__ uint32_t s2u(const void* p) {
    uint32_t a;
    asm("{ .reg .u64 t; cvta.to.shared.u64 t, %1; cvt.u32.u64 %0, t; }"
        : "=r"(a) : "l"(p));
    return a;
}
__device__ __forceinline__ void ldsm4(uint32_t* r, uint32_t addr) {
    asm volatile("ldmatrix.sync.aligned.m8n8.x4.shared.b16 {%0,%1,%2,%3}, [%4];"
                 : "=r"(r[0]), "=r"(r[1]), "=r"(r[2]), "=r"(r[3]) : "r"(addr));
}
__device__ __forceinline__ void mma168f16(float* d, const uint32_t* a,
                                          const uint32_t* b) {
    asm volatile(
        "mma.sync.aligned.m16n8k16.row.col.f32.f16.f16.f32 "
        "{%0,%1,%2,%3}, {%4,%5,%6,%7}, {%8,%9}, {%0,%1,%2,%3};\n"
        : "+f"(d[0]), "+f"(d[1]), "+f"(d[2]), "+f"(d[3])
        : "r"(a[0]), "r"(a[1]), "r"(a[2]), "r"(a[3]),
          "r"(b[0]), "r"(b[1]));
}

// ---------------- fp16 tensor-core GEMM (unchanged) --------------------------
#define STAGE_B 30720
#define GEMM_SMEM (2 * STAGE_B)

__global__ void __launch_bounds__(256)
h16gemm(const __half* __restrict__ A, const __half* __restrict__ Bt,
        float* __restrict__ Cm, int M, int N, int Kd)
{
    extern __shared__ char smem[];
    const uint32_t sb = s2u(smem);
    const int tid  = threadIdx.x;
    const int bm   = blockIdx.y * 128;
    const int bn   = blockIdx.x * 256;
    const int lane = tid & 31;
    const int warp = tid >> 5;
    const int wm   = (warp >> 2) * 64;
    const int wn   = (warp & 3) * 64;
    const int gid  = lane >> 2;
    const int tig  = lane & 3;

    const int lr = tid >> 2;
    const int lc = tid & 3;

    const __half* Ap = A  + (size_t)(bm + lr) * Kd + lc * 8;
    const __half* Bp = Bt + (size_t)(bn + lr) * Kd + lc * 8;
    const size_t a64 = (size_t)64 * Kd;

    float acc[4][8][4];
    #pragma unroll
    for (int i = 0; i < 4; i++)
        #pragma unroll
        for (int j = 0; j < 8; j++)
            #pragma unroll
            for (int r = 0; r < 4; r++) acc[i][j][r] = 0.f;

    {
        uint4 ra0 = *(const uint4*)Ap;
        uint4 ra1 = *(const uint4*)(Ap + a64);
        uint4 rb0 = *(const uint4*)Bp;
        uint4 rb1 = *(const uint4*)(Bp + a64);
        uint4 rb2 = *(const uint4*)(Bp + 2 * a64);
        uint4 rb3 = *(const uint4*)(Bp + 3 * a64);
        char* s0 = smem;
        *(uint4*)(s0 + lr * 80 + lc * 16)        = ra0;
        *(uint4*)(s0 + (lr + 64) * 80 + lc * 16) = ra1;
        char* s0b = s0 + 10240;
        *(uint4*)(s0b + lr * 80 + lc * 16)         = rb0;
        *(uint4*)(s0b + (lr + 64) * 80 + lc * 16)  = rb1;
        *(uint4*)(s0b + (lr + 128) * 80 + lc * 16) = rb2;
        *(uint4*)(s0b + (lr + 192) * 80 + lc * 16) = rb3;
    }
    __syncthreads();

    const int at = lane >> 3;
    const int arow = wm + (at & 1) * 8 + (lane & 7);
    const int akoff = (lane >> 4) * 16;
    const int brow = wn + (lane >> 4) * 8 + (lane & 7);
    const int bkoff = ((lane >> 3) & 1) * 16;

    const int nst = Kd / 32;
    for (int s = 0; s < nst; s++) {
        const bool more = (s + 1) < nst;
        uint4 ra0, ra1, rb0, rb1, rb2, rb3;
        if (more) {
            Ap += 32; Bp += 32;
            ra0 = *(const uint4*)Ap;
            ra1 = *(const uint4*)(Ap + a64);
            rb0 = *(const uint4*)Bp;
            rb1 = *(const uint4*)(Bp + a64);
            rb2 = *(const uint4*)(Bp + 2 * a64);
            rb3 = *(const uint4*)(Bp + 3 * a64);
        }

        const uint32_t base = sb + (uint32_t)(s & 1) * STAGE_B;
        #pragma unroll
        for (int ks = 0; ks < 2; ks++) {
            uint32_t aF[4][4], bF[4][4];
            const uint32_t ak = base + (uint32_t)(ks * 32 + akoff);
            #pragma unroll
            for (int mt = 0; mt < 4; mt++)
                ldsm4(aF[mt], ak + (uint32_t)(arow + mt * 16) * 80);
            const uint32_t bk = base + 10240u + (uint32_t)(ks * 32 + bkoff);
            #pragma unroll
            for (int np = 0; np < 4; np++)
                ldsm4(bF[np], bk + (uint32_t)(brow + np * 16) * 80);
            #pragma unroll
            for (int mt = 0; mt < 4; mt++)
                #pragma unroll
                for (int nt = 0; nt < 8; nt++)
                    mma168f16(acc[mt][nt], aF[mt], &bF[nt >> 1][(nt & 1) * 2]);
        }

        if (more) {
            char* sn = smem + ((s + 1) & 1) * STAGE_B;
            *(uint4*)(sn + lr * 80 + lc * 16)        = ra0;
            *(uint4*)(sn + (lr + 64) * 80 + lc * 16) = ra1;
            char* snb = sn + 10240;
            *(uint4*)(snb + lr * 80 + lc * 16)         = rb0;
            *(uint4*)(snb + (lr + 64) * 80 + lc * 16)  = rb1;
            *(uint4*)(snb + (lr + 128) * 80 + lc * 16) = rb2;
            *(uint4*)(snb + (lr + 192) * 80 + lc * 16) = rb3;
        }
        __syncthreads();
    }

    #pragma unroll
    for (int mt = 0; mt < 4; mt++) {
        const int row = bm + wm + mt * 16 + gid;
        #pragma unroll
        for (int nt = 0; nt < 8; nt++) {
            const int col = bn + wn + nt * 8 + 2 * tig;
            *(float2*)&Cm[(size_t)row * N + col]       = make_float2(acc[mt][nt][0], acc[mt][nt][1]);
            *(float2*)&Cm[(size_t)(row + 8) * N + col] = make_float2(acc[mt][nt][2], acc[mt][nt][3]);
        }
    }
}

// ---------------- f32 -> f16 convert -----------------------------------------
__global__ void __launch_bounds__(256)
to_half(const float* __restrict__ X, __half* __restrict__ Y, int n8)
{
    int i = blockIdx.x * 256 + threadIdx.x;
    if (i >= n8) return;
    float4 v0 = ((const float4*)X)[i * 2];
    float4 v1 = ((const float4*)X)[i * 2 + 1];
    __half2* H = (__half2*)Y;
    H[i * 4 + 0] = __floats2half2_rn(v0.x, v0.y);
    H[i * 4 + 1] = __floats2half2_rn(v0.z, v0.w);
    H[i * 4 + 2] = __floats2half2_rn(v1.x, v1.y);
    H[i * 4 + 3] = __floats2half2_rn(v1.z, v1.w);
}

// ---------------- transpose: W[K][N] f32 -> Wt[N][K] f16 ---------------------
__global__ void __launch_bounds__(256)
transpose_half(const float* __restrict__ W, __half* __restrict__ Th, int K, int N)
{
    __shared__ float tile[32][33];
    const int k0 = blockIdx.y * 32, n0 = blockIdx.x * 32;
    const int tx = threadIdx.x & 31, ty = threadIdx.x >> 5;
    #pragma unroll
    for (int r = 0; r < 32; r += 8)
        tile[ty + r][tx] = W[(size_t)(k0 + ty + r) * N + n0 + tx];
    __syncthreads();
    #pragma unroll
    for (int r = 0; r < 32; r += 8)
        Th[(size_t)(n0 + ty + r) * K + k0 + tx] = __float2half(tile[tx][ty + r]);
}

// ---------------- beta/alpha: tiled fp32 GEMM --------------------------------
#define BA_SMEM (64 * 132 * 4 + 128 * 32 * 4)
__global__ void __launch_bounds__(256)
ba2_kernel(const float* __restrict__ x, const float* __restrict__ Wb,
           const float* __restrict__ Wa, float* __restrict__ beta,
           float* __restrict__ alpha)
{
    extern __shared__ float sm[];
    float* xs = sm;
    float* ws = sm + 64 * 132;

    const int tid = threadIdx.x;
    const int r0 = blockIdx.x * 64;
    const int tr = tid >> 4;
    const int tc = tid & 15;

    float acc[4][2];
    #pragma unroll
    for (int i = 0; i < 4; i++) { acc[i][0] = 0.f; acc[i][1] = 0.f; }

    for (int k0 = 0; k0 < CC; k0 += 128) {
        #pragma unroll
        for (int i = 0; i < 8; i++) {
            const int idx = tid + i * 256;
            const int row = idx >> 5, c4 = (idx & 31) * 4;
            *(float4*)&xs[row * 132 + c4] =
                *(const float4*)&x[(size_t)(r0 + row) * CC + k0 + c4];
        }
        #pragma unroll
        for (int i = 0; i < 2; i++) {
            const int idx = tid + i * 256;
            const int kk = idx >> 2, q = (idx & 3) * 4;
            *(float4*)&ws[kk * 32 + q]      = *(const float4*)&Wb[(size_t)(k0 + kk) * HH + q];
            *(float4*)&ws[kk * 32 + 16 + q] = *(const float4*)&Wa[(size_t)(k0 + kk) * HH + q];
        }
        __syncthreads();

        for (int kk = 0; kk < 128; kk++) {
            const float2 wv = *(const float2*)&ws[kk * 32 + tc * 2];
            #pragma unroll
            for (int i = 0; i < 4; i++) {
                const float xv = xs[(tr * 4 + i) * 132 + kk];
                acc[i][0] = fmaf(xv, wv.x, acc[i][0]);
                acc[i][1] = fmaf(xv, wv.y, acc[i][1]);
            }
        }
        __syncthreads();
    }

    #pragma unroll
    for (int i = 0; i < 4; i++) {
        const int row = r0 + tr * 4 + i;
        #pragma unroll
        for (int j = 0; j < 2; j++) {
            const int c = tc * 2 + j;
            const float v = 1.f / (1.f + expf(-acc[i][j]));
            if (c < 16) beta[(size_t)row * HH + c] = v;
            else        alpha[(size_t)row * HH + (c - 16)] = v;
        }
    }
}

// ---------------- conv: time-tiled (unchanged) -------------------------------
#define CONV_SMEM ((11 * 768 + 8 * 768 + 48) * 4)
__global__ void __launch_bounds__(256)
conv2_kernel(const float* __restrict__ qkvz, const float* __restrict__ conv_w,
             const float* __restrict__ conv_state, const int* __restrict__ input_pos,
             float* __restrict__ y_out)
{
    extern __shared__ float sm[];
    float* in  = sm;
    float* yb  = sm + 11 * 768;
    float* nrm = sm + 19 * 768;

    const int cg = blockIdx.x;
    const int c0 = cg * 768;
    const int tgl = blockIdx.y;
    const int b = tgl >> 8;
    const int t0 = (tgl & 255) * 8;
    const int tid = threadIdx.x;
    const float keep = (input_pos[0] == 0) ? 0.f : 1.f;

    for (int idx = tid; idx < 11 * 192; idx += 256) {
        const int r = idx / 192, c4 = (idx % 192) * 4;
        const int tau = t0 - 3 + r;
        float4 v;
        if (tau >= 0) {
            v = *(const float4*)&qkvz[((size_t)(b * TT + tau)) * QKVZ_N + c0 + c4];
        } else {
            const int slot = tau + 4;
            v.x = keep * conv_state[((size_t)b * CONV_DIM + c0 + c4 + 0) * 4 + slot];
            v.y = keep * conv_state[((size_t)b * CONV_DIM + c0 + c4 + 1) * 4 + slot];
            v.z = keep * conv_state[((size_t)b * CONV_DIM + c0 + c4 + 2) * 4 + slot];
            v.w = keep * conv_state[((size_t)b * CONV_DIM + c0 + c4 + 3) * 4 + slot];
        }
        *(float4*)&in[r * 768 + c4] = v;
    }
    __syncthreads();

    for (int idx = tid; idx < 1536; idx += 256) {
        const int t = idx / 192, c4 = (idx % 192) * 4;
        float4 o;
        float* op = (float*)&o;
        #pragma unroll
        for (int e = 0; e < 4; e++) {
            const int c = c4 + e;
            const float4 w = *(const float4*)&conv_w[(size_t)(c0 + c) * 4];
            float acc = in[(t + 0) * 768 + c] * w.x + in[(t + 1) * 768 + c] * w.y
                      + in[(t + 2) * 768 + c] * w.z + in[(t + 3) * 768 + c] * w.w;
            op[e] = acc / (1.f + expf(-acc));
        }
        *(float4*)&yb[t * 768 + c4] = o;
    }
    __syncthreads();

    {
        const int w = tid >> 5, lane = tid & 31;
        for (int p = w; p < 48; p += 8) {
            const int t = p / 6, hl = p % 6;
            const int hg = (c0 >> 7) + hl;
            float ss = 0.f;
            #pragma unroll
            for (int i = 0; i < 4; i++) {
                const float v = yb[t * 768 + hl * 128 + lane + i * 32];
                ss = fmaf(v, v, ss);
            }
            #pragma unroll
            for (int off = 16; off > 0; off >>= 1)
                ss += __shfl_xor_sync(0xffffffffu, ss, off);
            if (lane == 0)
                nrm[t * 6 + hl] = (hg < 32) ? (1.f / fmaxf(sqrtf(ss), 1e-12f)) : 1.f;
        }
    }
    __syncthreads();

    for (int idx = tid; idx < 1536; idx += 256) {
        const int t = idx / 192, c4 = (idx % 192) * 4;
        const float inv = nrm[t * 6 + (c4 >> 7)];
        float4 v = *(const float4*)&yb[t * 768 + c4];
        v.x *= inv; v.y *= inv; v.z *= inv; v.w *= inv;
        *(float4*)&y_out[((size_t)(b * TT + t0 + t)) * CONV_DIM + c0 + c4] = v;
    }
}

// ---------------- chunked recurrence: phase A (vectorized LDS) ---------------
// smem layout (floats): qs[64][132], ksT[128][68], vs[64][132], P[64][68],
// cs[64], bs[64]  -> 30080 floats = 120320 B
#define SA_QS 0
#define SA_KT (64 * 132)
#define SA_VS (SA_KT + 128 * 68)
#define SA_P  (SA_VS + 64 * 132)
#define SA_CS (SA_P + 64 * 68)
#define SA_BS (SA_CS + 64)
#define SMA_BYTES ((SA_BS + 64) * 4)

__global__ void __launch_bounds__(256)
chunkA(const float* __restrict__ y, const float* __restrict__ beta,
       const float* __restrict__ alpha, float* __restrict__ att,
       float* __restrict__ sinc, float* __restrict__ cbuf)
{
    extern __shared__ float sm[];
    float* qs  = sm + SA_QS;
    float* ksT = sm + SA_KT;
    float* vs  = sm + SA_VS;
    float* P   = sm + SA_P;
    float* cs  = sm + SA_CS;
    float* bs  = sm + SA_BS;

    const int bh = blockIdx.y, j = blockIdx.x;
    const int b = bh >> 4, h = bh & 15;
    const int t0 = j * LCH;
    const int tid = threadIdx.x;

    for (int i = tid; i < 2048; i += 256) {
        const int row = i >> 5, c4 = (i & 31) * 4;
        const float* yr = y + ((size_t)(b * TT + t0 + row)) * CONV_DIM + h * 128;
        float4 q4 = *(const float4*)(yr + c4);
        float4 k4 = *(const float4*)(yr + KEY_DIM + c4);
        float4 v4 = *(const float4*)(yr + 2 * KEY_DIM + c4);
        *(float4*)&qs[row * 132 + c4] = q4;
        ksT[(c4 + 0) * 68 + row] = k4.x;
        ksT[(c4 + 1) * 68 + row] = k4.y;
        ksT[(c4 + 2) * 68 + row] = k4.z;
        ksT[(c4 + 3) * 68 + row] = k4.w;
        *(float4*)&vs[row * 132 + c4] = v4;
    }
    if (tid < 64) {
        cs[tid] = log2f(alpha[((size_t)(b * TT + t0 + tid)) * HH + h]);
        bs[tid] = beta[((size_t)(b * TT + t0 + tid)) * HH + h];
    }
    __syncthreads();
    if (tid == 0) {
        float run = 0.f;
        for (int t = 0; t < LCH; t++) { run += cs[t]; cs[t] = run; }
    }
    __syncthreads();
    if (tid < 64) cbuf[(size_t)bh * TT + t0 + tid] = cs[tid];

    // ---- P[t][tau] with float4 fragment loads ----
    {
        const int rt = tid >> 4, ct = tid & 15;
        float acc[4][4];
        #pragma unroll
        for (int i = 0; i < 4; i++)
            #pragma unroll
            for (int j2 = 0; j2 < 4; j2++) acc[i][j2] = 0.f;
        if (ct <= rt) {
            for (int kk0 = 0; kk0 < 128; kk0 += 4) {
                float4 qv[4], kv[4];
                #pragma unroll
                for (int i = 0; i < 4; i++)
                    qv[i] = *(const float4*)&qs[(rt * 4 + i) * 132 + kk0];
                #pragma unroll
                for (int q = 0; q < 4; q++)
                    kv[q] = *(const float4*)&ksT[(kk0 + q) * 68 + ct * 4];
                #pragma unroll
                for (int q = 0; q < 4; q++) {
                    const float* kq = (const float*)&kv[q];
                    #pragma unroll
                    for (int i = 0; i < 4; i++) {
                        const float qq = ((const float*)&qv[i])[q];
                        #pragma unroll
                        for (int j2 = 0; j2 < 4; j2++)
                            acc[i][j2] = fmaf(qq, kq[j2], acc[i][j2]);
                    }
                }
            }
        }
        #pragma unroll
        for (int i = 0; i < 4; i++)
            #pragma unroll
            for (int j2 = 0; j2 < 4; j2++) {
                const int t = rt * 4 + i, tau = ct * 4 + j2;
                float val = 0.f;
                if (tau <= t)
                    val = acc[i][j2] * bs[tau] * exp2f(cs[t] - cs[tau]);
                P[t * 68 + tau] = val;
            }
    }
    __syncthreads();

    // ---- o_intra = P @ v ; thread (tg, dvg): dv = dvg*4 + 32d + e ----
    {
        const int tg = tid >> 3, dvg = tid & 7;
        const int ta = tg * 2, tb = ta + 1;
        float4 o0[4], o1[4];
        #pragma unroll
        for (int d = 0; d < 4; d++) {
            o0[d] = make_float4(0.f, 0.f, 0.f, 0.f);
            o1[d] = make_float4(0.f, 0.f, 0.f, 0.f);
        }
        for (int tau = 0; tau < LCH; tau++) {
            const float p0 = P[ta * 68 + tau];
            const float p1 = P[tb * 68 + tau];
            const float* vr = vs + tau * 132;
            #pragma unroll
            for (int d = 0; d < 4; d++) {
                const float4 vv = *(const float4*)(vr + dvg * 4 + 32 * d);
                o0[d].x = fmaf(p0, vv.x, o0[d].x); o0[d].y = fmaf(p0, vv.y, o0[d].y);
                o0[d].z = fmaf(p0, vv.z, o0[d].z); o0[d].w = fmaf(p0, vv.w, o0[d].w);
                o1[d].x = fmaf(p1, vv.x, o1[d].x); o1[d].y = fmaf(p1, vv.y, o1[d].y);
                o1[d].z = fmaf(p1, vv.z, o1[d].z); o1[d].w = fmaf(p1, vv.w, o1[d].w);
            }
        }
        float* ar0 = att + ((size_t)(b * TT + t0 + ta)) * VALUE_DIM + h * 128;
        float* ar1 = att + ((size_t)(b * TT + t0 + tb)) * VALUE_DIM + h * 128;
        #pragma unroll
        for (int d = 0; d < 4; d++) {
            *(float4*)(ar0 + dvg * 4 + 32 * d) = o0[d];
            *(float4*)(ar1 + dvg * 4 + 32 * d) = o1[d];
        }
    }

    // ---- Sinc: thread (dkt, dvt): dk = dkt + 16i, dv = dvt*4 + 64dj + e ----
    {
        const int dkt = tid >> 4, dvt = tid & 15;
        float4 sacc[8][2];
        #pragma unroll
        for (int i = 0; i < 8; i++)
            #pragma unroll
            for (int dj = 0; dj < 2; dj++)
                sacc[i][dj] = make_float4(0.f, 0.f, 0.f, 0.f);
        const float cL = cs[63];
        for (int tau = 0; tau < LCH; tau++) {
            const float w = bs[tau] * exp2f(cL - cs[tau]);
            float kw[8];
            #pragma unroll
            for (int i = 0; i < 8; i++) kw[i] = ksT[(dkt + 16 * i) * 68 + tau] * w;
            float4 vv[2];
            #pragma unroll
            for (int dj = 0; dj < 2; dj++)
                vv[dj] = *(const float4*)&vs[tau * 132 + dvt * 4 + 64 * dj];
            #pragma unroll
            for (int i = 0; i < 8; i++)
                #pragma unroll
                for (int dj = 0; dj < 2; dj++) {
                    sacc[i][dj].x = fmaf(kw[i], vv[dj].x, sacc[i][dj].x);
                    sacc[i][dj].y = fmaf(kw[i], vv[dj].y, sacc[i][dj].y);
                    sacc[i][dj].z = fmaf(kw[i], vv[dj].z, sacc[i][dj].z);
                    sacc[i][dj].w = fmaf(kw[i], vv[dj].w, sacc[i][dj].w);
                }
        }
        float* sp = sinc + ((size_t)(bh * NCH + j)) * 16384;
        #pragma unroll
        for (int i = 0; i < 8; i++)
            #pragma unroll
            for (int dj = 0; dj < 2; dj++)
                *(float4*)&sp[(dkt + 16 * i) * 128 + dvt * 4 + 64 * dj] = sacc[i][dj];
    }
}

// ---------------- phase B (unchanged) ----------------------------------------
__global__ void __launch_bounds__(256)
chunkB(const float* __restrict__ sinc, float* __restrict__ spre,
       const float* __restrict__ cbuf, const float* __restrict__ rstate,
       const int* __restrict__ input_pos)
{
    const int bh = blockIdx.x;
    const int tid = threadIdx.x;
    const float keep = (input_pos[0] == 0) ? 0.f : 1.f;

    float s[64];
    #pragma unroll
    for (int i = 0; i < 64; i++)
        s[i] = keep * rstate[(size_t)bh * 16384 + tid + i * 256];

    for (int j = 0; j < NCH; j++) {
        const size_t base = ((size_t)(bh * NCH + j)) * 16384;
        #pragma unroll
        for (int i = 0; i < 64; i++)
            spre[base + tid + i * 256] = s[i];
        const float dec = exp2f(cbuf[(size_t)bh * TT + j * LCH + 63]);
        #pragma unroll
        for (int i = 0; i < 64; i++)
            s[i] = fmaf(dec, s[i], sinc[base + tid + i * 256]);
    }
}

// ---------------- phase C fused with gate (vectorized) -----------------------
// smem: S[128][132] + qs[64][132] + cs[64] + nws[128] = 25536 floats
#define SMC_BYTES (25536 * 4)
__global__ void __launch_bounds__(256)
chunkC(const float* __restrict__ y, const float* __restrict__ cbuf,
       const float* __restrict__ spre, const float* __restrict__ att,
       const float* __restrict__ qkvz, const float* __restrict__ norm_w,
       __half* __restrict__ goh)
{
    extern __shared__ float sm[];
    float* S   = sm;                         // [128][132]
    float* qs  = sm + 128 * 132;             // [64][132]
    float* cs  = qs + 64 * 132;
    float* nws = cs + 64;

    const int bh = blockIdx.y, j = blockIdx.x;
    const int b = bh >> 4, h = bh & 15;
    const int t0 = j * LCH;
    const int tid = threadIdx.x;

    const float* sp = spre + ((size_t)(bh * NCH + j)) * 16384;
    for (int i = tid; i < 4096; i += 256) {
        const int dk = i >> 5, dv4 = (i & 31) * 4;
        *(float4*)&S[dk * 132 + dv4] = *(const float4*)&sp[dk * 128 + dv4];
    }
    for (int i = tid; i < 2048; i += 256) {
        const int row = i >> 5, c4 = (i & 31) * 4;
        const float* yr = y + ((size_t)(b * TT + t0 + row)) * CONV_DIM + h * 128;
        *(float4*)&qs[row * 132 + c4] = *(const float4*)(yr + c4);
    }
    if (tid < 64) cs[tid] = cbuf[(size_t)bh * TT + t0 + tid];
    if (tid < 128) nws[tid] = norm_w[tid];
    __syncthreads();

    const int tg = tid >> 3, dvg = tid & 7;
    const int ta = tg * 2, tb = ta + 1;
    float4 o0[4], o1[4];
    #pragma unroll
    for (int d = 0; d < 4; d++) {
        o0[d] = make_float4(0.f, 0.f, 0.f, 0.f);
        o1[d] = make_float4(0.f, 0.f, 0.f, 0.f);
    }
    for (int dk = 0; dk < 128; dk++) {
        const float q0 = qs[ta * 132 + dk];
        const float q1 = qs[tb * 132 + dk];
        const float* srow = S + dk * 132;
        #pragma unroll
        for (int d = 0; d < 4; d++) {
            const float4 sv = *(const float4*)(srow + dvg * 4 + 32 * d);
            o0[d].x = fmaf(q0, sv.x, o0[d].x); o0[d].y = fmaf(q0, sv.y, o0[d].y);
            o0[d].z = fmaf(q0, sv.z, o0[d].z); o0[d].w = fmaf(q0, sv.w, o0[d].w);
            o1[d].x = fmaf(q1, sv.x, o1[d].x); o1[d].y = fmaf(q1, sv.y, o1[d].y);
            o1[d].z = fmaf(q1, sv.z, o1[d].z); o1[d].w = fmaf(q1, sv.w, o1[d].w);
        }
    }
    const float e0 = exp2f(cs[ta]);
    const float e1 = exp2f(cs[tb]);

    const float* ar0 = att + ((size_t)(b * TT + t0 + ta)) * VALUE_DIM + h * 128;
    const float* ar1 = att + ((size_t)(b * TT + t0 + tb)) * VALUE_DIM + h * 128;
    float ss0 = 0.f, ss1 = 0.f;
    #pragma unroll
    for (int d = 0; d < 4; d++) {
        const float4 a0 = *(const float4*)(ar0 + dvg * 4 + 32 * d);
        const float4 a1 = *(const float4*)(ar1 + dvg * 4 + 32 * d);
        o0[d].x = a0.x + e0 * o0[d].x;  o0[d].y = a0.y + e0 * o0[d].y;
        o0[d].z = a0.z + e0 * o0[d].z;  o0[d].w = a0.w + e0 * o0[d].w;
        o1[d].x = a1.x + e1 * o1[d].x;  o1[d].y = a1.y + e1 * o1[d].y;
        o1[d].z = a1.z + e1 * o1[d].z;  o1[d].w = a1.w + e1 * o1[d].w;
        ss0 = fmaf(o0[d].x, o0[d].x, ss0); ss0 = fmaf(o0[d].y, o0[d].y, ss0);
        ss0 = fmaf(o0[d].z, o0[d].z, ss0); ss0 = fmaf(o0[d].w, o0[d].w, ss0);
        ss1 = fmaf(o1[d].x, o1[d].x, ss1); ss1 = fmaf(o1[d].y, o1[d].y, ss1);
        ss1 = fmaf(o1[d].z, o1[d].z, ss1); ss1 = fmaf(o1[d].w, o1[d].w, ss1);
    }
    #pragma unroll
    for (int off = 1; off < 8; off <<= 1) {
        ss0 += __shfl_xor_sync(0xffffffffu, ss0, off);
        ss1 += __shfl_xor_sync(0xffffffffu, ss1, off);
    }
    const float sc0 = rsqrtf(ss0 * (1.f / 128.f) + 1e-6f);
    const float sc1 = rsqrtf(ss1 * (1.f / 128.f) + 1e-6f);

    const float* zr0 = qkvz + ((size_t)(b * TT + t0 + ta)) * QKVZ_N + CONV_DIM + h * 128;
    const float* zr1 = qkvz + ((size_t)(b * TT + t0 + tb)) * QKVZ_N + CONV_DIM + h * 128;
    __half* gr0 = goh + ((size_t)(b * TT + t0 + ta)) * VALUE_DIM + h * 128;
    __half* gr1 = goh + ((size_t)(b * TT + t0 + tb)) * VALUE_DIM + h * 128;
    #pragma unroll
    for (int d = 0; d < 4; d++) {
        const int dvi = dvg * 4 + 32 * d;
        const float4 z0 = *(const float4*)(zr0 + dvi);
        const float4 z1 = *(const float4*)(zr1 + dvi);
        const float4 nw = *(const float4*)(nws + dvi);
        __half2 h0a = __floats2half2_rn(
            o0[d].x * sc0 * nw.x * (1.f / (1.f + expf(-z0.x))),
            o0[d].y * sc0 * nw.y * (1.f / (1.f + expf(-z0.y))));
        __half2 h0b = __floats2half2_rn(
            o0[d].z * sc0 * nw.z * (1.f / (1.f + expf(-z0.z))),
            o0[d].w * sc0 * nw.w * (1.f / (1.f + expf(-z0.w))));
        __half2 h1a = __floats2half2_rn(
            o1[d].x * sc1 * nw.x * (1.f / (1.f + expf(-z1.x))),
            o1[d].y * sc1 * nw.y * (1.f / (1.f + expf(-z1.y))));
        __half2 h1b = __floats2half2_rn(
            o1[d].z * sc1 * nw.z * (1.f / (1.f + expf(-z1.z))),
            o1[d].w * sc1 * nw.w * (1.f / (1.f + expf(-z1.w))));
        *(__half2*)(gr0 + dvi)     = h0a;
        *(__half2*)(gr0 + dvi + 2) = h0b;
        *(__half2*)(gr1 + dvi)     = h1a;
        *(__half2*)(gr1 + dvi + 2) = h1b;
    }
}

// ---------------- launch -----------------------------------------------------
extern "C" void kernel_launch(void* const* d_in, const int* in_sizes, int n_in,
                              void* d_out, int out_size)
{
    const float* x          = (const float*)d_in[0];
    const int*   input_pos  = (const int*)  d_in[1];
    const float* W_qkvz     = (const float*)d_in[2];
    const float* W_b        = (const float*)d_in[3];
    const float* W_a        = (const float*)d_in[4];
    const float* conv_w     = (const float*)d_in[5];
    const float* norm_w     = (const float*)d_in[6];
    const float* W_out      = (const float*)d_in[7];
    const float* conv_state = (const float*)d_in[8];
    const float* rec_state  = (const float*)d_in[9];
    float* out = (float*)d_out;

    float *qkvz, *y, *beta, *alpha, *attb, *sinc, *spre, *cbuf;
    __half *xh, *wqt, *wot, *goh;
    cudaGetSymbolAddress((void**)&qkvz, g_qkvz);
    cudaGetSymbolAddress((void**)&y,    g_y);
    cudaGetSymbolAddress((void**)&beta, g_beta);
    cudaGetSymbolAddress((void**)&alpha,g_alpha);
    cudaGetSymbolAddress((void**)&attb, g_att);
    cudaGetSymbolAddress((void**)&sinc, g_sinc);
    cudaGetSymbolAddress((void**)&spre, g_spre);
    cudaGetSymbolAddress((void**)&cbuf, g_cc);
    cudaGetSymbolAddress((void**)&xh,  g_xh);
    cudaGetSymbolAddress((void**)&wqt, g_wqt);
    cudaGetSymbolAddress((void**)&wot, g_wot);
    cudaGetSymbolAddress((void**)&goh, g_goh);

    cudaFuncSetAttribute(h16gemm, cudaFuncAttributeMaxDynamicSharedMemorySize,
                         GEMM_SMEM);
    cudaFuncSetAttribute(chunkA, cudaFuncAttributeMaxDynamicSharedMemorySize,
                         SMA_BYTES);
    cudaFuncSetAttribute(chunkC, cudaFuncAttributeMaxDynamicSharedMemorySize,
                         SMC_BYTES);
    cudaFuncSetAttribute(ba2_kernel, cudaFuncAttributeMaxDynamicSharedMemorySize,
                         BA_SMEM);
    cudaFuncSetAttribute(conv2_kernel, cudaFuncAttributeMaxDynamicSharedMemorySize,
                         CONV_SMEM);

    // 0) operand prep
    to_half<<<(BT * CC / 8 + 255) / 256, 256>>>(x, xh, BT * CC / 8);
    transpose_half<<<dim3(QKVZ_N / 32, CC / 32), 256>>>(W_qkvz, wqt, CC, QKVZ_N);
    transpose_half<<<dim3(CC / 32, CC / 32), 256>>>(W_out, wot, CC, CC);

    // 1) qkvz = x @ W_qkvz
    h16gemm<<<dim3(QKVZ_N / 256, BT / 128), 256, GEMM_SMEM>>>(
        xh, wqt, qkvz, BT, QKVZ_N, CC);
    // 2) beta/alpha
    ba2_kernel<<<BT / 64, 256, BA_SMEM>>>(x, W_b, W_a, beta, alpha);
    // 3) conv + silu + l2norm
    conv2_kernel<<<dim3(8, BT / 8), 256, CONV_SMEM>>>(
        qkvz, conv_w, conv_state, input_pos, y);
    // 4) chunked recurrence
    chunkA<<<dim3(NCH, BH), 256, SMA_BYTES>>>(y, beta, alpha, attb, sinc, cbuf);
    chunkB<<<BH, 256>>>(sinc, spre, cbuf, rec_state, input_pos);
    chunkC<<<dim3(NCH, BH), 256, SMC_BYTES>>>(y, cbuf, spre, attb, qkvz,
                                              norm_w, goh);
    // 5) out = gated @ W_out
    h16gemm<<<dim3(CC / 256, BT / 128), 256, GEMM_SMEM>>>(
        goh, wot, out, BT, CC, CC);
}

// round 13
// speedup vs baseline: 1.6295x; 1.2132x over previous
#include <cuda_runtime.h>
#include <cuda_fp16.h>
#include <math.h>
#include <stdint.h>

// Problem constants
#define BB 2
#define TT 2048
#define CC 2048
#define HH 16
#define KEY_DIM 2048
#define VALUE_DIM 2048
#define CONV_DIM 6144
#define QKVZ_N 8192
#define BT 4096   // B*T
#define LCH 64
#define NCH (TT / LCH)   // 32 chunks
#define BH 32            // B*H

// ---------------- scratch (static device globals; no allocation) -------------
__device__ float g_qkvz[(size_t)BT * QKVZ_N];
__device__ float g_y[(size_t)BT * CONV_DIM];
__device__ float g_beta[(size_t)BT * HH];
__device__ float g_alpha[(size_t)BT * HH];
__device__ float g_att[(size_t)BT * VALUE_DIM];
__device__ __half g_xh[(size_t)BT * CC];
__device__ __half g_wqt[(size_t)QKVZ_N * CC];
__device__ __half g_wot[(size_t)CC * CC];
__device__ __half g_goh[(size_t)BT * CC];
__device__ float g_sinc[(size_t)BH * NCH * 16384];
__device__ float g_spre[(size_t)BH * NCH * 16384];
__device__ float g_cc[(size_t)BH * TT];

// ---------------- PTX helpers ------------------------------------------------
__device__ __forceinline__ uint32_t s2u(const void* p) {
    uint32_t a;
    asm("{ .reg .u64 t; cvta.to.shared.u64 t, %1; cvt.u32.u64 %0, t; }"
        : "=r"(a) : "l"(p));
    return a;
}
__device__ __forceinline__ void ldsm4(uint32_t* r, uint32_t addr) {
    asm volatile("ldmatrix.sync.aligned.m8n8.x4.shared.b16 {%0,%1,%2,%3}, [%4];"
                 : "=r"(r[0]), "=r"(r[1]), "=r"(r[2]), "=r"(r[3]) : "r"(addr));
}
__device__ __forceinline__ void mma168f16(float* d, const uint32_t* a,
                                          const uint32_t* b) {
    asm volatile(
        "mma.sync.aligned.m16n8k16.row.col.f32.f16.f16.f32 "
        "{%0,%1,%2,%3}, {%4,%5,%6,%7}, {%8,%9}, {%0,%1,%2,%3};\n"
        : "+f"(d[0]), "+f"(d[1]), "+f"(d[2]), "+f"(d[3])
        : "r"(a[0]), "r"(a[1]), "r"(a[2]), "r"(a[3]),
          "r"(b[0]), "r"(b[1]));
}

// ---------------- fp16 tensor-core GEMM, 2 CTAs/SM ---------------------------
// C[M,N] = A[M,K] * B^T. CTA tile 128x128, BK=32, 256 threads, 8 warps (2x4),
// warp tile 64x32, acc = 64 regs -> fits 128 regs, 2 CTAs/SM resident.
// Stage = (128+128) rows x 80B = 20480B; double-buffered 40KB.
#define STAGE_B 20480
#define GEMM_SMEM (2 * STAGE_B)

__global__ void __launch_bounds__(256, 2)
h16gemm(const __half* __restrict__ A, const __half* __restrict__ Bt,
        float* __restrict__ Cm, int M, int N, int Kd)
{
    extern __shared__ char smem[];
    const uint32_t sb = s2u(smem);
    const int tid  = threadIdx.x;
    const int bm   = blockIdx.y * 128;
    const int bn   = blockIdx.x * 128;
    const int lane = tid & 31;
    const int warp = tid >> 5;
    const int wm   = (warp >> 2) * 64;   // 0 / 64
    const int wn   = (warp & 3) * 32;    // 0 / 32 / 64 / 96
    const int gid  = lane >> 2;
    const int tig  = lane & 3;

    const int lr = tid >> 2;             // 0..63
    const int lc = tid & 3;              // k-chunk 0..3 (8 halves each)

    const __half* Ap = A  + (size_t)(bm + lr) * Kd + lc * 8;
    const __half* Bp = Bt + (size_t)(bn + lr) * Kd + lc * 8;
    const size_t a64 = (size_t)64 * Kd;

    float acc[4][4][4];
    #pragma unroll
    for (int i = 0; i < 4; i++)
        #pragma unroll
        for (int j = 0; j < 4; j++)
            #pragma unroll
            for (int r = 0; r < 4; r++) acc[i][j][r] = 0.f;

    {
        uint4 ra0 = *(const uint4*)Ap;
        uint4 ra1 = *(const uint4*)(Ap + a64);
        uint4 rb0 = *(const uint4*)Bp;
        uint4 rb1 = *(const uint4*)(Bp + a64);
        char* s0 = smem;
        *(uint4*)(s0 + lr * 80 + lc * 16)        = ra0;
        *(uint4*)(s0 + (lr + 64) * 80 + lc * 16) = ra1;
        char* s0b = s0 + 10240;
        *(uint4*)(s0b + lr * 80 + lc * 16)        = rb0;
        *(uint4*)(s0b + (lr + 64) * 80 + lc * 16) = rb1;
    }
    __syncthreads();

    const int at = lane >> 3;
    const int arow = wm + (at & 1) * 8 + (lane & 7);
    const int akoff = (lane >> 4) * 16;
    const int brow = wn + (lane >> 4) * 8 + (lane & 7);
    const int bkoff = ((lane >> 3) & 1) * 16;

    const int nst = Kd / 32;
    for (int s = 0; s < nst; s++) {
        const bool more = (s + 1) < nst;
        uint4 ra0, ra1, rb0, rb1;
        if (more) {
            Ap += 32; Bp += 32;
            ra0 = *(const uint4*)Ap;
            ra1 = *(const uint4*)(Ap + a64);
            rb0 = *(const uint4*)Bp;
            rb1 = *(const uint4*)(Bp + a64);
        }

        const uint32_t base = sb + (uint32_t)(s & 1) * STAGE_B;
        #pragma unroll
        for (int ks = 0; ks < 2; ks++) {
            uint32_t aF[4][4], bF[2][4];
            const uint32_t ak = base + (uint32_t)(ks * 32 + akoff);
            #pragma unroll
            for (int mt = 0; mt < 4; mt++)
                ldsm4(aF[mt], ak + (uint32_t)(arow + mt * 16) * 80);
            const uint32_t bk = base + 10240u + (uint32_t)(ks * 32 + bkoff);
            #pragma unroll
            for (int np = 0; np < 2; np++)
                ldsm4(bF[np], bk + (uint32_t)(brow + np * 16) * 80);
            #pragma unroll
            for (int mt = 0; mt < 4; mt++)
                #pragma unroll
                for (int nt = 0; nt < 4; nt++)
                    mma168f16(acc[mt][nt], aF[mt], &bF[nt >> 1][(nt & 1) * 2]);
        }

        if (more) {
            char* sn = smem + ((s + 1) & 1) * STAGE_B;
            *(uint4*)(sn + lr * 80 + lc * 16)        = ra0;
            *(uint4*)(sn + (lr + 64) * 80 + lc * 16) = ra1;
            char* snb = sn + 10240;
            *(uint4*)(snb + lr * 80 + lc * 16)        = rb0;
            *(uint4*)(snb + (lr + 64) * 80 + lc * 16) = rb1;
        }
        __syncthreads();
    }

    #pragma unroll
    for (int mt = 0; mt < 4; mt++) {
        const int row = bm + wm + mt * 16 + gid;
        #pragma unroll
        for (int nt = 0; nt < 4; nt++) {
            const int col = bn + wn + nt * 8 + 2 * tig;
            *(float2*)&Cm[(size_t)row * N + col]       = make_float2(acc[mt][nt][0], acc[mt][nt][1]);
            *(float2*)&Cm[(size_t)(row + 8) * N + col] = make_float2(acc[mt][nt][2], acc[mt][nt][3]);
        }
    }
}

// ---------------- f32 -> f16 convert -----------------------------------------
__global__ void __launch_bounds__(256)
to_half(const float* __restrict__ X, __half* __restrict__ Y, int n8)
{
    int i = blockIdx.x * 256 + threadIdx.x;
    if (i >= n8) return;
    float4 v0 = ((const float4*)X)[i * 2];
    float4 v1 = ((const float4*)X)[i * 2 + 1];
    __half2* H = (__half2*)Y;
    H[i * 4 + 0] = __floats2half2_rn(v0.x, v0.y);
    H[i * 4 + 1] = __floats2half2_rn(v0.z, v0.w);
    H[i * 4 + 2] = __floats2half2_rn(v1.x, v1.y);
    H[i * 4 + 3] = __floats2half2_rn(v1.z, v1.w);
}

// ---------------- transpose: W[K][N] f32 -> Wt[N][K] f16 ---------------------
__global__ void __launch_bounds__(256)
transpose_half(const float* __restrict__ W, __half* __restrict__ Th, int K, int N)
{
    __shared__ float tile[32][33];
    const int k0 = blockIdx.y * 32, n0 = blockIdx.x * 32;
    const int tx = threadIdx.x & 31, ty = threadIdx.x >> 5;
    #pragma unroll
    for (int r = 0; r < 32; r += 8)
        tile[ty + r][tx] = W[(size_t)(k0 + ty + r) * N + n0 + tx];
    __syncthreads();
    #pragma unroll
    for (int r = 0; r < 32; r += 8)
        Th[(size_t)(n0 + ty + r) * K + k0 + tx] = __float2half(tile[tx][ty + r]);
}

// ---------------- beta/alpha: tiled fp32 GEMM --------------------------------
#define BA_SMEM (64 * 132 * 4 + 128 * 32 * 4)
__global__ void __launch_bounds__(256)
ba2_kernel(const float* __restrict__ x, const float* __restrict__ Wb,
           const float* __restrict__ Wa, float* __restrict__ beta,
           float* __restrict__ alpha)
{
    extern __shared__ float sm[];
    float* xs = sm;
    float* ws = sm + 64 * 132;

    const int tid = threadIdx.x;
    const int r0 = blockIdx.x * 64;
    const int tr = tid >> 4;
    const int tc = tid & 15;

    float acc[4][2];
    #pragma unroll
    for (int i = 0; i < 4; i++) { acc[i][0] = 0.f; acc[i][1] = 0.f; }

    for (int k0 = 0; k0 < CC; k0 += 128) {
        #pragma unroll
        for (int i = 0; i < 8; i++) {
            const int idx = tid + i * 256;
            const int row = idx >> 5, c4 = (idx & 31) * 4;
            *(float4*)&xs[row * 132 + c4] =
                *(const float4*)&x[(size_t)(r0 + row) * CC + k0 + c4];
        }
        #pragma unroll
        for (int i = 0; i < 2; i++) {
            const int idx = tid + i * 256;
            const int kk = idx >> 2, q = (idx & 3) * 4;
            *(float4*)&ws[kk * 32 + q]      = *(const float4*)&Wb[(size_t)(k0 + kk) * HH + q];
            *(float4*)&ws[kk * 32 + 16 + q] = *(const float4*)&Wa[(size_t)(k0 + kk) * HH + q];
        }
        __syncthreads();

        for (int kk = 0; kk < 128; kk++) {
            const float2 wv = *(const float2*)&ws[kk * 32 + tc * 2];
            #pragma unroll
            for (int i = 0; i < 4; i++) {
                const float xv = xs[(tr * 4 + i) * 132 + kk];
                acc[i][0] = fmaf(xv, wv.x, acc[i][0]);
                acc[i][1] = fmaf(xv, wv.y, acc[i][1]);
            }
        }
        __syncthreads();
    }

    #pragma unroll
    for (int i = 0; i < 4; i++) {
        const int row = r0 + tr * 4 + i;
        #pragma unroll
        for (int j = 0; j < 2; j++) {
            const int c = tc * 2 + j;
            const float v = 1.f / (1.f + expf(-acc[i][j]));
            if (c < 16) beta[(size_t)row * HH + c] = v;
            else        alpha[(size_t)row * HH + (c - 16)] = v;
        }
    }
}

// ---------------- conv: time-tiled -------------------------------------------
#define CONV_SMEM ((11 * 768 + 8 * 768 + 48) * 4)
__global__ void __launch_bounds__(256)
conv2_kernel(const float* __restrict__ qkvz, const float* __restrict__ conv_w,
             const float* __restrict__ conv_state, const int* __restrict__ input_pos,
             float* __restrict__ y_out)
{
    extern __shared__ float sm[];
    float* in  = sm;
    float* yb  = sm + 11 * 768;
    float* nrm = sm + 19 * 768;

    const int cg = blockIdx.x;
    const int c0 = cg * 768;
    const int tgl = blockIdx.y;
    const int b = tgl >> 8;
    const int t0 = (tgl & 255) * 8;
    const int tid = threadIdx.x;
    const float keep = (input_pos[0] == 0) ? 0.f : 1.f;

    for (int idx = tid; idx < 11 * 192; idx += 256) {
        const int r = idx / 192, c4 = (idx % 192) * 4;
        const int tau = t0 - 3 + r;
        float4 v;
        if (tau >= 0) {
            v = *(const float4*)&qkvz[((size_t)(b * TT + tau)) * QKVZ_N + c0 + c4];
        } else {
            const int slot = tau + 4;
            v.x = keep * conv_state[((size_t)b * CONV_DIM + c0 + c4 + 0) * 4 + slot];
            v.y = keep * conv_state[((size_t)b * CONV_DIM + c0 + c4 + 1) * 4 + slot];
            v.z = keep * conv_state[((size_t)b * CONV_DIM + c0 + c4 + 2) * 4 + slot];
            v.w = keep * conv_state[((size_t)b * CONV_DIM + c0 + c4 + 3) * 4 + slot];
        }
        *(float4*)&in[r * 768 + c4] = v;
    }
    __syncthreads();

    for (int idx = tid; idx < 1536; idx += 256) {
        const int t = idx / 192, c4 = (idx % 192) * 4;
        float4 o;
        float* op = (float*)&o;
        #pragma unroll
        for (int e = 0; e < 4; e++) {
            const int c = c4 + e;
            const float4 w = *(const float4*)&conv_w[(size_t)(c0 + c) * 4];
            float acc = in[(t + 0) * 768 + c] * w.x + in[(t + 1) * 768 + c] * w.y
                      + in[(t + 2) * 768 + c] * w.z + in[(t + 3) * 768 + c] * w.w;
            op[e] = acc / (1.f + expf(-acc));
        }
        *(float4*)&yb[t * 768 + c4] = o;
    }
    __syncthreads();

    {
        const int w = tid >> 5, lane = tid & 31;
        for (int p = w; p < 48; p += 8) {
            const int t = p / 6, hl = p % 6;
            const int hg = (c0 >> 7) + hl;
            float ss = 0.f;
            #pragma unroll
            for (int i = 0; i < 4; i++) {
                const float v = yb[t * 768 + hl * 128 + lane + i * 32];
                ss = fmaf(v, v, ss);
            }
            #pragma unroll
            for (int off = 16; off > 0; off >>= 1)
                ss += __shfl_xor_sync(0xffffffffu, ss, off);
            if (lane == 0)
                nrm[t * 6 + hl] = (hg < 32) ? (1.f / fmaxf(sqrtf(ss), 1e-12f)) : 1.f;
        }
    }
    __syncthreads();

    for (int idx = tid; idx < 1536; idx += 256) {
        const int t = idx / 192, c4 = (idx % 192) * 4;
        const float inv = nrm[t * 6 + (c4 >> 7)];
        float4 v = *(const float4*)&yb[t * 768 + c4];
        v.x *= inv; v.y *= inv; v.z *= inv; v.w *= inv;
        *(float4*)&y_out[((size_t)(b * TT + t0 + t)) * CONV_DIM + c0 + c4] = v;
    }
}

// ---------------- chunked recurrence: phase A --------------------------------
#define SA_QS 0
#define SA_KT (64 * 132)
#define SA_VS (SA_KT + 128 * 68)
#define SA_P  (SA_VS + 64 * 132)
#define SA_CS (SA_P + 64 * 68)
#define SA_BS (SA_CS + 64)
#define SMA_BYTES ((SA_BS + 64) * 4)

__global__ void __launch_bounds__(256)
chunkA(const float* __restrict__ y, const float* __restrict__ beta,
       const float* __restrict__ alpha, float* __restrict__ att,
       float* __restrict__ sinc, float* __restrict__ cbuf)
{
    extern __shared__ float sm[];
    float* qs  = sm + SA_QS;
    float* ksT = sm + SA_KT;
    float* vs  = sm + SA_VS;
    float* P   = sm + SA_P;
    float* cs  = sm + SA_CS;
    float* bs  = sm + SA_BS;

    const int bh = blockIdx.y, j = blockIdx.x;
    const int b = bh >> 4, h = bh & 15;
    const int t0 = j * LCH;
    const int tid = threadIdx.x;

    for (int i = tid; i < 2048; i += 256) {
        const int row = i >> 5, c4 = (i & 31) * 4;
        const float* yr = y + ((size_t)(b * TT + t0 + row)) * CONV_DIM + h * 128;
        float4 q4 = *(const float4*)(yr + c4);
        float4 k4 = *(const float4*)(yr + KEY_DIM + c4);
        float4 v4 = *(const float4*)(yr + 2 * KEY_DIM + c4);
        *(float4*)&qs[row * 132 + c4] = q4;
        ksT[(c4 + 0) * 68 + row] = k4.x;
        ksT[(c4 + 1) * 68 + row] = k4.y;
        ksT[(c4 + 2) * 68 + row] = k4.z;
        ksT[(c4 + 3) * 68 + row] = k4.w;
        *(float4*)&vs[row * 132 + c4] = v4;
    }
    if (tid < 64) {
        cs[tid] = log2f(alpha[((size_t)(b * TT + t0 + tid)) * HH + h]);
        bs[tid] = beta[((size_t)(b * TT + t0 + tid)) * HH + h];
    }
    __syncthreads();
    if (tid == 0) {
        float run = 0.f;
        for (int t = 0; t < LCH; t++) { run += cs[t]; cs[t] = run; }
    }
    __syncthreads();
    if (tid < 64) cbuf[(size_t)bh * TT + t0 + tid] = cs[tid];

    {
        const int rt = tid >> 4, ct = tid & 15;
        float acc[4][4];
        #pragma unroll
        for (int i = 0; i < 4; i++)
            #pragma unroll
            for (int j2 = 0; j2 < 4; j2++) acc[i][j2] = 0.f;
        if (ct <= rt) {
            for (int kk0 = 0; kk0 < 128; kk0 += 4) {
                float4 qv[4], kv[4];
                #pragma unroll
                for (int i = 0; i < 4; i++)
                    qv[i] = *(const float4*)&qs[(rt * 4 + i) * 132 + kk0];
                #pragma unroll
                for (int q = 0; q < 4; q++)
                    kv[q] = *(const float4*)&ksT[(kk0 + q) * 68 + ct * 4];
                #pragma unroll
                for (int q = 0; q < 4; q++) {
                    const float* kq = (const float*)&kv[q];
                    #pragma unroll
                    for (int i = 0; i < 4; i++) {
                        const float qq = ((const float*)&qv[i])[q];
                        #pragma unroll
                        for (int j2 = 0; j2 < 4; j2++)
                            acc[i][j2] = fmaf(qq, kq[j2], acc[i][j2]);
                    }
                }
            }
        }
        #pragma unroll
        for (int i = 0; i < 4; i++)
            #pragma unroll
            for (int j2 = 0; j2 < 4; j2++) {
                const int t = rt * 4 + i, tau = ct * 4 + j2;
                float val = 0.f;
                if (tau <= t)
                    val = acc[i][j2] * bs[tau] * exp2f(cs[t] - cs[tau]);
                P[t * 68 + tau] = val;
            }
    }
    __syncthreads();

    {
        const int tg = tid >> 3, dvg = tid & 7;
        const int ta = tg * 2, tb = ta + 1;
        float4 o0[4], o1[4];
        #pragma unroll
        for (int d = 0; d < 4; d++) {
            o0[d] = make_float4(0.f, 0.f, 0.f, 0.f);
            o1[d] = make_float4(0.f, 0.f, 0.f, 0.f);
        }
        for (int tau = 0; tau < LCH; tau++) {
            const float p0 = P[ta * 68 + tau];
            const float p1 = P[tb * 68 + tau];
            const float* vr = vs + tau * 132;
            #pragma unroll
            for (int d = 0; d < 4; d++) {
                const float4 vv = *(const float4*)(vr + dvg * 4 + 32 * d);
                o0[d].x = fmaf(p0, vv.x, o0[d].x); o0[d].y = fmaf(p0, vv.y, o0[d].y);
                o0[d].z = fmaf(p0, vv.z, o0[d].z); o0[d].w = fmaf(p0, vv.w, o0[d].w);
                o1[d].x = fmaf(p1, vv.x, o1[d].x); o1[d].y = fmaf(p1, vv.y, o1[d].y);
                o1[d].z = fmaf(p1, vv.z, o1[d].z); o1[d].w = fmaf(p1, vv.w, o1[d].w);
            }
        }
        float* ar0 = att + ((size_t)(b * TT + t0 + ta)) * VALUE_DIM + h * 128;
        float* ar1 = att + ((size_t)(b * TT + t0 + tb)) * VALUE_DIM + h * 128;
        #pragma unroll
        for (int d = 0; d < 4; d++) {
            *(float4*)(ar0 + dvg * 4 + 32 * d) = o0[d];
            *(float4*)(ar1 + dvg * 4 + 32 * d) = o1[d];
        }
    }

    {
        const int dkt = tid >> 4, dvt = tid & 15;
        float4 sacc[8][2];
        #pragma unroll
        for (int i = 0; i < 8; i++)
            #pragma unroll
            for (int dj = 0; dj < 2; dj++)
                sacc[i][dj] = make_float4(0.f, 0.f, 0.f, 0.f);
        const float cL = cs[63];
        for (int tau = 0; tau < LCH; tau++) {
            const float w = bs[tau] * exp2f(cL - cs[tau]);
            float kw[8];
            #pragma unroll
            for (int i = 0; i < 8; i++) kw[i] = ksT[(dkt + 16 * i) * 68 + tau] * w;
            float4 vv[2];
            #pragma unroll
            for (int dj = 0; dj < 2; dj++)
                vv[dj] = *(const float4*)&vs[tau * 132 + dvt * 4 + 64 * dj];
            #pragma unroll
            for (int i = 0; i < 8; i++)
                #pragma unroll
                for (int dj = 0; dj < 2; dj++) {
                    sacc[i][dj].x = fmaf(kw[i], vv[dj].x, sacc[i][dj].x);
                    sacc[i][dj].y = fmaf(kw[i], vv[dj].y, sacc[i][dj].y);
                    sacc[i][dj].z = fmaf(kw[i], vv[dj].z, sacc[i][dj].z);
                    sacc[i][dj].w = fmaf(kw[i], vv[dj].w, sacc[i][dj].w);
                }
        }
        float* sp = sinc + ((size_t)(bh * NCH + j)) * 16384;
        #pragma unroll
        for (int i = 0; i < 8; i++)
            #pragma unroll
            for (int dj = 0; dj < 2; dj++)
                *(float4*)&sp[(dkt + 16 * i) * 128 + dvt * 4 + 64 * dj] = sacc[i][dj];
    }
}

// ---------------- phase B: 8-way sliced scan (256 CTAs) ----------------------
__global__ void __launch_bounds__(256)
chunkB(const float* __restrict__ sinc, float* __restrict__ spre,
       const float* __restrict__ cbuf, const float* __restrict__ rstate,
       const int* __restrict__ input_pos)
{
    const int bh = blockIdx.y;
    const int off0 = blockIdx.x * 2048 + threadIdx.x;
    const float keep = (input_pos[0] == 0) ? 0.f : 1.f;

    float s[8];
    #pragma unroll
    for (int i = 0; i < 8; i++)
        s[i] = keep * rstate[(size_t)bh * 16384 + off0 + i * 256];

    for (int j = 0; j < NCH; j++) {
        const size_t base = ((size_t)(bh * NCH + j)) * 16384 + off0;
        #pragma unroll
        for (int i = 0; i < 8; i++)
            spre[base + i * 256] = s[i];
        const float dec = exp2f(cbuf[(size_t)bh * TT + j * LCH + 63]);
        #pragma unroll
        for (int i = 0; i < 8; i++)
            s[i] = fmaf(dec, s[i], sinc[base + i * 256]);
    }
}

// ---------------- phase C fused with gate ------------------------------------
#define SMC_BYTES (25536 * 4)
__global__ void __launch_bounds__(256)
chunkC(const float* __restrict__ y, const float* __restrict__ cbuf,
       const float* __restrict__ spre, const float* __restrict__ att,
       const float* __restrict__ qkvz, const float* __restrict__ norm_w,
       __half* __restrict__ goh)
{
    extern __shared__ float sm[];
    float* S   = sm;
    float* qs  = sm + 128 * 132;
    float* cs  = qs + 64 * 132;
    float* nws = cs + 64;

    const int bh = blockIdx.y, j = blockIdx.x;
    const int b = bh >> 4, h = bh & 15;
    const int t0 = j * LCH;
    const int tid = threadIdx.x;

    const float* sp = spre + ((size_t)(bh * NCH + j)) * 16384;
    for (int i = tid; i < 4096; i += 256) {
        const int dk = i >> 5, dv4 = (i & 31) * 4;
        *(float4*)&S[dk * 132 + dv4] = *(const float4*)&sp[dk * 128 + dv4];
    }
    for (int i = tid; i < 2048; i += 256) {
        const int row = i >> 5, c4 = (i & 31) * 4;
        const float* yr = y + ((size_t)(b * TT + t0 + row)) * CONV_DIM + h * 128;
        *(float4*)&qs[row * 132 + c4] = *(const float4*)(yr + c4);
    }
    if (tid < 64) cs[tid] = cbuf[(size_t)bh * TT + t0 + tid];
    if (tid < 128) nws[tid] = norm_w[tid];
    __syncthreads();

    const int tg = tid >> 3, dvg = tid & 7;
    const int ta = tg * 2, tb = ta + 1;
    float4 o0[4], o1[4];
    #pragma unroll
    for (int d = 0; d < 4; d++) {
        o0[d] = make_float4(0.f, 0.f, 0.f, 0.f);
        o1[d] = make_float4(0.f, 0.f, 0.f, 0.f);
    }
    for (int dk = 0; dk < 128; dk++) {
        const float q0 = qs[ta * 132 + dk];
        const float q1 = qs[tb * 132 + dk];
        const float* srow = S + dk * 132;
        #pragma unroll
        for (int d = 0; d < 4; d++) {
            const float4 sv = *(const float4*)(srow + dvg * 4 + 32 * d);
            o0[d].x = fmaf(q0, sv.x, o0[d].x); o0[d].y = fmaf(q0, sv.y, o0[d].y);
            o0[d].z = fmaf(q0, sv.z, o0[d].z); o0[d].w = fmaf(q0, sv.w, o0[d].w);
            o1[d].x = fmaf(q1, sv.x, o1[d].x); o1[d].y = fmaf(q1, sv.y, o1[d].y);
            o1[d].z = fmaf(q1, sv.z, o1[d].z); o1[d].w = fmaf(q1, sv.w, o1[d].w);
        }
    }
    const float e0 = exp2f(cs[ta]);
    const float e1 = exp2f(cs[tb]);

    const float* ar0 = att + ((size_t)(b * TT + t0 + ta)) * VALUE_DIM + h * 128;
    const float* ar1 = att + ((size_t)(b * TT + t0 + tb)) * VALUE_DIM + h * 128;
    float ss0 = 0.f, ss1 = 0.f;
    #pragma unroll
    for (int d = 0; d < 4; d++) {
        const float4 a0 = *(const float4*)(ar0 + dvg * 4 + 32 * d);
        const float4 a1 = *(const float4*)(ar1 + dvg * 4 + 32 * d);
        o0[d].x = a0.x + e0 * o0[d].x;  o0[d].y = a0.y + e0 * o0[d].y;
        o0[d].z = a0.z + e0 * o0[d].z;  o0[d].w = a0.w + e0 * o0[d].w;
        o1[d].x = a1.x + e1 * o1[d].x;  o1[d].y = a1.y + e1 * o1[d].y;
        o1[d].z = a1.z + e1 * o1[d].z;  o1[d].w = a1.w + e1 * o1[d].w;
        ss0 = fmaf(o0[d].x, o0[d].x, ss0); ss0 = fmaf(o0[d].y, o0[d].y, ss0);
        ss0 = fmaf(o0[d].z, o0[d].z, ss0); ss0 = fmaf(o0[d].w, o0[d].w, ss0);
        ss1 = fmaf(o1[d].x, o1[d].x, ss1); ss1 = fmaf(o1[d].y, o1[d].y, ss1);
        ss1 = fmaf(o1[d].z, o1[d].z, ss1); ss1 = fmaf(o1[d].w, o1[d].w, ss1);
    }
    #pragma unroll
    for (int off = 1; off < 8; off <<= 1) {
        ss0 += __shfl_xor_sync(0xffffffffu, ss0, off);
        ss1 += __shfl_xor_sync(0xffffffffu, ss1, off);
    }
    const float sc0 = rsqrtf(ss0 * (1.f / 128.f) + 1e-6f);
    const float sc1 = rsqrtf(ss1 * (1.f / 128.f) + 1e-6f);

    const float* zr0 = qkvz + ((size_t)(b * TT + t0 + ta)) * QKVZ_N + CONV_DIM + h * 128;
    const float* zr1 = qkvz + ((size_t)(b * TT + t0 + tb)) * QKVZ_N + CONV_DIM + h * 128;
    __half* gr0 = goh + ((size_t)(b * TT + t0 + ta)) * VALUE_DIM + h * 128;
    __half* gr1 = goh + ((size_t)(b * TT + t0 + tb)) * VALUE_DIM + h * 128;
    #pragma unroll
    for (int d = 0; d < 4; d++) {
        const int dvi = dvg * 4 + 32 * d;
        const float4 z0 = *(const float4*)(zr0 + dvi);
        const float4 z1 = *(const float4*)(zr1 + dvi);
        const float4 nw = *(const float4*)(nws + dvi);
        __half2 h0a = __floats2half2_rn(
            o0[d].x * sc0 * nw.x * (1.f / (1.f + expf(-z0.x))),
            o0[d].y * sc0 * nw.y * (1.f / (1.f + expf(-z0.y))));
        __half2 h0b = __floats2half2_rn(
            o0[d].z * sc0 * nw.z * (1.f / (1.f + expf(-z0.z))),
            o0[d].w * sc0 * nw.w * (1.f / (1.f + expf(-z0.w))));
        __half2 h1a = __floats2half2_rn(
            o1[d].x * sc1 * nw.x * (1.f / (1.f + expf(-z1.x))),
            o1[d].y * sc1 * nw.y * (1.f / (1.f + expf(-z1.y))));
        __half2 h1b = __floats2half2_rn(
            o1[d].z * sc1 * nw.z * (1.f / (1.f + expf(-z1.z))),
            o1[d].w * sc1 * nw.w * (1.f / (1.f + expf(-z1.w))));
        *(__half2*)(gr0 + dvi)     = h0a;
        *(__half2*)(gr0 + dvi + 2) = h0b;
        *(__half2*)(gr1 + dvi)     = h1a;
        *(__half2*)(gr1 + dvi + 2) = h1b;
    }
}

// ---------------- launch -----------------------------------------------------
extern "C" void kernel_launch(void* const* d_in, const int* in_sizes, int n_in,
                              void* d_out, int out_size)
{
    const float* x          = (const float*)d_in[0];
    const int*   input_pos  = (const int*)  d_in[1];
    const float* W_qkvz     = (const float*)d_in[2];
    const float* W_b        = (const float*)d_in[3];
    const float* W_a        = (const float*)d_in[4];
    const float* conv_w     = (const float*)d_in[5];
    const float* norm_w     = (const float*)d_in[6];
    const float* W_out      = (const float*)d_in[7];
    const float* conv_state = (const float*)d_in[8];
    const float* rec_state  = (const float*)d_in[9];
    float* out = (float*)d_out;

    float *qkvz, *y, *beta, *alpha, *attb, *sinc, *spre, *cbuf;
    __half *xh, *wqt, *wot, *goh;
    cudaGetSymbolAddress((void**)&qkvz, g_qkvz);
    cudaGetSymbolAddress((void**)&y,    g_y);
    cudaGetSymbolAddress((void**)&beta, g_beta);
    cudaGetSymbolAddress((void**)&alpha,g_alpha);
    cudaGetSymbolAddress((void**)&attb, g_att);
    cudaGetSymbolAddress((void**)&sinc, g_sinc);
    cudaGetSymbolAddress((void**)&spre, g_spre);
    cudaGetSymbolAddress((void**)&cbuf, g_cc);
    cudaGetSymbolAddress((void**)&xh,  g_xh);
    cudaGetSymbolAddress((void**)&wqt, g_wqt);
    cudaGetSymbolAddress((void**)&wot, g_wot);
    cudaGetSymbolAddress((void**)&goh, g_goh);

    cudaFuncSetAttribute(h16gemm, cudaFuncAttributeMaxDynamicSharedMemorySize,
                         GEMM_SMEM);
    cudaFuncSetAttribute(chunkA, cudaFuncAttributeMaxDynamicSharedMemorySize,
                         SMA_BYTES);
    cudaFuncSetAttribute(chunkC, cudaFuncAttributeMaxDynamicSharedMemorySize,
                         SMC_BYTES);
    cudaFuncSetAttribute(ba2_kernel, cudaFuncAttributeMaxDynamicSharedMemorySize,
                         BA_SMEM);
    cudaFuncSetAttribute(conv2_kernel, cudaFuncAttributeMaxDynamicSharedMemorySize,
                         CONV_SMEM);

    // 0) operand prep
    to_half<<<(BT * CC / 8 + 255) / 256, 256>>>(x, xh, BT * CC / 8);
    transpose_half<<<dim3(QKVZ_N / 32, CC / 32), 256>>>(W_qkvz, wqt, CC, QKVZ_N);
    transpose_half<<<dim3(CC / 32, CC / 32), 256>>>(W_out, wot, CC, CC);

    // 1) qkvz = x @ W_qkvz  (fp16, 2 CTAs/SM)
    h16gemm<<<dim3(QKVZ_N / 128, BT / 128), 256, GEMM_SMEM>>>(
        xh, wqt, qkvz, BT, QKVZ_N, CC);
    // 2) beta/alpha
    ba2_kernel<<<BT / 64, 256, BA_SMEM>>>(x, W_b, W_a, beta, alpha);
    // 3) conv + silu + l2norm
    conv2_kernel<<<dim3(8, BT / 8), 256, CONV_SMEM>>>(
        qkvz, conv_w, conv_state, input_pos, y);
    // 4) chunked recurrence
    chunkA<<<dim3(NCH, BH), 256, SMA_BYTES>>>(y, beta, alpha, attb, sinc, cbuf);
    chunkB<<<dim3(8, BH), 256>>>(sinc, spre, cbuf, rec_state, input_pos);
    chunkC<<<dim3(NCH, BH), 256, SMC_BYTES>>>(y, cbuf, spre, attb, qkvz,
                                              norm_w, goh);
    // 5) out = gated @ W_out
    h16gemm<<<dim3(CC / 128, BT / 128), 256, GEMM_SMEM>>>(
        goh, wot, out, BT, CC, CC);
}

// round 14
// speedup vs baseline: 1.7626x; 1.0817x over previous
#include <cuda_runtime.h>
#include <cuda_fp16.h>
#include <math.h>
#include <stdint.h>

// Problem constants
#define BB 2
#define TT 2048
#define CC 2048
#define HH 16
#define KEY_DIM 2048
#define VALUE_DIM 2048
#define CONV_DIM 6144
#define QKVZ_N 8192
#define BT 4096   // B*T
#define LCH 64
#define NCH (TT / LCH)   // 32 chunks
#define BH 32            // B*H

// ---------------- scratch (static device globals; no allocation) -------------
__device__ float g_qkvz[(size_t)BT * QKVZ_N];
__device__ float g_y[(size_t)BT * CONV_DIM];
__device__ float g_beta[(size_t)BT * HH];
__device__ float g_alpha[(size_t)BT * HH];
__device__ float g_att[(size_t)BT * VALUE_DIM];
__device__ __half g_xh[(size_t)BT * CC];
__device__ __half g_wqt[(size_t)QKVZ_N * CC];
__device__ __half g_wot[(size_t)CC * CC];
__device__ __half g_goh[(size_t)BT * CC];
__device__ float g_sinc[(size_t)BH * NCH * 16384];
__device__ float g_spre[(size_t)BH * NCH * 16384];
__device__ float g_cc[(size_t)BH * TT];

// ---------------- PTX helpers ------------------------------------------------
__device__ __forceinline__ uint32_t s2u(const void* p) {
    uint32_t a;
    asm("{ .reg .u64 t; cvta.to.shared.u64 t, %1; cvt.u32.u64 %0, t; }"
        : "=r"(a) : "l"(p));
    return a;
}
__device__ __forceinline__ void ldsm4(uint32_t* r, uint32_t addr) {
    asm volatile("ldmatrix.sync.aligned.m8n8.x4.shared.b16 {%0,%1,%2,%3}, [%4];"
                 : "=r"(r[0]), "=r"(r[1]), "=r"(r[2]), "=r"(r[3]) : "r"(addr));
}
__device__ __forceinline__ void mma168f16(float* d, const uint32_t* a,
                                          const uint32_t* b) {
    asm volatile(
        "mma.sync.aligned.m16n8k16.row.col.f32.f16.f16.f32 "
        "{%0,%1,%2,%3}, {%4,%5,%6,%7}, {%8,%9}, {%0,%1,%2,%3};\n"
        : "+f"(d[0]), "+f"(d[1]), "+f"(d[2]), "+f"(d[3])
        : "r"(a[0]), "r"(a[1]), "r"(a[2]), "r"(a[3]),
          "r"(b[0]), "r"(b[1]));
}

// ---------------- fp16 tensor-core GEMM: 4 warps, 64x64 warp tile ------------
// C[M,N] = A[M,K] * B^T. CTA tile 128x128, BK=32, 128 threads (2x2 warps),
// warp tile 64x64 (128 B frag traffic per MMA), 2 CTAs/SM.
// Stage = 256 rows x 80B = 20480B, double-buffered 40KB.
#define STAGE_B 20480
#define GEMM_SMEM (2 * STAGE_B)

__global__ void __launch_bounds__(128, 2)
h16gemm(const __half* __restrict__ A, const __half* __restrict__ Bt,
        float* __restrict__ Cm, int M, int N, int Kd)
{
    extern __shared__ char smem[];
    const uint32_t sb = s2u(smem);
    const int tid  = threadIdx.x;
    const int bm   = blockIdx.y * 128;
    const int bn   = blockIdx.x * 128;
    const int lane = tid & 31;
    const int warp = tid >> 5;
    const int wm   = (warp >> 1) * 64;   // 0 / 64
    const int wn   = (warp & 1) * 64;    // 0 / 64
    const int gid  = lane >> 2;
    const int tig  = lane & 3;

    const int lr = tid >> 2;             // 0..31 (rows lr, +32, +64, +96)
    const int lc = tid & 3;              // k-chunk (8 halves)

    const __half* Ap = A  + (size_t)(bm + lr) * Kd + lc * 8;
    const __half* Bp = Bt + (size_t)(bn + lr) * Kd + lc * 8;
    const size_t r32 = (size_t)32 * Kd;

    float acc[4][8][4];
    #pragma unroll
    for (int i = 0; i < 4; i++)
        #pragma unroll
        for (int j = 0; j < 8; j++)
            #pragma unroll
            for (int r = 0; r < 4; r++) acc[i][j][r] = 0.f;

    {
        uint4 ra[4], rb[4];
        #pragma unroll
        for (int i = 0; i < 4; i++) {
            ra[i] = *(const uint4*)(Ap + i * r32);
            rb[i] = *(const uint4*)(Bp + i * r32);
        }
        char* s0 = smem;
        char* s0b = smem + 10240;
        #pragma unroll
        for (int i = 0; i < 4; i++) {
            *(uint4*)(s0  + (lr + 32 * i) * 80 + lc * 16) = ra[i];
            *(uint4*)(s0b + (lr + 32 * i) * 80 + lc * 16) = rb[i];
        }
    }
    __syncthreads();

    const int at = lane >> 3;
    const int arow = wm + (at & 1) * 8 + (lane & 7);
    const int akoff = (lane >> 4) * 16;
    const int brow = wn + (lane >> 4) * 8 + (lane & 7);
    const int bkoff = ((lane >> 3) & 1) * 16;

    const int nst = Kd / 32;
    for (int s = 0; s < nst; s++) {
        const bool more = (s + 1) < nst;
        uint4 ra[4], rb[4];
        if (more) {
            Ap += 32; Bp += 32;
            #pragma unroll
            for (int i = 0; i < 4; i++) {
                ra[i] = *(const uint4*)(Ap + i * r32);
                rb[i] = *(const uint4*)(Bp + i * r32);
            }
        }

        const uint32_t base = sb + (uint32_t)(s & 1) * STAGE_B;
        #pragma unroll
        for (int ks = 0; ks < 2; ks++) {
            uint32_t aF[4][4], bF[4][4];
            const uint32_t ak = base + (uint32_t)(ks * 32 + akoff);
            #pragma unroll
            for (int mt = 0; mt < 4; mt++)
                ldsm4(aF[mt], ak + (uint32_t)(arow + mt * 16) * 80);
            const uint32_t bk = base + 10240u + (uint32_t)(ks * 32 + bkoff);
            #pragma unroll
            for (int np = 0; np < 4; np++)
                ldsm4(bF[np], bk + (uint32_t)(brow + np * 16) * 80);
            #pragma unroll
            for (int mt = 0; mt < 4; mt++)
                #pragma unroll
                for (int nt = 0; nt < 8; nt++)
                    mma168f16(acc[mt][nt], aF[mt], &bF[nt >> 1][(nt & 1) * 2]);
        }

        if (more) {
            char* sn  = smem + ((s + 1) & 1) * STAGE_B;
            char* snb = sn + 10240;
            #pragma unroll
            for (int i = 0; i < 4; i++) {
                *(uint4*)(sn  + (lr + 32 * i) * 80 + lc * 16) = ra[i];
                *(uint4*)(snb + (lr + 32 * i) * 80 + lc * 16) = rb[i];
            }
        }
        __syncthreads();
    }

    #pragma unroll
    for (int mt = 0; mt < 4; mt++) {
        const int row = bm + wm + mt * 16 + gid;
        #pragma unroll
        for (int nt = 0; nt < 8; nt++) {
            const int col = bn + wn + nt * 8 + 2 * tig;
            *(float2*)&Cm[(size_t)row * N + col]       = make_float2(acc[mt][nt][0], acc[mt][nt][1]);
            *(float2*)&Cm[(size_t)(row + 8) * N + col] = make_float2(acc[mt][nt][2], acc[mt][nt][3]);
        }
    }
}

// ---------------- f32 -> f16 convert -----------------------------------------
__global__ void __launch_bounds__(256)
to_half(const float* __restrict__ X, __half* __restrict__ Y, int n8)
{
    int i = blockIdx.x * 256 + threadIdx.x;
    if (i >= n8) return;
    float4 v0 = ((const float4*)X)[i * 2];
    float4 v1 = ((const float4*)X)[i * 2 + 1];
    __half2* H = (__half2*)Y;
    H[i * 4 + 0] = __floats2half2_rn(v0.x, v0.y);
    H[i * 4 + 1] = __floats2half2_rn(v0.z, v0.w);
    H[i * 4 + 2] = __floats2half2_rn(v1.x, v1.y);
    H[i * 4 + 3] = __floats2half2_rn(v1.z, v1.w);
}

// ---------------- transpose: W[K][N] f32 -> Wt[N][K] f16 ---------------------
__global__ void __launch_bounds__(256)
transpose_half(const float* __restrict__ W, __half* __restrict__ Th, int K, int N)
{
    __shared__ float tile[32][33];
    const int k0 = blockIdx.y * 32, n0 = blockIdx.x * 32;
    const int tx = threadIdx.x & 31, ty = threadIdx.x >> 5;
    #pragma unroll
    for (int r = 0; r < 32; r += 8)
        tile[ty + r][tx] = W[(size_t)(k0 + ty + r) * N + n0 + tx];
    __syncthreads();
    #pragma unroll
    for (int r = 0; r < 32; r += 8)
        Th[(size_t)(n0 + ty + r) * K + k0 + tx] = __float2half(tile[tx][ty + r]);
}

// ---------------- beta/alpha: tiled fp32 GEMM --------------------------------
#define BA_SMEM (64 * 132 * 4 + 128 * 32 * 4)
__global__ void __launch_bounds__(256)
ba2_kernel(const float* __restrict__ x, const float* __restrict__ Wb,
           const float* __restrict__ Wa, float* __restrict__ beta,
           float* __restrict__ alpha)
{
    extern __shared__ float sm[];
    float* xs = sm;
    float* ws = sm + 64 * 132;

    const int tid = threadIdx.x;
    const int r0 = blockIdx.x * 64;
    const int tr = tid >> 4;
    const int tc = tid & 15;

    float acc[4][2];
    #pragma unroll
    for (int i = 0; i < 4; i++) { acc[i][0] = 0.f; acc[i][1] = 0.f; }

    for (int k0 = 0; k0 < CC; k0 += 128) {
        #pragma unroll
        for (int i = 0; i < 8; i++) {
            const int idx = tid + i * 256;
            const int row = idx >> 5, c4 = (idx & 31) * 4;
            *(float4*)&xs[row * 132 + c4] =
                *(const float4*)&x[(size_t)(r0 + row) * CC + k0 + c4];
        }
        #pragma unroll
        for (int i = 0; i < 2; i++) {
            const int idx = tid + i * 256;
            const int kk = idx >> 2, q = (idx & 3) * 4;
            *(float4*)&ws[kk * 32 + q]      = *(const float4*)&Wb[(size_t)(k0 + kk) * HH + q];
            *(float4*)&ws[kk * 32 + 16 + q] = *(const float4*)&Wa[(size_t)(k0 + kk) * HH + q];
        }
        __syncthreads();

        for (int kk = 0; kk < 128; kk++) {
            const float2 wv = *(const float2*)&ws[kk * 32 + tc * 2];
            #pragma unroll
            for (int i = 0; i < 4; i++) {
                const float xv = xs[(tr * 4 + i) * 132 + kk];
                acc[i][0] = fmaf(xv, wv.x, acc[i][0]);
                acc[i][1] = fmaf(xv, wv.y, acc[i][1]);
            }
        }
        __syncthreads();
    }

    #pragma unroll
    for (int i = 0; i < 4; i++) {
        const int row = r0 + tr * 4 + i;
        #pragma unroll
        for (int j = 0; j < 2; j++) {
            const int c = tc * 2 + j;
            const float v = 1.f / (1.f + expf(-acc[i][j]));
            if (c < 16) beta[(size_t)row * HH + c] = v;
            else        alpha[(size_t)row * HH + (c - 16)] = v;
        }
    }
}

// ---------------- conv: time-tiled -------------------------------------------
#define CONV_SMEM ((11 * 768 + 8 * 768 + 48) * 4)
__global__ void __launch_bounds__(256)
conv2_kernel(const float* __restrict__ qkvz, const float* __restrict__ conv_w,
             const float* __restrict__ conv_state, const int* __restrict__ input_pos,
             float* __restrict__ y_out)
{
    extern __shared__ float sm[];
    float* in  = sm;
    float* yb  = sm + 11 * 768;
    float* nrm = sm + 19 * 768;

    const int cg = blockIdx.x;
    const int c0 = cg * 768;
    const int tgl = blockIdx.y;
    const int b = tgl >> 8;
    const int t0 = (tgl & 255) * 8;
    const int tid = threadIdx.x;
    const float keep = (input_pos[0] == 0) ? 0.f : 1.f;

    for (int idx = tid; idx < 11 * 192; idx += 256) {
        const int r = idx / 192, c4 = (idx % 192) * 4;
        const int tau = t0 - 3 + r;
        float4 v;
        if (tau >= 0) {
            v = *(const float4*)&qkvz[((size_t)(b * TT + tau)) * QKVZ_N + c0 + c4];
        } else {
            const int slot = tau + 4;
            v.x = keep * conv_state[((size_t)b * CONV_DIM + c0 + c4 + 0) * 4 + slot];
            v.y = keep * conv_state[((size_t)b * CONV_DIM + c0 + c4 + 1) * 4 + slot];
            v.z = keep * conv_state[((size_t)b * CONV_DIM + c0 + c4 + 2) * 4 + slot];
            v.w = keep * conv_state[((size_t)b * CONV_DIM + c0 + c4 + 3) * 4 + slot];
        }
        *(float4*)&in[r * 768 + c4] = v;
    }
    __syncthreads();

    for (int idx = tid; idx < 1536; idx += 256) {
        const int t = idx / 192, c4 = (idx % 192) * 4;
        float4 o;
        float* op = (float*)&o;
        #pragma unroll
        for (int e = 0; e < 4; e++) {
            const int c = c4 + e;
            const float4 w = *(const float4*)&conv_w[(size_t)(c0 + c) * 4];
            float acc = in[(t + 0) * 768 + c] * w.x + in[(t + 1) * 768 + c] * w.y
                      + in[(t + 2) * 768 + c] * w.z + in[(t + 3) * 768 + c] * w.w;
            op[e] = acc / (1.f + expf(-acc));
        }
        *(float4*)&yb[t * 768 + c4] = o;
    }
    __syncthreads();

    {
        const int w = tid >> 5, lane = tid & 31;
        for (int p = w; p < 48; p += 8) {
            const int t = p / 6, hl = p % 6;
            const int hg = (c0 >> 7) + hl;
            float ss = 0.f;
            #pragma unroll
            for (int i = 0; i < 4; i++) {
                const float v = yb[t * 768 + hl * 128 + lane + i * 32];
                ss = fmaf(v, v, ss);
            }
            #pragma unroll
            for (int off = 16; off > 0; off >>= 1)
                ss += __shfl_xor_sync(0xffffffffu, ss, off);
            if (lane == 0)
                nrm[t * 6 + hl] = (hg < 32) ? (1.f / fmaxf(sqrtf(ss), 1e-12f)) : 1.f;
        }
    }
    __syncthreads();

    for (int idx = tid; idx < 1536; idx += 256) {
        const int t = idx / 192, c4 = (idx % 192) * 4;
        const float inv = nrm[t * 6 + (c4 >> 7)];
        float4 v = *(const float4*)&yb[t * 768 + c4];
        v.x *= inv; v.y *= inv; v.z *= inv; v.w *= inv;
        *(float4*)&y_out[((size_t)(b * TT + t0 + t)) * CONV_DIM + c0 + c4] = v;
    }
}

// ---------------- chunked recurrence: phase A --------------------------------
#define SA_QS 0
#define SA_KT (64 * 132)
#define SA_VS (SA_KT + 128 * 68)
#define SA_P  (SA_VS + 64 * 132)
#define SA_CS (SA_P + 64 * 68)
#define SA_BS (SA_CS + 64)
#define SMA_BYTES ((SA_BS + 64) * 4)

__global__ void __launch_bounds__(256)
chunkA(const float* __restrict__ y, const float* __restrict__ beta,
       const float* __restrict__ alpha, float* __restrict__ att,
       float* __restrict__ sinc, float* __restrict__ cbuf)
{
    extern __shared__ float sm[];
    float* qs  = sm + SA_QS;
    float* ksT = sm + SA_KT;
    float* vs  = sm + SA_VS;
    float* P   = sm + SA_P;
    float* cs  = sm + SA_CS;
    float* bs  = sm + SA_BS;

    const int bh = blockIdx.y, j = blockIdx.x;
    const int b = bh >> 4, h = bh & 15;
    const int t0 = j * LCH;
    const int tid = threadIdx.x;

    for (int i = tid; i < 2048; i += 256) {
        const int row = i >> 5, c4 = (i & 31) * 4;
        const float* yr = y + ((size_t)(b * TT + t0 + row)) * CONV_DIM + h * 128;
        float4 q4 = *(const float4*)(yr + c4);
        float4 k4 = *(const float4*)(yr + KEY_DIM + c4);
        float4 v4 = *(const float4*)(yr + 2 * KEY_DIM + c4);
        *(float4*)&qs[row * 132 + c4] = q4;
        ksT[(c4 + 0) * 68 + row] = k4.x;
        ksT[(c4 + 1) * 68 + row] = k4.y;
        ksT[(c4 + 2) * 68 + row] = k4.z;
        ksT[(c4 + 3) * 68 + row] = k4.w;
        *(float4*)&vs[row * 132 + c4] = v4;
    }
    if (tid < 64) {
        cs[tid] = log2f(alpha[((size_t)(b * TT + t0 + tid)) * HH + h]);
        bs[tid] = beta[((size_t)(b * TT + t0 + tid)) * HH + h];
    }
    __syncthreads();
    if (tid == 0) {
        float run = 0.f;
        for (int t = 0; t < LCH; t++) { run += cs[t]; cs[t] = run; }
    }
    __syncthreads();
    if (tid < 64) cbuf[(size_t)bh * TT + t0 + tid] = cs[tid];

    {
        const int rt = tid >> 4, ct = tid & 15;
        float acc[4][4];
        #pragma unroll
        for (int i = 0; i < 4; i++)
            #pragma unroll
            for (int j2 = 0; j2 < 4; j2++) acc[i][j2] = 0.f;
        if (ct <= rt) {
            for (int kk0 = 0; kk0 < 128; kk0 += 4) {
                float4 qv[4], kv[4];
                #pragma unroll
                for (int i = 0; i < 4; i++)
                    qv[i] = *(const float4*)&qs[(rt * 4 + i) * 132 + kk0];
                #pragma unroll
                for (int q = 0; q < 4; q++)
                    kv[q] = *(const float4*)&ksT[(kk0 + q) * 68 + ct * 4];
                #pragma unroll
                for (int q = 0; q < 4; q++) {
                    const float* kq = (const float*)&kv[q];
                    #pragma unroll
                    for (int i = 0; i < 4; i++) {
                        const float qq = ((const float*)&qv[i])[q];
                        #pragma unroll
                        for (int j2 = 0; j2 < 4; j2++)
                            acc[i][j2] = fmaf(qq, kq[j2], acc[i][j2]);
                    }
                }
            }
        }
        #pragma unroll
        for (int i = 0; i < 4; i++)
            #pragma unroll
            for (int j2 = 0; j2 < 4; j2++) {
                const int t = rt * 4 + i, tau = ct * 4 + j2;
                float val = 0.f;
                if (tau <= t)
                    val = acc[i][j2] * bs[tau] * exp2f(cs[t] - cs[tau]);
                P[t * 68 + tau] = val;
            }
    }
    __syncthreads();

    {
        const int tg = tid >> 3, dvg = tid & 7;
        const int ta = tg * 2, tb = ta + 1;
        float4 o0[4], o1[4];
        #pragma unroll
        for (int d = 0; d < 4; d++) {
            o0[d] = make_float4(0.f, 0.f, 0.f, 0.f);
            o1[d] = make_float4(0.f, 0.f, 0.f, 0.f);
        }
        for (int tau = 0; tau < LCH; tau++) {
            const float p0 = P[ta * 68 + tau];
            const float p1 = P[tb * 68 + tau];
            const float* vr = vs + tau * 132;
            #pragma unroll
            for (int d = 0; d < 4; d++) {
                const float4 vv = *(const float4*)(vr + dvg * 4 + 32 * d);
                o0[d].x = fmaf(p0, vv.x, o0[d].x); o0[d].y = fmaf(p0, vv.y, o0[d].y);
                o0[d].z = fmaf(p0, vv.z, o0[d].z); o0[d].w = fmaf(p0, vv.w, o0[d].w);
                o1[d].x = fmaf(p1, vv.x, o1[d].x); o1[d].y = fmaf(p1, vv.y, o1[d].y);
                o1[d].z = fmaf(p1, vv.z, o1[d].z); o1[d].w = fmaf(p1, vv.w, o1[d].w);
            }
        }
        float* ar0 = att + ((size_t)(b * TT + t0 + ta)) * VALUE_DIM + h * 128;
        float* ar1 = att + ((size_t)(b * TT + t0 + tb)) * VALUE_DIM + h * 128;
        #pragma unroll
        for (int d = 0; d < 4; d++) {
            *(float4*)(ar0 + dvg * 4 + 32 * d) = o0[d];
            *(float4*)(ar1 + dvg * 4 + 32 * d) = o1[d];
        }
    }

    {
        const int dkt = tid >> 4, dvt = tid & 15;
        float4 sacc[8][2];
        #pragma unroll
        for (int i = 0; i < 8; i++)
            #pragma unroll
            for (int dj = 0; dj < 2; dj++)
                sacc[i][dj] = make_float4(0.f, 0.f, 0.f, 0.f);
        const float cL = cs[63];
        for (int tau = 0; tau < LCH; tau++) {
            const float w = bs[tau] * exp2f(cL - cs[tau]);
            float kw[8];
            #pragma unroll
            for (int i = 0; i < 8; i++) kw[i] = ksT[(dkt + 16 * i) * 68 + tau] * w;
            float4 vv[2];
            #pragma unroll
            for (int dj = 0; dj < 2; dj++)
                vv[dj] = *(const float4*)&vs[tau * 132 + dvt * 4 + 64 * dj];
            #pragma unroll
            for (int i = 0; i < 8; i++)
                #pragma unroll
                for (int dj = 0; dj < 2; dj++) {
                    sacc[i][dj].x = fmaf(kw[i], vv[dj].x, sacc[i][dj].x);
                    sacc[i][dj].y = fmaf(kw[i], vv[dj].y, sacc[i][dj].y);
                    sacc[i][dj].z = fmaf(kw[i], vv[dj].z, sacc[i][dj].z);
                    sacc[i][dj].w = fmaf(kw[i], vv[dj].w, sacc[i][dj].w);
                }
        }
        float* sp = sinc + ((size_t)(bh * NCH + j)) * 16384;
        #pragma unroll
        for (int i = 0; i < 8; i++)
            #pragma unroll
            for (int dj = 0; dj < 2; dj++)
                *(float4*)&sp[(dkt + 16 * i) * 128 + dvt * 4 + 64 * dj] = sacc[i][dj];
    }
}

// ---------------- phase B: 8-way sliced scan ---------------------------------
__global__ void __launch_bounds__(256)
chunkB(const float* __restrict__ sinc, float* __restrict__ spre,
       const float* __restrict__ cbuf, const float* __restrict__ rstate,
       const int* __restrict__ input_pos)
{
    const int bh = blockIdx.y;
    const int off0 = blockIdx.x * 2048 + threadIdx.x;
    const float keep = (input_pos[0] == 0) ? 0.f : 1.f;

    float s[8];
    #pragma unroll
    for (int i = 0; i < 8; i++)
        s[i] = keep * rstate[(size_t)bh * 16384 + off0 + i * 256];

    for (int j = 0; j < NCH; j++) {
        const size_t base = ((size_t)(bh * NCH + j)) * 16384 + off0;
        #pragma unroll
        for (int i = 0; i < 8; i++)
            spre[base + i * 256] = s[i];
        const float dec = exp2f(cbuf[(size_t)bh * TT + j * LCH + 63]);
        #pragma unroll
        for (int i = 0; i < 8; i++)
            s[i] = fmaf(dec, s[i], sinc[base + i * 256]);
    }
}

// ---------------- phase C fused with gate ------------------------------------
#define SMC_BYTES (25536 * 4)
__global__ void __launch_bounds__(256)
chunkC(const float* __restrict__ y, const float* __restrict__ cbuf,
       const float* __restrict__ spre, const float* __restrict__ att,
       const float* __restrict__ qkvz, const float* __restrict__ norm_w,
       __half* __restrict__ goh)
{
    extern __shared__ float sm[];
    float* S   = sm;
    float* qs  = sm + 128 * 132;
    float* cs  = qs + 64 * 132;
    float* nws = cs + 64;

    const int bh = blockIdx.y, j = blockIdx.x;
    const int b = bh >> 4, h = bh & 15;
    const int t0 = j * LCH;
    const int tid = threadIdx.x;

    const float* sp = spre + ((size_t)(bh * NCH + j)) * 16384;
    for (int i = tid; i < 4096; i += 256) {
        const int dk = i >> 5, dv4 = (i & 31) * 4;
        *(float4*)&S[dk * 132 + dv4] = *(const float4*)&sp[dk * 128 + dv4];
    }
    for (int i = tid; i < 2048; i += 256) {
        const int row = i >> 5, c4 = (i & 31) * 4;
        const float* yr = y + ((size_t)(b * TT + t0 + row)) * CONV_DIM + h * 128;
        *(float4*)&qs[row * 132 + c4] = *(const float4*)(yr + c4);
    }
    if (tid < 64) cs[tid] = cbuf[(size_t)bh * TT + t0 + tid];
    if (tid < 128) nws[tid] = norm_w[tid];
    __syncthreads();

    const int tg = tid >> 3, dvg = tid & 7;
    const int ta = tg * 2, tb = ta + 1;
    float4 o0[4], o1[4];
    #pragma unroll
    for (int d = 0; d < 4; d++) {
        o0[d] = make_float4(0.f, 0.f, 0.f, 0.f);
        o1[d] = make_float4(0.f, 0.f, 0.f, 0.f);
    }
    for (int dk = 0; dk < 128; dk++) {
        const float q0 = qs[ta * 132 + dk];
        const float q1 = qs[tb * 132 + dk];
        const float* srow = S + dk * 132;
        #pragma unroll
        for (int d = 0; d < 4; d++) {
            const float4 sv = *(const float4*)(srow + dvg * 4 + 32 * d);
            o0[d].x = fmaf(q0, sv.x, o0[d].x); o0[d].y = fmaf(q0, sv.y, o0[d].y);
            o0[d].z = fmaf(q0, sv.z, o0[d].z); o0[d].w = fmaf(q0, sv.w, o0[d].w);
            o1[d].x = fmaf(q1, sv.x, o1[d].x); o1[d].y = fmaf(q1, sv.y, o1[d].y);
            o1[d].z = fmaf(q1, sv.z, o1[d].z); o1[d].w = fmaf(q1, sv.w, o1[d].w);
        }
    }
    const float e0 = exp2f(cs[ta]);
    const float e1 = exp2f(cs[tb]);

    const float* ar0 = att + ((size_t)(b * TT + t0 + ta)) * VALUE_DIM + h * 128;
    const float* ar1 = att + ((size_t)(b * TT + t0 + tb)) * VALUE_DIM + h * 128;
    float ss0 = 0.f, ss1 = 0.f;
    #pragma unroll
    for (int d = 0; d < 4; d++) {
        const float4 a0 = *(const float4*)(ar0 + dvg * 4 + 32 * d);
        const float4 a1 = *(const float4*)(ar1 + dvg * 4 + 32 * d);
        o0[d].x = a0.x + e0 * o0[d].x;  o0[d].y = a0.y + e0 * o0[d].y;
        o0[d].z = a0.z + e0 * o0[d].z;  o0[d].w = a0.w + e0 * o0[d].w;
        o1[d].x = a1.x + e1 * o1[d].x;  o1[d].y = a1.y + e1 * o1[d].y;
        o1[d].z = a1.z + e1 * o1[d].z;  o1[d].w = a1.w + e1 * o1[d].w;
        ss0 = fmaf(o0[d].x, o0[d].x, ss0); ss0 = fmaf(o0[d].y, o0[d].y, ss0);
        ss0 = fmaf(o0[d].z, o0[d].z, ss0); ss0 = fmaf(o0[d].w, o0[d].w, ss0);
        ss1 = fmaf(o1[d].x, o1[d].x, ss1); ss1 = fmaf(o1[d].y, o1[d].y, ss1);
        ss1 = fmaf(o1[d].z, o1[d].z, ss1); ss1 = fmaf(o1[d].w, o1[d].w, ss1);
    }
    #pragma unroll
    for (int off = 1; off < 8; off <<= 1) {
        ss0 += __shfl_xor_sync(0xffffffffu, ss0, off);
        ss1 += __shfl_xor_sync(0xffffffffu, ss1, off);
    }
    const float sc0 = rsqrtf(ss0 * (1.f / 128.f) + 1e-6f);
    const float sc1 = rsqrtf(ss1 * (1.f / 128.f) + 1e-6f);

    const float* zr0 = qkvz + ((size_t)(b * TT + t0 + ta)) * QKVZ_N + CONV_DIM + h * 128;
    const float* zr1 = qkvz + ((size_t)(b * TT + t0 + tb)) * QKVZ_N + CONV_DIM + h * 128;
    __half* gr0 = goh + ((size_t)(b * TT + t0 + ta)) * VALUE_DIM + h * 128;
    __half* gr1 = goh + ((size_t)(b * TT + t0 + tb)) * VALUE_DIM + h * 128;
    #pragma unroll
    for (int d = 0; d < 4; d++) {
        const int dvi = dvg * 4 + 32 * d;
        const float4 z0 = *(const float4*)(zr0 + dvi);
        const float4 z1 = *(const float4*)(zr1 + dvi);
        const float4 nw = *(const float4*)(nws + dvi);
        __half2 h0a = __floats2half2_rn(
            o0[d].x * sc0 * nw.x * (1.f / (1.f + expf(-z0.x))),
            o0[d].y * sc0 * nw.y * (1.f / (1.f + expf(-z0.y))));
        __half2 h0b = __floats2half2_rn(
            o0[d].z * sc0 * nw.z * (1.f / (1.f + expf(-z0.z))),
            o0[d].w * sc0 * nw.w * (1.f / (1.f + expf(-z0.w))));
        __half2 h1a = __floats2half2_rn(
            o1[d].x * sc1 * nw.x * (1.f / (1.f + expf(-z1.x))),
            o1[d].y * sc1 * nw.y * (1.f / (1.f + expf(-z1.y))));
        __half2 h1b = __floats2half2_rn(
            o1[d].z * sc1 * nw.z * (1.f / (1.f + expf(-z1.z))),
            o1[d].w * sc1 * nw.w * (1.f / (1.f + expf(-z1.w))));
        *(__half2*)(gr0 + dvi)     = h0a;
        *(__half2*)(gr0 + dvi + 2) = h0b;
        *(__half2*)(gr1 + dvi)     = h1a;
        *(__half2*)(gr1 + dvi + 2) = h1b;
    }
}

// ---------------- launch -----------------------------------------------------
extern "C" void kernel_launch(void* const* d_in, const int* in_sizes, int n_in,
                              void* d_out, int out_size)
{
    const float* x          = (const float*)d_in[0];
    const int*   input_pos  = (const int*)  d_in[1];
    const float* W_qkvz     = (const float*)d_in[2];
    const float* W_b        = (const float*)d_in[3];
    const float* W_a        = (const float*)d_in[4];
    const float* conv_w     = (const float*)d_in[5];
    const float* norm_w     = (const float*)d_in[6];
    const float* W_out      = (const float*)d_in[7];
    const float* conv_state = (const float*)d_in[8];
    const float* rec_state  = (const float*)d_in[9];
    float* out = (float*)d_out;

    float *qkvz, *y, *beta, *alpha, *attb, *sinc, *spre, *cbuf;
    __half *xh, *wqt, *wot, *goh;
    cudaGetSymbolAddress((void**)&qkvz, g_qkvz);
    cudaGetSymbolAddress((void**)&y,    g_y);
    cudaGetSymbolAddress((void**)&beta, g_beta);
    cudaGetSymbolAddress((void**)&alpha,g_alpha);
    cudaGetSymbolAddress((void**)&attb, g_att);
    cudaGetSymbolAddress((void**)&sinc, g_sinc);
    cudaGetSymbolAddress((void**)&spre, g_spre);
    cudaGetSymbolAddress((void**)&cbuf, g_cc);
    cudaGetSymbolAddress((void**)&xh,  g_xh);
    cudaGetSymbolAddress((void**)&wqt, g_wqt);
    cudaGetSymbolAddress((void**)&wot, g_wot);
    cudaGetSymbolAddress((void**)&goh, g_goh);

    // streams/events created once on the (uncaptured) correctness call
    static cudaStream_t s1 = nullptr;
    static cudaEvent_t evFork = nullptr, evJoin = nullptr;
    if (s1 == nullptr) {
        cudaStreamCreateWithFlags(&s1, cudaStreamNonBlocking);
        cudaEventCreateWithFlags(&evFork, cudaEventDisableTiming);
        cudaEventCreateWithFlags(&evJoin, cudaEventDisableTiming);
        cudaFuncSetAttribute(h16gemm, cudaFuncAttributeMaxDynamicSharedMemorySize, GEMM_SMEM);
        cudaFuncSetAttribute(chunkA, cudaFuncAttributeMaxDynamicSharedMemorySize, SMA_BYTES);
        cudaFuncSetAttribute(chunkC, cudaFuncAttributeMaxDynamicSharedMemorySize, SMC_BYTES);
        cudaFuncSetAttribute(ba2_kernel, cudaFuncAttributeMaxDynamicSharedMemorySize, BA_SMEM);
        cudaFuncSetAttribute(conv2_kernel, cudaFuncAttributeMaxDynamicSharedMemorySize, CONV_SMEM);
    }

    // fork: side stream does ba2 + W_out transpose (depend only on inputs)
    cudaEventRecord(evFork, 0);
    cudaStreamWaitEvent(s1, evFork, 0);
    ba2_kernel<<<BT / 64, 256, BA_SMEM, s1>>>(x, W_b, W_a, beta, alpha);
    transpose_half<<<dim3(CC / 32, CC / 32), 256, 0, s1>>>(W_out, wot, CC, CC);
    cudaEventRecord(evJoin, s1);

    // main stream
    to_half<<<(BT * CC / 8 + 255) / 256, 256>>>(x, xh, BT * CC / 8);
    transpose_half<<<dim3(QKVZ_N / 32, CC / 32), 256>>>(W_qkvz, wqt, CC, QKVZ_N);
    h16gemm<<<dim3(QKVZ_N / 128, BT / 128), 128, GEMM_SMEM>>>(
        xh, wqt, qkvz, BT, QKVZ_N, CC);
    conv2_kernel<<<dim3(8, BT / 8), 256, CONV_SMEM>>>(
        qkvz, conv_w, conv_state, input_pos, y);

    // join: chunkA needs beta/alpha; GEMM2 needs wot
    cudaStreamWaitEvent(0, evJoin, 0);
    chunkA<<<dim3(NCH, BH), 256, SMA_BYTES>>>(y, beta, alpha, attb, sinc, cbuf);
    chunkB<<<dim3(8, BH), 256>>>(sinc, spre, cbuf, rec_state, input_pos);
    chunkC<<<dim3(NCH, BH), 256, SMC_BYTES>>>(y, cbuf, spre, attb, qkvz,
                                              norm_w, goh);
    h16gemm<<<dim3(CC / 128, BT / 128), 128, GEMM_SMEM>>>(
        goh, wot, out, BT, CC, CC);
}

// round 15
// speedup vs baseline: 1.7771x; 1.0082x over previous
#include <cuda_runtime.h>
#include <cuda_fp16.h>
#include <math.h>
#include <stdint.h>

// Problem constants
#define BB 2
#define TT 2048
#define CC 2048
#define HH 16
#define KEY_DIM 2048
#define VALUE_DIM 2048
#define CONV_DIM 6144
#define QKVZ_N 8192
#define BT 4096   // B*T
#define LCH 64
#define NCH (TT / LCH)   // 32 chunks
#define BH 32            // B*H

// ---------------- scratch (static device globals; no allocation) -------------
__device__ float g_qkvz[(size_t)BT * QKVZ_N];
__device__ float g_y[(size_t)BT * CONV_DIM];
__device__ float g_beta[(size_t)BT * HH];
__device__ float g_alpha[(size_t)BT * HH];
__device__ float g_att[(size_t)BT * VALUE_DIM];
__device__ __half g_xh[(size_t)BT * CC];
__device__ __half g_wqt[(size_t)QKVZ_N * CC];
__device__ __half g_wot[(size_t)CC * CC];
__device__ __half g_goh[(size_t)BT * CC];
__device__ float g_sinc[(size_t)BH * NCH * 16384];
__device__ float g_spre[(size_t)BH * NCH * 16384];
__device__ float g_cc[(size_t)BH * TT];

// ---------------- PTX helpers ------------------------------------------------
__device__ __forceinline__ uint32_t s2u(const void* p) {
    uint32_t a;
    asm("{ .reg .u64 t; cvta.to.shared.u64 t, %1; cvt.u32.u64 %0, t; }"
        : "=r"(a) : "l"(p));
    return a;
}
__device__ __forceinline__ void ldsm4(uint32_t* r, uint32_t addr) {
    asm volatile("ldmatrix.sync.aligned.m8n8.x4.shared.b16 {%0,%1,%2,%3}, [%4];"
                 : "=r"(r[0]), "=r"(r[1]), "=r"(r[2]), "=r"(r[3]) : "r"(addr));
}
__device__ __forceinline__ void mma168f16(float* d, const uint32_t* a,
                                          const uint32_t* b) {
    asm volatile(
        "mma.sync.aligned.m16n8k16.row.col.f32.f16.f16.f32 "
        "{%0,%1,%2,%3}, {%4,%5,%6,%7}, {%8,%9}, {%0,%1,%2,%3};\n"
        : "+f"(d[0]), "+f"(d[1]), "+f"(d[2]), "+f"(d[3])
        : "r"(a[0]), "r"(a[1]), "r"(a[2]), "r"(a[3]),
          "r"(b[0]), "r"(b[1]));
}

// ---------------- fp16 tensor-core GEMM: 4 warps, 64x64 warp tile ------------
// C[M, n-range] = A[M,K] * Bt^T, Bt fp16 [n][K] (pre-offset pointer), output
// written with row stride ldc. CTA tile 128x128, 128 threads, 2 CTAs/SM.
#define STAGE_B 20480
#define GEMM_SMEM (2 * STAGE_B)

__global__ void __launch_bounds__(128, 2)
h16gemm(const __half* __restrict__ A, const __half* __restrict__ Bt,
        float* __restrict__ Cm, int ldc, int Kd)
{
    extern __shared__ char smem[];
    const uint32_t sb = s2u(smem);
    const int tid  = threadIdx.x;
    const int bm   = blockIdx.y * 128;
    const int bn   = blockIdx.x * 128;
    const int lane = tid & 31;
    const int warp = tid >> 5;
    const int wm   = (warp >> 1) * 64;
    const int wn   = (warp & 1) * 64;
    const int gid  = lane >> 2;
    const int tig  = lane & 3;

    const int lr = tid >> 2;
    const int lc = tid & 3;

    const __half* Ap = A  + (size_t)(bm + lr) * Kd + lc * 8;
    const __half* Bp = Bt + (size_t)(bn + lr) * Kd + lc * 8;
    const size_t r32 = (size_t)32 * Kd;

    float acc[4][8][4];
    #pragma unroll
    for (int i = 0; i < 4; i++)
        #pragma unroll
        for (int j = 0; j < 8; j++)
            #pragma unroll
            for (int r = 0; r < 4; r++) acc[i][j][r] = 0.f;

    {
        uint4 ra[4], rb[4];
        #pragma unroll
        for (int i = 0; i < 4; i++) {
            ra[i] = *(const uint4*)(Ap + i * r32);
            rb[i] = *(const uint4*)(Bp + i * r32);
        }
        char* s0 = smem;
        char* s0b = smem + 10240;
        #pragma unroll
        for (int i = 0; i < 4; i++) {
            *(uint4*)(s0  + (lr + 32 * i) * 80 + lc * 16) = ra[i];
            *(uint4*)(s0b + (lr + 32 * i) * 80 + lc * 16) = rb[i];
        }
    }
    __syncthreads();

    const int at = lane >> 3;
    const int arow = wm + (at & 1) * 8 + (lane & 7);
    const int akoff = (lane >> 4) * 16;
    const int brow = wn + (lane >> 4) * 8 + (lane & 7);
    const int bkoff = ((lane >> 3) & 1) * 16;

    const int nst = Kd / 32;
    for (int s = 0; s < nst; s++) {
        const bool more = (s + 1) < nst;
        uint4 ra[4], rb[4];
        if (more) {
            Ap += 32; Bp += 32;
            #pragma unroll
            for (int i = 0; i < 4; i++) {
                ra[i] = *(const uint4*)(Ap + i * r32);
                rb[i] = *(const uint4*)(Bp + i * r32);
            }
        }

        const uint32_t base = sb + (uint32_t)(s & 1) * STAGE_B;
        #pragma unroll
        for (int ks = 0; ks < 2; ks++) {
            uint32_t aF[4][4], bF[4][4];
            const uint32_t ak = base + (uint32_t)(ks * 32 + akoff);
            #pragma unroll
            for (int mt = 0; mt < 4; mt++)
                ldsm4(aF[mt], ak + (uint32_t)(arow + mt * 16) * 80);
            const uint32_t bk = base + 10240u + (uint32_t)(ks * 32 + bkoff);
            #pragma unroll
            for (int np = 0; np < 4; np++)
                ldsm4(bF[np], bk + (uint32_t)(brow + np * 16) * 80);
            #pragma unroll
            for (int mt = 0; mt < 4; mt++)
                #pragma unroll
                for (int nt = 0; nt < 8; nt++)
                    mma168f16(acc[mt][nt], aF[mt], &bF[nt >> 1][(nt & 1) * 2]);
        }

        if (more) {
            char* sn  = smem + ((s + 1) & 1) * STAGE_B;
            char* snb = sn + 10240;
            #pragma unroll
            for (int i = 0; i < 4; i++) {
                *(uint4*)(sn  + (lr + 32 * i) * 80 + lc * 16) = ra[i];
                *(uint4*)(snb + (lr + 32 * i) * 80 + lc * 16) = rb[i];
            }
        }
        __syncthreads();
    }

    #pragma unroll
    for (int mt = 0; mt < 4; mt++) {
        const int row = bm + wm + mt * 16 + gid;
        #pragma unroll
        for (int nt = 0; nt < 8; nt++) {
            const int col = bn + wn + nt * 8 + 2 * tig;
            *(float2*)&Cm[(size_t)row * ldc + col]       = make_float2(acc[mt][nt][0], acc[mt][nt][1]);
            *(float2*)&Cm[(size_t)(row + 8) * ldc + col] = make_float2(acc[mt][nt][2], acc[mt][nt][3]);
        }
    }
}

// ---------------- f32 -> f16 convert -----------------------------------------
__global__ void __launch_bounds__(256)
to_half(const float* __restrict__ X, __half* __restrict__ Y, int n8)
{
    int i = blockIdx.x * 256 + threadIdx.x;
    if (i >= n8) return;
    float4 v0 = ((const float4*)X)[i * 2];
    float4 v1 = ((const float4*)X)[i * 2 + 1];
    __half2* H = (__half2*)Y;
    H[i * 4 + 0] = __floats2half2_rn(v0.x, v0.y);
    H[i * 4 + 1] = __floats2half2_rn(v0.z, v0.w);
    H[i * 4 + 2] = __floats2half2_rn(v1.x, v1.y);
    H[i * 4 + 3] = __floats2half2_rn(v1.z, v1.w);
}

// ---------------- transpose: W[K][N] f32 -> Wt[N][K] f16 ---------------------
__global__ void __launch_bounds__(256)
transpose_half(const float* __restrict__ W, __half* __restrict__ Th, int K, int N)
{
    __shared__ float tile[32][33];
    const int k0 = blockIdx.y * 32, n0 = blockIdx.x * 32;
    const int tx = threadIdx.x & 31, ty = threadIdx.x >> 5;
    #pragma unroll
    for (int r = 0; r < 32; r += 8)
        tile[ty + r][tx] = W[(size_t)(k0 + ty + r) * N + n0 + tx];
    __syncthreads();
    #pragma unroll
    for (int r = 0; r < 32; r += 8)
        Th[(size_t)(n0 + ty + r) * K + k0 + tx] = __float2half(tile[tx][ty + r]);
}

// ---------------- beta/alpha: tiled fp32 GEMM --------------------------------
#define BA_SMEM (64 * 132 * 4 + 128 * 32 * 4)
__global__ void __launch_bounds__(256)
ba2_kernel(const float* __restrict__ x, const float* __restrict__ Wb,
           const float* __restrict__ Wa, float* __restrict__ beta,
           float* __restrict__ alpha)
{
    extern __shared__ float sm[];
    float* xs = sm;
    float* ws = sm + 64 * 132;

    const int tid = threadIdx.x;
    const int r0 = blockIdx.x * 64;
    const int tr = tid >> 4;
    const int tc = tid & 15;

    float acc[4][2];
    #pragma unroll
    for (int i = 0; i < 4; i++) { acc[i][0] = 0.f; acc[i][1] = 0.f; }

    for (int k0 = 0; k0 < CC; k0 += 128) {
        #pragma unroll
        for (int i = 0; i < 8; i++) {
            const int idx = tid + i * 256;
            const int row = idx >> 5, c4 = (idx & 31) * 4;
            *(float4*)&xs[row * 132 + c4] =
                *(const float4*)&x[(size_t)(r0 + row) * CC + k0 + c4];
        }
        #pragma unroll
        for (int i = 0; i < 2; i++) {
            const int idx = tid + i * 256;
            const int kk = idx >> 2, q = (idx & 3) * 4;
            *(float4*)&ws[kk * 32 + q]      = *(const float4*)&Wb[(size_t)(k0 + kk) * HH + q];
            *(float4*)&ws[kk * 32 + 16 + q] = *(const float4*)&Wa[(size_t)(k0 + kk) * HH + q];
        }
        __syncthreads();

        for (int kk = 0; kk < 128; kk++) {
            const float2 wv = *(const float2*)&ws[kk * 32 + tc * 2];
            #pragma unroll
            for (int i = 0; i < 4; i++) {
                const float xv = xs[(tr * 4 + i) * 132 + kk];
                acc[i][0] = fmaf(xv, wv.x, acc[i][0]);
                acc[i][1] = fmaf(xv, wv.y, acc[i][1]);
            }
        }
        __syncthreads();
    }

    #pragma unroll
    for (int i = 0; i < 4; i++) {
        const int row = r0 + tr * 4 + i;
        #pragma unroll
        for (int j = 0; j < 2; j++) {
            const int c = tc * 2 + j;
            const float v = 1.f / (1.f + expf(-acc[i][j]));
            if (c < 16) beta[(size_t)row * HH + c] = v;
            else        alpha[(size_t)row * HH + (c - 16)] = v;
        }
    }
}

// ---------------- conv: time-tiled -------------------------------------------
#define CONV_SMEM ((11 * 768 + 8 * 768 + 48) * 4)
__global__ void __launch_bounds__(256)
conv2_kernel(const float* __restrict__ qkvz, const float* __restrict__ conv_w,
             const float* __restrict__ conv_state, const int* __restrict__ input_pos,
             float* __restrict__ y_out)
{
    extern __shared__ float sm[];
    float* in  = sm;
    float* yb  = sm + 11 * 768;
    float* nrm = sm + 19 * 768;

    const int cg = blockIdx.x;
    const int c0 = cg * 768;
    const int tgl = blockIdx.y;
    const int b = tgl >> 8;
    const int t0 = (tgl & 255) * 8;
    const int tid = threadIdx.x;
    const float keep = (input_pos[0] == 0) ? 0.f : 1.f;

    for (int idx = tid; idx < 11 * 192; idx += 256) {
        const int r = idx / 192, c4 = (idx % 192) * 4;
        const int tau = t0 - 3 + r;
        float4 v;
        if (tau >= 0) {
            v = *(const float4*)&qkvz[((size_t)(b * TT + tau)) * QKVZ_N + c0 + c4];
        } else {
            const int slot = tau + 4;
            v.x = keep * conv_state[((size_t)b * CONV_DIM + c0 + c4 + 0) * 4 + slot];
            v.y = keep * conv_state[((size_t)b * CONV_DIM + c0 + c4 + 1) * 4 + slot];
            v.z = keep * conv_state[((size_t)b * CONV_DIM + c0 + c4 + 2) * 4 + slot];
            v.w = keep * conv_state[((size_t)b * CONV_DIM + c0 + c4 + 3) * 4 + slot];
        }
        *(float4*)&in[r * 768 + c4] = v;
    }
    __syncthreads();

    for (int idx = tid; idx < 1536; idx += 256) {
        const int t = idx / 192, c4 = (idx % 192) * 4;
        float4 o;
        float* op = (float*)&o;
        #pragma unroll
        for (int e = 0; e < 4; e++) {
            const int c = c4 + e;
            const float4 w = *(const float4*)&conv_w[(size_t)(c0 + c) * 4];
            float acc = in[(t + 0) * 768 + c] * w.x + in[(t + 1) * 768 + c] * w.y
                      + in[(t + 2) * 768 + c] * w.z + in[(t + 3) * 768 + c] * w.w;
            op[e] = acc / (1.f + expf(-acc));
        }
        *(float4*)&yb[t * 768 + c4] = o;
    }
    __syncthreads();

    {
        const int w = tid >> 5, lane = tid & 31;
        for (int p = w; p < 48; p += 8) {
            const int t = p / 6, hl = p % 6;
            const int hg = (c0 >> 7) + hl;
            float ss = 0.f;
            #pragma unroll
            for (int i = 0; i < 4; i++) {
                const float v = yb[t * 768 + hl * 128 + lane + i * 32];
                ss = fmaf(v, v, ss);
            }
            #pragma unroll
            for (int off = 16; off > 0; off >>= 1)
                ss += __shfl_xor_sync(0xffffffffu, ss, off);
            if (lane == 0)
                nrm[t * 6 + hl] = (hg < 32) ? (1.f / fmaxf(sqrtf(ss), 1e-12f)) : 1.f;
        }
    }
    __syncthreads();

    for (int idx = tid; idx < 1536; idx += 256) {
        const int t = idx / 192, c4 = (idx % 192) * 4;
        const float inv = nrm[t * 6 + (c4 >> 7)];
        float4 v = *(const float4*)&yb[t * 768 + c4];
        v.x *= inv; v.y *= inv; v.z *= inv; v.w *= inv;
        *(float4*)&y_out[((size_t)(b * TT + t0 + t)) * CONV_DIM + c0 + c4] = v;
    }
}

// ---------------- chunked recurrence: phase A --------------------------------
#define SA_QS 0
#define SA_KT (64 * 132)
#define SA_VS (SA_KT + 128 * 68)
#define SA_P  (SA_VS + 64 * 132)
#define SA_CS (SA_P + 64 * 68)
#define SA_BS (SA_CS + 64)
#define SMA_BYTES ((SA_BS + 64) * 4)

__global__ void __launch_bounds__(256)
chunkA(const float* __restrict__ y, const float* __restrict__ beta,
       const float* __restrict__ alpha, float* __restrict__ att,
       float* __restrict__ sinc, float* __restrict__ cbuf)
{
    extern __shared__ float sm[];
    float* qs  = sm + SA_QS;
    float* ksT = sm + SA_KT;
    float* vs  = sm + SA_VS;
    float* P   = sm + SA_P;
    float* cs  = sm + SA_CS;
    float* bs  = sm + SA_BS;

    const int bh = blockIdx.y, j = blockIdx.x;
    const int b = bh >> 4, h = bh & 15;
    const int t0 = j * LCH;
    const int tid = threadIdx.x;

    for (int i = tid; i < 2048; i += 256) {
        const int row = i >> 5, c4 = (i & 31) * 4;
        const float* yr = y + ((size_t)(b * TT + t0 + row)) * CONV_DIM + h * 128;
        float4 q4 = *(const float4*)(yr + c4);
        float4 k4 = *(const float4*)(yr + KEY_DIM + c4);
        float4 v4 = *(const float4*)(yr + 2 * KEY_DIM + c4);
        *(float4*)&qs[row * 132 + c4] = q4;
        ksT[(c4 + 0) * 68 + row] = k4.x;
        ksT[(c4 + 1) * 68 + row] = k4.y;
        ksT[(c4 + 2) * 68 + row] = k4.z;
        ksT[(c4 + 3) * 68 + row] = k4.w;
        *(float4*)&vs[row * 132 + c4] = v4;
    }
    if (tid < 64) {
        cs[tid] = log2f(alpha[((size_t)(b * TT + t0 + tid)) * HH + h]);
        bs[tid] = beta[((size_t)(b * TT + t0 + tid)) * HH + h];
    }
    __syncthreads();
    if (tid == 0) {
        float run = 0.f;
        for (int t = 0; t < LCH; t++) { run += cs[t]; cs[t] = run; }
    }
    __syncthreads();
    if (tid < 64) cbuf[(size_t)bh * TT + t0 + tid] = cs[tid];

    {
        const int rt = tid >> 4, ct = tid & 15;
        float acc[4][4];
        #pragma unroll
        for (int i = 0; i < 4; i++)
            #pragma unroll
            for (int j2 = 0; j2 < 4; j2++) acc[i][j2] = 0.f;
        if (ct <= rt) {
            for (int kk0 = 0; kk0 < 128; kk0 += 4) {
                float4 qv[4], kv[4];
                #pragma unroll
                for (int i = 0; i < 4; i++)
                    qv[i] = *(const float4*)&qs[(rt * 4 + i) * 132 + kk0];
                #pragma unroll
                for (int q = 0; q < 4; q++)
                    kv[q] = *(const float4*)&ksT[(kk0 + q) * 68 + ct * 4];
                #pragma unroll
                for (int q = 0; q < 4; q++) {
                    const float* kq = (const float*)&kv[q];
                    #pragma unroll
                    for (int i = 0; i < 4; i++) {
                        const float qq = ((const float*)&qv[i])[q];
                        #pragma unroll
                        for (int j2 = 0; j2 < 4; j2++)
                            acc[i][j2] = fmaf(qq, kq[j2], acc[i][j2]);
                    }
                }
            }
        }
        #pragma unroll
        for (int i = 0; i < 4; i++)
            #pragma unroll
            for (int j2 = 0; j2 < 4; j2++) {
                const int t = rt * 4 + i, tau = ct * 4 + j2;
                float val = 0.f;
                if (tau <= t)
                    val = acc[i][j2] * bs[tau] * exp2f(cs[t] - cs[tau]);
                P[t * 68 + tau] = val;
            }
    }
    __syncthreads();

    {
        const int tg = tid >> 3, dvg = tid & 7;
        const int ta = tg * 2, tb = ta + 1;
        float4 o0[4], o1[4];
        #pragma unroll
        for (int d = 0; d < 4; d++) {
            o0[d] = make_float4(0.f, 0.f, 0.f, 0.f);
            o1[d] = make_float4(0.f, 0.f, 0.f, 0.f);
        }
        for (int tau = 0; tau < LCH; tau++) {
            const float p0 = P[ta * 68 + tau];
            const float p1 = P[tb * 68 + tau];
            const float* vr = vs + tau * 132;
            #pragma unroll
            for (int d = 0; d < 4; d++) {
                const float4 vv = *(const float4*)(vr + dvg * 4 + 32 * d);
                o0[d].x = fmaf(p0, vv.x, o0[d].x); o0[d].y = fmaf(p0, vv.y, o0[d].y);
                o0[d].z = fmaf(p0, vv.z, o0[d].z); o0[d].w = fmaf(p0, vv.w, o0[d].w);
                o1[d].x = fmaf(p1, vv.x, o1[d].x); o1[d].y = fmaf(p1, vv.y, o1[d].y);
                o1[d].z = fmaf(p1, vv.z, o1[d].z); o1[d].w = fmaf(p1, vv.w, o1[d].w);
            }
        }
        float* ar0 = att + ((size_t)(b * TT + t0 + ta)) * VALUE_DIM + h * 128;
        float* ar1 = att + ((size_t)(b * TT + t0 + tb)) * VALUE_DIM + h * 128;
        #pragma unroll
        for (int d = 0; d < 4; d++) {
            *(float4*)(ar0 + dvg * 4 + 32 * d) = o0[d];
            *(float4*)(ar1 + dvg * 4 + 32 * d) = o1[d];
        }
    }

    {
        const int dkt = tid >> 4, dvt = tid & 15;
        float4 sacc[8][2];
        #pragma unroll
        for (int i = 0; i < 8; i++)
            #pragma unroll
            for (int dj = 0; dj < 2; dj++)
                sacc[i][dj] = make_float4(0.f, 0.f, 0.f, 0.f);
        const float cL = cs[63];
        for (int tau = 0; tau < LCH; tau++) {
            const float w = bs[tau] * exp2f(cL - cs[tau]);
            float kw[8];
            #pragma unroll
            for (int i = 0; i < 8; i++) kw[i] = ksT[(dkt + 16 * i) * 68 + tau] * w;
            float4 vv[2];
            #pragma unroll
            for (int dj = 0; dj < 2; dj++)
                vv[dj] = *(const float4*)&vs[tau * 132 + dvt * 4 + 64 * dj];
            #pragma unroll
            for (int i = 0; i < 8; i++)
                #pragma unroll
                for (int dj = 0; dj < 2; dj++) {
                    sacc[i][dj].x = fmaf(kw[i], vv[dj].x, sacc[i][dj].x);
                    sacc[i][dj].y = fmaf(kw[i], vv[dj].y, sacc[i][dj].y);
                    sacc[i][dj].z = fmaf(kw[i], vv[dj].z, sacc[i][dj].z);
                    sacc[i][dj].w = fmaf(kw[i], vv[dj].w, sacc[i][dj].w);
                }
        }
        float* sp = sinc + ((size_t)(bh * NCH + j)) * 16384;
        #pragma unroll
        for (int i = 0; i < 8; i++)
            #pragma unroll
            for (int dj = 0; dj < 2; dj++)
                *(float4*)&sp[(dkt + 16 * i) * 128 + dvt * 4 + 64 * dj] = sacc[i][dj];
    }
}

// ---------------- phase B: 8-way sliced scan ---------------------------------
__global__ void __launch_bounds__(256)
chunkB(const float* __restrict__ sinc, float* __restrict__ spre,
       const float* __restrict__ cbuf, const float* __restrict__ rstate,
       const int* __restrict__ input_pos)
{
    const int bh = blockIdx.y;
    const int off0 = blockIdx.x * 2048 + threadIdx.x;
    const float keep = (input_pos[0] == 0) ? 0.f : 1.f;

    float s[8];
    #pragma unroll
    for (int i = 0; i < 8; i++)
        s[i] = keep * rstate[(size_t)bh * 16384 + off0 + i * 256];

    for (int j = 0; j < NCH; j++) {
        const size_t base = ((size_t)(bh * NCH + j)) * 16384 + off0;
        #pragma unroll
        for (int i = 0; i < 8; i++)
            spre[base + i * 256] = s[i];
        const float dec = exp2f(cbuf[(size_t)bh * TT + j * LCH + 63]);
        #pragma unroll
        for (int i = 0; i < 8; i++)
            s[i] = fmaf(dec, s[i], sinc[base + i * 256]);
    }
}

// ---------------- phase C fused with gate ------------------------------------
#define SMC_BYTES (25536 * 4)
__global__ void __launch_bounds__(256)
chunkC(const float* __restrict__ y, const float* __restrict__ cbuf,
       const float* __restrict__ spre, const float* __restrict__ att,
       const float* __restrict__ qkvz, const float* __restrict__ norm_w,
       __half* __restrict__ goh)
{
    extern __shared__ float sm[];
    float* S   = sm;
    float* qs  = sm + 128 * 132;
    float* cs  = qs + 64 * 132;
    float* nws = cs + 64;

    const int bh = blockIdx.y, j = blockIdx.x;
    const int b = bh >> 4, h = bh & 15;
    const int t0 = j * LCH;
    const int tid = threadIdx.x;

    const float* sp = spre + ((size_t)(bh * NCH + j)) * 16384;
    for (int i = tid; i < 4096; i += 256) {
        const int dk = i >> 5, dv4 = (i & 31) * 4;
        *(float4*)&S[dk * 132 + dv4] = *(const float4*)&sp[dk * 128 + dv4];
    }
    for (int i = tid; i < 2048; i += 256) {
        const int row = i >> 5, c4 = (i & 31) * 4;
        const float* yr = y + ((size_t)(b * TT + t0 + row)) * CONV_DIM + h * 128;
        *(float4*)&qs[row * 132 + c4] = *(const float4*)(yr + c4);
    }
    if (tid < 64) cs[tid] = cbuf[(size_t)bh * TT + t0 + tid];
    if (tid < 128) nws[tid] = norm_w[tid];
    __syncthreads();

    const int tg = tid >> 3, dvg = tid & 7;
    const int ta = tg * 2, tb = ta + 1;
    float4 o0[4], o1[4];
    #pragma unroll
    for (int d = 0; d < 4; d++) {
        o0[d] = make_float4(0.f, 0.f, 0.f, 0.f);
        o1[d] = make_float4(0.f, 0.f, 0.f, 0.f);
    }
    for (int dk = 0; dk < 128; dk++) {
        const float q0 = qs[ta * 132 + dk];
        const float q1 = qs[tb * 132 + dk];
        const float* srow = S + dk * 132;
        #pragma unroll
        for (int d = 0; d < 4; d++) {
            const float4 sv = *(const float4*)(srow + dvg * 4 + 32 * d);
            o0[d].x = fmaf(q0, sv.x, o0[d].x); o0[d].y = fmaf(q0, sv.y, o0[d].y);
            o0[d].z = fmaf(q0, sv.z, o0[d].z); o0[d].w = fmaf(q0, sv.w, o0[d].w);
            o1[d].x = fmaf(q1, sv.x, o1[d].x); o1[d].y = fmaf(q1, sv.y, o1[d].y);
            o1[d].z = fmaf(q1, sv.z, o1[d].z); o1[d].w = fmaf(q1, sv.w, o1[d].w);
        }
    }
    const float e0 = exp2f(cs[ta]);
    const float e1 = exp2f(cs[tb]);

    const float* ar0 = att + ((size_t)(b * TT + t0 + ta)) * VALUE_DIM + h * 128;
    const float* ar1 = att + ((size_t)(b * TT + t0 + tb)) * VALUE_DIM + h * 128;
    float ss0 = 0.f, ss1 = 0.f;
    #pragma unroll
    for (int d = 0; d < 4; d++) {
        const float4 a0 = *(const float4*)(ar0 + dvg * 4 + 32 * d);
        const float4 a1 = *(const float4*)(ar1 + dvg * 4 + 32 * d);
        o0[d].x = a0.x + e0 * o0[d].x;  o0[d].y = a0.y + e0 * o0[d].y;
        o0[d].z = a0.z + e0 * o0[d].z;  o0[d].w = a0.w + e0 * o0[d].w;
        o1[d].x = a1.x + e1 * o1[d].x;  o1[d].y = a1.y + e1 * o1[d].y;
        o1[d].z = a1.z + e1 * o1[d].z;  o1[d].w = a1.w + e1 * o1[d].w;
        ss0 = fmaf(o0[d].x, o0[d].x, ss0); ss0 = fmaf(o0[d].y, o0[d].y, ss0);
        ss0 = fmaf(o0[d].z, o0[d].z, ss0); ss0 = fmaf(o0[d].w, o0[d].w, ss0);
        ss1 = fmaf(o1[d].x, o1[d].x, ss1); ss1 = fmaf(o1[d].y, o1[d].y, ss1);
        ss1 = fmaf(o1[d].z, o1[d].z, ss1); ss1 = fmaf(o1[d].w, o1[d].w, ss1);
    }
    #pragma unroll
    for (int off = 1; off < 8; off <<= 1) {
        ss0 += __shfl_xor_sync(0xffffffffu, ss0, off);
        ss1 += __shfl_xor_sync(0xffffffffu, ss1, off);
    }
    const float sc0 = rsqrtf(ss0 * (1.f / 128.f) + 1e-6f);
    const float sc1 = rsqrtf(ss1 * (1.f / 128.f) + 1e-6f);

    const float* zr0 = qkvz + ((size_t)(b * TT + t0 + ta)) * QKVZ_N + CONV_DIM + h * 128;
    const float* zr1 = qkvz + ((size_t)(b * TT + t0 + tb)) * QKVZ_N + CONV_DIM + h * 128;
    __half* gr0 = goh + ((size_t)(b * TT + t0 + ta)) * VALUE_DIM + h * 128;
    __half* gr1 = goh + ((size_t)(b * TT + t0 + tb)) * VALUE_DIM + h * 128;
    #pragma unroll
    for (int d = 0; d < 4; d++) {
        const int dvi = dvg * 4 + 32 * d;
        const float4 z0 = *(const float4*)(zr0 + dvi);
        const float4 z1 = *(const float4*)(zr1 + dvi);
        const float4 nw = *(const float4*)(nws + dvi);
        __half2 h0a = __floats2half2_rn(
            o0[d].x * sc0 * nw.x * (1.f / (1.f + expf(-z0.x))),
            o0[d].y * sc0 * nw.y * (1.f / (1.f + expf(-z0.y))));
        __half2 h0b = __floats2half2_rn(
            o0[d].z * sc0 * nw.z * (1.f / (1.f + expf(-z0.z))),
            o0[d].w * sc0 * nw.w * (1.f / (1.f + expf(-z0.w))));
        __half2 h1a = __floats2half2_rn(
            o1[d].x * sc1 * nw.x * (1.f / (1.f + expf(-z1.x))),
            o1[d].y * sc1 * nw.y * (1.f / (1.f + expf(-z1.y))));
        __half2 h1b = __floats2half2_rn(
            o1[d].z * sc1 * nw.z * (1.f / (1.f + expf(-z1.z))),
            o1[d].w * sc1 * nw.w * (1.f / (1.f + expf(-z1.w))));
        *(__half2*)(gr0 + dvi)     = h0a;
        *(__half2*)(gr0 + dvi + 2) = h0b;
        *(__half2*)(gr1 + dvi)     = h1a;
        *(__half2*)(gr1 + dvi + 2) = h1b;
    }
}

// ---------------- launch -----------------------------------------------------
extern "C" void kernel_launch(void* const* d_in, const int* in_sizes, int n_in,
                              void* d_out, int out_size)
{
    const float* x          = (const float*)d_in[0];
    const int*   input_pos  = (const int*)  d_in[1];
    const float* W_qkvz     = (const float*)d_in[2];
    const float* W_b        = (const float*)d_in[3];
    const float* W_a        = (const float*)d_in[4];
    const float* conv_w     = (const float*)d_in[5];
    const float* norm_w     = (const float*)d_in[6];
    const float* W_out      = (const float*)d_in[7];
    const float* conv_state = (const float*)d_in[8];
    const float* rec_state  = (const float*)d_in[9];
    float* out = (float*)d_out;

    float *qkvz, *y, *beta, *alpha, *attb, *sinc, *spre, *cbuf;
    __half *xh, *wqt, *wot, *goh;
    cudaGetSymbolAddress((void**)&qkvz, g_qkvz);
    cudaGetSymbolAddress((void**)&y,    g_y);
    cudaGetSymbolAddress((void**)&beta, g_beta);
    cudaGetSymbolAddress((void**)&alpha,g_alpha);
    cudaGetSymbolAddress((void**)&attb, g_att);
    cudaGetSymbolAddress((void**)&sinc, g_sinc);
    cudaGetSymbolAddress((void**)&spre, g_spre);
    cudaGetSymbolAddress((void**)&cbuf, g_cc);
    cudaGetSymbolAddress((void**)&xh,  g_xh);
    cudaGetSymbolAddress((void**)&wqt, g_wqt);
    cudaGetSymbolAddress((void**)&wot, g_wot);
    cudaGetSymbolAddress((void**)&goh, g_goh);

    static cudaStream_t s1 = nullptr, s2 = nullptr;
    static cudaEvent_t evFork = nullptr, evWq = nullptr, evBA = nullptr, evZ = nullptr;
    if (s1 == nullptr) {
        cudaStreamCreateWithFlags(&s1, cudaStreamNonBlocking);
        cudaStreamCreateWithFlags(&s2, cudaStreamNonBlocking);
        cudaEventCreateWithFlags(&evFork, cudaEventDisableTiming);
        cudaEventCreateWithFlags(&evWq, cudaEventDisableTiming);
        cudaEventCreateWithFlags(&evBA, cudaEventDisableTiming);
        cudaEventCreateWithFlags(&evZ, cudaEventDisableTiming);
        cudaFuncSetAttribute(h16gemm, cudaFuncAttributeMaxDynamicSharedMemorySize, GEMM_SMEM);
        cudaFuncSetAttribute(chunkA, cudaFuncAttributeMaxDynamicSharedMemorySize, SMA_BYTES);
        cudaFuncSetAttribute(chunkC, cudaFuncAttributeMaxDynamicSharedMemorySize, SMC_BYTES);
        cudaFuncSetAttribute(ba2_kernel, cudaFuncAttributeMaxDynamicSharedMemorySize, BA_SMEM);
        cudaFuncSetAttribute(conv2_kernel, cudaFuncAttributeMaxDynamicSharedMemorySize, CONV_SMEM);
    }

    // fork
    cudaEventRecord(evFork, 0);
    cudaStreamWaitEvent(s1, evFork, 0);
    cudaStreamWaitEvent(s2, evFork, 0);

    // s1: transpose W_qkvz (feeds GEMM1)
    transpose_half<<<dim3(QKVZ_N / 32, CC / 32), 256, 0, s1>>>(W_qkvz, wqt, CC, QKVZ_N);
    cudaEventRecord(evWq, s1);

    // s2: ba2 + transpose W_out (feed chunkA / GEMM2)
    ba2_kernel<<<BT / 64, 256, BA_SMEM, s2>>>(x, W_b, W_a, beta, alpha);
    transpose_half<<<dim3(CC / 32, CC / 32), 256, 0, s2>>>(W_out, wot, CC, CC);
    cudaEventRecord(evBA, s2);

    // main: to_half(x), then GEMM1a (qkv columns only, N range 6144)
    to_half<<<(BT * CC / 8 + 255) / 256, 256>>>(x, xh, BT * CC / 8);
    cudaStreamWaitEvent(0, evWq, 0);
    h16gemm<<<dim3(CONV_DIM / 128, BT / 128), 128, GEMM_SMEM>>>(
        xh, wqt, qkvz, QKVZ_N, CC);
    cudaEventRecord(evFork, 0);   // reuse as "GEMM1a done / xh+wqt ready"

    // s1: z-block GEMM (N=2048) concurrent with conv/chunkA
    cudaStreamWaitEvent(s1, evFork, 0);
    h16gemm<<<dim3(VALUE_DIM / 128, BT / 128), 128, GEMM_SMEM, s1>>>(
        xh, wqt + (size_t)CONV_DIM * CC, qkvz + CONV_DIM, QKVZ_N, CC);
    cudaEventRecord(evZ, s1);

    // main: conv (reads only qkv columns)
    conv2_kernel<<<dim3(8, BT / 8), 256, CONV_SMEM>>>(
        qkvz, conv_w, conv_state, input_pos, y);

    cudaStreamWaitEvent(0, evBA, 0);
    chunkA<<<dim3(NCH, BH), 256, SMA_BYTES>>>(y, beta, alpha, attb, sinc, cbuf);
    chunkB<<<dim3(8, BH), 256>>>(sinc, spre, cbuf, rec_state, input_pos);
    cudaStreamWaitEvent(0, evZ, 0);
    chunkC<<<dim3(NCH, BH), 256, SMC_BYTES>>>(y, cbuf, spre, attb, qkvz,
                                              norm_w, goh);
    h16gemm<<<dim3(CC / 128, BT / 128), 128, GEMM_SMEM>>>(
        goh, wot, out, CC, CC);
}

// round 16
// speedup vs baseline: 1.9225x; 1.0818x over previous
#include <cuda_runtime.h>
#include <cuda_fp16.h>
#include <math.h>
#include <stdint.h>

// Problem constants
#define BB 2
#define TT 2048
#define CC 2048
#define HH 16
#define KEY_DIM 2048
#define VALUE_DIM 2048
#define CONV_DIM 6144
#define QKVZ_N 8192
#define BT 4096   // B*T
#define LCH 64
#define NCH (TT / LCH)   // 32 chunks
#define BH 32            // B*H

// ---------------- scratch (static device globals; no allocation) -------------
__device__ float g_qkvz[(size_t)BT * QKVZ_N];
__device__ float g_y[(size_t)BT * CONV_DIM];
__device__ float g_beta[(size_t)BT * HH];
__device__ float g_alpha[(size_t)BT * HH];
__device__ float g_att[(size_t)BT * VALUE_DIM];
__device__ __half g_xh[(size_t)BT * CC];
__device__ __half g_wqt[(size_t)QKVZ_N * CC];
__device__ __half g_wot[(size_t)CC * CC];
__device__ __half g_goh[(size_t)BT * CC];
__device__ float g_sinc[(size_t)BH * NCH * 16384];
__device__ float g_spre[(size_t)BH * NCH * 16384];
__device__ float g_cc[(size_t)BH * TT];

// ---------------- PTX helpers ------------------------------------------------
__device__ __forceinline__ uint32_t s2u(const void* p) {
    uint32_t a;
    asm("{ .reg .u64 t; cvta.to.shared.u64 t, %1; cvt.u32.u64 %0, t; }"
        : "=r"(a) : "l"(p));
    return a;
}
__device__ __forceinline__ void ldsm4(uint32_t* r, uint32_t addr) {
    asm volatile("ldmatrix.sync.aligned.m8n8.x4.shared.b16 {%0,%1,%2,%3}, [%4];"
                 : "=r"(r[0]), "=r"(r[1]), "=r"(r[2]), "=r"(r[3]) : "r"(addr));
}
__device__ __forceinline__ void mma168f16(float* d, const uint32_t* a,
                                          const uint32_t* b) {
    asm volatile(
        "mma.sync.aligned.m16n8k16.row.col.f32.f16.f16.f32 "
        "{%0,%1,%2,%3}, {%4,%5,%6,%7}, {%8,%9}, {%0,%1,%2,%3};\n"
        : "+f"(d[0]), "+f"(d[1]), "+f"(d[2]), "+f"(d[3])
        : "r"(a[0]), "r"(a[1]), "r"(a[2]), "r"(a[3]),
          "r"(b[0]), "r"(b[1]));
}
__device__ __forceinline__ void cpasync16(uint32_t dst, const void* src) {
    asm volatile("cp.async.cg.shared.global [%0], [%1], 16;"
                 :: "r"(dst), "l"(src));
}
__device__ __forceinline__ void cp_commit() {
    asm volatile("cp.async.commit_group;");
}
__device__ __forceinline__ void cp_wait1() {
    asm volatile("cp.async.wait_group 1;" ::: "memory");
}
__device__ __forceinline__ void cp_wait0() {
    asm volatile("cp.async.wait_group 0;" ::: "memory");
}

// ---------------- fp16 tensor-core GEMM: cp.async 3-stage pipeline -----------
// C[M, n-range] = A[M,K] * Bt^T, Bt fp16 [n][K] (pre-offset), output stride ldc.
// CTA tile 128x128, 128 threads (2x2 warps), warp tile 64x64, 2 CTAs/SM.
// Stage = (128 A + 128 B) rows x 80B = 20480B; 3 stages = 61440B.
#define STAGE_B 20480
#define GEMM_SMEM (3 * STAGE_B)

__global__ void __launch_bounds__(128, 2)
h16gemm(const __half* __restrict__ A, const __half* __restrict__ Bt,
        float* __restrict__ Cm, int ldc, int Kd)
{
    extern __shared__ char smem[];
    const uint32_t sb = s2u(smem);
    const int tid  = threadIdx.x;
    const int bm   = blockIdx.y * 128;
    const int bn   = blockIdx.x * 128;
    const int lane = tid & 31;
    const int warp = tid >> 5;
    const int wm   = (warp >> 1) * 64;
    const int wn   = (warp & 1) * 64;
    const int gid  = lane >> 2;
    const int tig  = lane & 3;

    const int lr = tid >> 2;             // 0..31
    const int lc = tid & 3;              // k-chunk (8 halves)

    const __half* Ap0 = A  + (size_t)(bm + lr) * Kd + lc * 8;
    const __half* Bp0 = Bt + (size_t)(bn + lr) * Kd + lc * 8;
    const size_t r32 = (size_t)32 * Kd;

    float acc[4][8][4];
    #pragma unroll
    for (int i = 0; i < 4; i++)
        #pragma unroll
        for (int j = 0; j < 8; j++)
            #pragma unroll
            for (int r = 0; r < 4; r++) acc[i][j][r] = 0.f;

    // async stage fill: 8 x 16B per thread
    auto issue = [&](int s) {
        const uint32_t dst = sb + (uint32_t)(s % 3) * STAGE_B;
        const __half* Ap = Ap0 + s * 32;
        const __half* Bp = Bp0 + s * 32;
        #pragma unroll
        for (int i = 0; i < 4; i++) {
            cpasync16(dst + (uint32_t)(lr + 32 * i) * 80 + lc * 16, Ap + i * r32);
            cpasync16(dst + 10240u + (uint32_t)(lr + 32 * i) * 80 + lc * 16, Bp + i * r32);
        }
        cp_commit();
    };

    const int nst = Kd / 32;
    issue(0);
    issue(1);

    const int at = lane >> 3;
    const int arow = wm + (at & 1) * 8 + (lane & 7);
    const int akoff = (lane >> 4) * 16;
    const int brow = wn + (lane >> 4) * 8 + (lane & 7);
    const int bkoff = ((lane >> 3) & 1) * 16;

    for (int s = 0; s < nst; s++) {
        if (s + 1 < nst) cp_wait1();
        else             cp_wait0();
        __syncthreads();                 // all warps done with stage s-1 compute
        if (s + 2 < nst) issue(s + 2);   // fills buffer (s+2)%3 == (s-1)%3

        const uint32_t base = sb + (uint32_t)(s % 3) * STAGE_B;
        #pragma unroll
        for (int ks = 0; ks < 2; ks++) {
            uint32_t aF[4][4], bF[4][4];
            const uint32_t ak = base + (uint32_t)(ks * 32 + akoff);
            #pragma unroll
            for (int mt = 0; mt < 4; mt++)
                ldsm4(aF[mt], ak + (uint32_t)(arow + mt * 16) * 80);
            const uint32_t bk = base + 10240u + (uint32_t)(ks * 32 + bkoff);
            #pragma unroll
            for (int np = 0; np < 4; np++)
                ldsm4(bF[np], bk + (uint32_t)(brow + np * 16) * 80);
            #pragma unroll
            for (int mt = 0; mt < 4; mt++)
                #pragma unroll
                for (int nt = 0; nt < 8; nt++)
                    mma168f16(acc[mt][nt], aF[mt], &bF[nt >> 1][(nt & 1) * 2]);
        }
    }

    #pragma unroll
    for (int mt = 0; mt < 4; mt++) {
        const int row = bm + wm + mt * 16 + gid;
        #pragma unroll
        for (int nt = 0; nt < 8; nt++) {
            const int col = bn + wn + nt * 8 + 2 * tig;
            *(float2*)&Cm[(size_t)row * ldc + col]       = make_float2(acc[mt][nt][0], acc[mt][nt][1]);
            *(float2*)&Cm[(size_t)(row + 8) * ldc + col] = make_float2(acc[mt][nt][2], acc[mt][nt][3]);
        }
    }
}

// ---------------- f32 -> f16 convert -----------------------------------------
__global__ void __launch_bounds__(256)
to_half(const float* __restrict__ X, __half* __restrict__ Y, int n8)
{
    int i = blockIdx.x * 256 + threadIdx.x;
    if (i >= n8) return;
    float4 v0 = ((const float4*)X)[i * 2];
    float4 v1 = ((const float4*)X)[i * 2 + 1];
    __half2* H = (__half2*)Y;
    H[i * 4 + 0] = __floats2half2_rn(v0.x, v0.y);
    H[i * 4 + 1] = __floats2half2_rn(v0.z, v0.w);
    H[i * 4 + 2] = __floats2half2_rn(v1.x, v1.y);
    H[i * 4 + 3] = __floats2half2_rn(v1.z, v1.w);
}

// ---------------- transpose: W[K][N] f32 -> Wt[N][K] f16 ---------------------
__global__ void __launch_bounds__(256)
transpose_half(const float* __restrict__ W, __half* __restrict__ Th, int K, int N)
{
    __shared__ float tile[32][33];
    const int k0 = blockIdx.y * 32, n0 = blockIdx.x * 32;
    const int tx = threadIdx.x & 31, ty = threadIdx.x >> 5;
    #pragma unroll
    for (int r = 0; r < 32; r += 8)
        tile[ty + r][tx] = W[(size_t)(k0 + ty + r) * N + n0 + tx];
    __syncthreads();
    #pragma unroll
    for (int r = 0; r < 32; r += 8)
        Th[(size_t)(n0 + ty + r) * K + k0 + tx] = __float2half(tile[tx][ty + r]);
}

// ---------------- beta/alpha: tiled fp32 GEMM --------------------------------
#define BA_SMEM (64 * 132 * 4 + 128 * 32 * 4)
__global__ void __launch_bounds__(256)
ba2_kernel(const float* __restrict__ x, const float* __restrict__ Wb,
           const float* __restrict__ Wa, float* __restrict__ beta,
           float* __restrict__ alpha)
{
    extern __shared__ float sm[];
    float* xs = sm;
    float* ws = sm + 64 * 132;

    const int tid = threadIdx.x;
    const int r0 = blockIdx.x * 64;
    const int tr = tid >> 4;
    const int tc = tid & 15;

    float acc[4][2];
    #pragma unroll
    for (int i = 0; i < 4; i++) { acc[i][0] = 0.f; acc[i][1] = 0.f; }

    for (int k0 = 0; k0 < CC; k0 += 128) {
        #pragma unroll
        for (int i = 0; i < 8; i++) {
            const int idx = tid + i * 256;
            const int row = idx >> 5, c4 = (idx & 31) * 4;
            *(float4*)&xs[row * 132 + c4] =
                *(const float4*)&x[(size_t)(r0 + row) * CC + k0 + c4];
        }
        #pragma unroll
        for (int i = 0; i < 2; i++) {
            const int idx = tid + i * 256;
            const int kk = idx >> 2, q = (idx & 3) * 4;
            *(float4*)&ws[kk * 32 + q]      = *(const float4*)&Wb[(size_t)(k0 + kk) * HH + q];
            *(float4*)&ws[kk * 32 + 16 + q] = *(const float4*)&Wa[(size_t)(k0 + kk) * HH + q];
        }
        __syncthreads();

        for (int kk = 0; kk < 128; kk++) {
            const float2 wv = *(const float2*)&ws[kk * 32 + tc * 2];
            #pragma unroll
            for (int i = 0; i < 4; i++) {
                const float xv = xs[(tr * 4 + i) * 132 + kk];
                acc[i][0] = fmaf(xv, wv.x, acc[i][0]);
                acc[i][1] = fmaf(xv, wv.y, acc[i][1]);
            }
        }
        __syncthreads();
    }

    #pragma unroll
    for (int i = 0; i < 4; i++) {
        const int row = r0 + tr * 4 + i;
        #pragma unroll
        for (int j = 0; j < 2; j++) {
            const int c = tc * 2 + j;
            const float v = 1.f / (1.f + expf(-acc[i][j]));
            if (c < 16) beta[(size_t)row * HH + c] = v;
            else        alpha[(size_t)row * HH + (c - 16)] = v;
        }
    }
}

// ---------------- conv: time-tiled -------------------------------------------
#define CONV_SMEM ((11 * 768 + 8 * 768 + 48) * 4)
__global__ void __launch_bounds__(256)
conv2_kernel(const float* __restrict__ qkvz, const float* __restrict__ conv_w,
             const float* __restrict__ conv_state, const int* __restrict__ input_pos,
             float* __restrict__ y_out)
{
    extern __shared__ float sm[];
    float* in  = sm;
    float* yb  = sm + 11 * 768;
    float* nrm = sm + 19 * 768;

    const int cg = blockIdx.x;
    const int c0 = cg * 768;
    const int tgl = blockIdx.y;
    const int b = tgl >> 8;
    const int t0 = (tgl & 255) * 8;
    const int tid = threadIdx.x;
    const float keep = (input_pos[0] == 0) ? 0.f : 1.f;

    for (int idx = tid; idx < 11 * 192; idx += 256) {
        const int r = idx / 192, c4 = (idx % 192) * 4;
        const int tau = t0 - 3 + r;
        float4 v;
        if (tau >= 0) {
            v = *(const float4*)&qkvz[((size_t)(b * TT + tau)) * QKVZ_N + c0 + c4];
        } else {
            const int slot = tau + 4;
            v.x = keep * conv_state[((size_t)b * CONV_DIM + c0 + c4 + 0) * 4 + slot];
            v.y = keep * conv_state[((size_t)b * CONV_DIM + c0 + c4 + 1) * 4 + slot];
            v.z = keep * conv_state[((size_t)b * CONV_DIM + c0 + c4 + 2) * 4 + slot];
            v.w = keep * conv_state[((size_t)b * CONV_DIM + c0 + c4 + 3) * 4 + slot];
        }
        *(float4*)&in[r * 768 + c4] = v;
    }
    __syncthreads();

    for (int idx = tid; idx < 1536; idx += 256) {
        const int t = idx / 192, c4 = (idx % 192) * 4;
        float4 o;
        float* op = (float*)&o;
        #pragma unroll
        for (int e = 0; e < 4; e++) {
            const int c = c4 + e;
            const float4 w = *(const float4*)&conv_w[(size_t)(c0 + c) * 4];
            float acc = in[(t + 0) * 768 + c] * w.x + in[(t + 1) * 768 + c] * w.y
                      + in[(t + 2) * 768 + c] * w.z + in[(t + 3) * 768 + c] * w.w;
            op[e] = acc / (1.f + expf(-acc));
        }
        *(float4*)&yb[t * 768 + c4] = o;
    }
    __syncthreads();

    {
        const int w = tid >> 5, lane = tid & 31;
        for (int p = w; p < 48; p += 8) {
            const int t = p / 6, hl = p % 6;
            const int hg = (c0 >> 7) + hl;
            float ss = 0.f;
            #pragma unroll
            for (int i = 0; i < 4; i++) {
                const float v = yb[t * 768 + hl * 128 + lane + i * 32];
                ss = fmaf(v, v, ss);
            }
            #pragma unroll
            for (int off = 16; off > 0; off >>= 1)
                ss += __shfl_xor_sync(0xffffffffu, ss, off);
            if (lane == 0)
                nrm[t * 6 + hl] = (hg < 32) ? (1.f / fmaxf(sqrtf(ss), 1e-12f)) : 1.f;
        }
    }
    __syncthreads();

    for (int idx = tid; idx < 1536; idx += 256) {
        const int t = idx / 192, c4 = (idx % 192) * 4;
        const float inv = nrm[t * 6 + (c4 >> 7)];
        float4 v = *(const float4*)&yb[t * 768 + c4];
        v.x *= inv; v.y *= inv; v.z *= inv; v.w *= inv;
        *(float4*)&y_out[((size_t)(b * TT + t0 + t)) * CONV_DIM + c0 + c4] = v;
    }
}

// ---------------- chunked recurrence: phase A --------------------------------
#define SA_QS 0
#define SA_KT (64 * 132)
#define SA_VS (SA_KT + 128 * 68)
#define SA_P  (SA_VS + 64 * 132)
#define SA_CS (SA_P + 64 * 68)
#define SA_BS (SA_CS + 64)
#define SMA_BYTES ((SA_BS + 64) * 4)

__global__ void __launch_bounds__(256)
chunkA(const float* __restrict__ y, const float* __restrict__ beta,
       const float* __restrict__ alpha, float* __restrict__ att,
       float* __restrict__ sinc, float* __restrict__ cbuf)
{
    extern __shared__ float sm[];
    float* qs  = sm + SA_QS;
    float* ksT = sm + SA_KT;
    float* vs  = sm + SA_VS;
    float* P   = sm + SA_P;
    float* cs  = sm + SA_CS;
    float* bs  = sm + SA_BS;

    const int bh = blockIdx.y, j = blockIdx.x;
    const int b = bh >> 4, h = bh & 15;
    const int t0 = j * LCH;
    const int tid = threadIdx.x;

    for (int i = tid; i < 2048; i += 256) {
        const int row = i >> 5, c4 = (i & 31) * 4;
        const float* yr = y + ((size_t)(b * TT + t0 + row)) * CONV_DIM + h * 128;
        float4 q4 = *(const float4*)(yr + c4);
        float4 k4 = *(const float4*)(yr + KEY_DIM + c4);
        float4 v4 = *(const float4*)(yr + 2 * KEY_DIM + c4);
        *(float4*)&qs[row * 132 + c4] = q4;
        ksT[(c4 + 0) * 68 + row] = k4.x;
        ksT[(c4 + 1) * 68 + row] = k4.y;
        ksT[(c4 + 2) * 68 + row] = k4.z;
        ksT[(c4 + 3) * 68 + row] = k4.w;
        *(float4*)&vs[row * 132 + c4] = v4;
    }
    if (tid < 64) {
        cs[tid] = log2f(alpha[((size_t)(b * TT + t0 + tid)) * HH + h]);
        bs[tid] = beta[((size_t)(b * TT + t0 + tid)) * HH + h];
    }
    __syncthreads();
    if (tid == 0) {
        float run = 0.f;
        for (int t = 0; t < LCH; t++) { run += cs[t]; cs[t] = run; }
    }
    __syncthreads();
    if (tid < 64) cbuf[(size_t)bh * TT + t0 + tid] = cs[tid];

    {
        const int rt = tid >> 4, ct = tid & 15;
        float acc[4][4];
        #pragma unroll
        for (int i = 0; i < 4; i++)
            #pragma unroll
            for (int j2 = 0; j2 < 4; j2++) acc[i][j2] = 0.f;
        if (ct <= rt) {
            for (int kk0 = 0; kk0 < 128; kk0 += 4) {
                float4 qv[4], kv[4];
                #pragma unroll
                for (int i = 0; i < 4; i++)
                    qv[i] = *(const float4*)&qs[(rt * 4 + i) * 132 + kk0];
                #pragma unroll
                for (int q = 0; q < 4; q++)
                    kv[q] = *(const float4*)&ksT[(kk0 + q) * 68 + ct * 4];
                #pragma unroll
                for (int q = 0; q < 4; q++) {
                    const float* kq = (const float*)&kv[q];
                    #pragma unroll
                    for (int i = 0; i < 4; i++) {
                        const float qq = ((const float*)&qv[i])[q];
                        #pragma unroll
                        for (int j2 = 0; j2 < 4; j2++)
                            acc[i][j2] = fmaf(qq, kq[j2], acc[i][j2]);
                    }
                }
            }
        }
        #pragma unroll
        for (int i = 0; i < 4; i++)
            #pragma unroll
            for (int j2 = 0; j2 < 4; j2++) {
                const int t = rt * 4 + i, tau = ct * 4 + j2;
                float val = 0.f;
                if (tau <= t)
                    val = acc[i][j2] * bs[tau] * exp2f(cs[t] - cs[tau]);
                P[t * 68 + tau] = val;
            }
    }
    __syncthreads();

    {
        const int tg = tid >> 3, dvg = tid & 7;
        const int ta = tg * 2, tb = ta + 1;
        float4 o0[4], o1[4];
        #pragma unroll
        for (int d = 0; d < 4; d++) {
            o0[d] = make_float4(0.f, 0.f, 0.f, 0.f);
            o1[d] = make_float4(0.f, 0.f, 0.f, 0.f);
        }
        for (int tau = 0; tau < LCH; tau++) {
            const float p0 = P[ta * 68 + tau];
            const float p1 = P[tb * 68 + tau];
            const float* vr = vs + tau * 132;
            #pragma unroll
            for (int d = 0; d < 4; d++) {
                const float4 vv = *(const float4*)(vr + dvg * 4 + 32 * d);
                o0[d].x = fmaf(p0, vv.x, o0[d].x); o0[d].y = fmaf(p0, vv.y, o0[d].y);
                o0[d].z = fmaf(p0, vv.z, o0[d].z); o0[d].w = fmaf(p0, vv.w, o0[d].w);
                o1[d].x = fmaf(p1, vv.x, o1[d].x); o1[d].y = fmaf(p1, vv.y, o1[d].y);
                o1[d].z = fmaf(p1, vv.z, o1[d].z); o1[d].w = fmaf(p1, vv.w, o1[d].w);
            }
        }
        float* ar0 = att + ((size_t)(b * TT + t0 + ta)) * VALUE_DIM + h * 128;
        float* ar1 = att + ((size_t)(b * TT + t0 + tb)) * VALUE_DIM + h * 128;
        #pragma unroll
        for (int d = 0; d < 4; d++) {
            *(float4*)(ar0 + dvg * 4 + 32 * d) = o0[d];
            *(float4*)(ar1 + dvg * 4 + 32 * d) = o1[d];
        }
    }

    {
        const int dkt = tid >> 4, dvt = tid & 15;
        float4 sacc[8][2];
        #pragma unroll
        for (int i = 0; i < 8; i++)
            #pragma unroll
            for (int dj = 0; dj < 2; dj++)
                sacc[i][dj] = make_float4(0.f, 0.f, 0.f, 0.f);
        const float cL = cs[63];
        for (int tau = 0; tau < LCH; tau++) {
            const float w = bs[tau] * exp2f(cL - cs[tau]);
            float kw[8];
            #pragma unroll
            for (int i = 0; i < 8; i++) kw[i] = ksT[(dkt + 16 * i) * 68 + tau] * w;
            float4 vv[2];
            #pragma unroll
            for (int dj = 0; dj < 2; dj++)
                vv[dj] = *(const float4*)&vs[tau * 132 + dvt * 4 + 64 * dj];
            #pragma unroll
            for (int i = 0; i < 8; i++)
                #pragma unroll
                for (int dj = 0; dj < 2; dj++) {
                    sacc[i][dj].x = fmaf(kw[i], vv[dj].x, sacc[i][dj].x);
                    sacc[i][dj].y = fmaf(kw[i], vv[dj].y, sacc[i][dj].y);
                    sacc[i][dj].z = fmaf(kw[i], vv[dj].z, sacc[i][dj].z);
                    sacc[i][dj].w = fmaf(kw[i], vv[dj].w, sacc[i][dj].w);
                }
        }
        float* sp = sinc + ((size_t)(bh * NCH + j)) * 16384;
        #pragma unroll
        for (int i = 0; i < 8; i++)
            #pragma unroll
            for (int dj = 0; dj < 2; dj++)
                *(float4*)&sp[(dkt + 16 * i) * 128 + dvt * 4 + 64 * dj] = sacc[i][dj];
    }
}

// ---------------- phase B: 8-way sliced scan ---------------------------------
__global__ void __launch_bounds__(256)
chunkB(const float* __restrict__ sinc, float* __restrict__ spre,
       const float* __restrict__ cbuf, const float* __restrict__ rstate,
       const int* __restrict__ input_pos)
{
    const int bh = blockIdx.y;
    const int off0 = blockIdx.x * 2048 + threadIdx.x;
    const float keep = (input_pos[0] == 0) ? 0.f : 1.f;

    float s[8];
    #pragma unroll
    for (int i = 0; i < 8; i++)
        s[i] = keep * rstate[(size_t)bh * 16384 + off0 + i * 256];

    for (int j = 0; j < NCH; j++) {
        const size_t base = ((size_t)(bh * NCH + j)) * 16384 + off0;
        #pragma unroll
        for (int i = 0; i < 8; i++)
            spre[base + i * 256] = s[i];
        const float dec = exp2f(cbuf[(size_t)bh * TT + j * LCH + 63]);
        #pragma unroll
        for (int i = 0; i < 8; i++)
            s[i] = fmaf(dec, s[i], sinc[base + i * 256]);
    }
}

// ---------------- phase C fused with gate ------------------------------------
#define SMC_BYTES (25536 * 4)
__global__ void __launch_bounds__(256)
chunkC(const float* __restrict__ y, const float* __restrict__ cbuf,
       const float* __restrict__ spre, const float* __restrict__ att,
       const float* __restrict__ qkvz, const float* __restrict__ norm_w,
       __half* __restrict__ goh)
{
    extern __shared__ float sm[];
    float* S   = sm;
    float* qs  = sm + 128 * 132;
    float* cs  = qs + 64 * 132;
    float* nws = cs + 64;

    const int bh = blockIdx.y, j = blockIdx.x;
    const int b = bh >> 4, h = bh & 15;
    const int t0 = j * LCH;
    const int tid = threadIdx.x;

    const float* sp = spre + ((size_t)(bh * NCH + j)) * 16384;
    for (int i = tid; i < 4096; i += 256) {
        const int dk = i >> 5, dv4 = (i & 31) * 4;
        *(float4*)&S[dk * 132 + dv4] = *(const float4*)&sp[dk * 128 + dv4];
    }
    for (int i = tid; i < 2048; i += 256) {
        const int row = i >> 5, c4 = (i & 31) * 4;
        const float* yr = y + ((size_t)(b * TT + t0 + row)) * CONV_DIM + h * 128;
        *(float4*)&qs[row * 132 + c4] = *(const float4*)(yr + c4);
    }
    if (tid < 64) cs[tid] = cbuf[(size_t)bh * TT + t0 + tid];
    if (tid < 128) nws[tid] = norm_w[tid];
    __syncthreads();

    const int tg = tid >> 3, dvg = tid & 7;
    const int ta = tg * 2, tb = ta + 1;
    float4 o0[4], o1[4];
    #pragma unroll
    for (int d = 0; d < 4; d++) {
        o0[d] = make_float4(0.f, 0.f, 0.f, 0.f);
        o1[d] = make_float4(0.f, 0.f, 0.f, 0.f);
    }
    for (int dk = 0; dk < 128; dk++) {
        const float q0 = qs[ta * 132 + dk];
        const float q1 = qs[tb * 132 + dk];
        const float* srow = S + dk * 132;
        #pragma unroll
        for (int d = 0; d < 4; d++) {
            const float4 sv = *(const float4*)(srow + dvg * 4 + 32 * d);
            o0[d].x = fmaf(q0, sv.x, o0[d].x); o0[d].y = fmaf(q0, sv.y, o0[d].y);
            o0[d].z = fmaf(q0, sv.z, o0[d].z); o0[d].w = fmaf(q0, sv.w, o0[d].w);
            o1[d].x = fmaf(q1, sv.x, o1[d].x); o1[d].y = fmaf(q1, sv.y, o1[d].y);
            o1[d].z = fmaf(q1, sv.z, o1[d].z); o1[d].w = fmaf(q1, sv.w, o1[d].w);
        }
    }
    const float e0 = exp2f(cs[ta]);
    const float e1 = exp2f(cs[tb]);

    const float* ar0 = att + ((size_t)(b * TT + t0 + ta)) * VALUE_DIM + h * 128;
    const float* ar1 = att + ((size_t)(b * TT + t0 + tb)) * VALUE_DIM + h * 128;
    float ss0 = 0.f, ss1 = 0.f;
    #pragma unroll
    for (int d = 0; d < 4; d++) {
        const float4 a0 = *(const float4*)(ar0 + dvg * 4 + 32 * d);
        const float4 a1 = *(const float4*)(ar1 + dvg * 4 + 32 * d);
        o0[d].x = a0.x + e0 * o0[d].x;  o0[d].y = a0.y + e0 * o0[d].y;
        o0[d].z = a0.z + e0 * o0[d].z;  o0[d].w = a0.w + e0 * o0[d].w;
        o1[d].x = a1.x + e1 * o1[d].x;  o1[d].y = a1.y + e1 * o1[d].y;
        o1[d].z = a1.z + e1 * o1[d].z;  o1[d].w = a1.w + e1 * o1[d].w;
        ss0 = fmaf(o0[d].x, o0[d].x, ss0); ss0 = fmaf(o0[d].y, o0[d].y, ss0);
        ss0 = fmaf(o0[d].z, o0[d].z, ss0); ss0 = fmaf(o0[d].w, o0[d].w, ss0);
        ss1 = fmaf(o1[d].x, o1[d].x, ss1); ss1 = fmaf(o1[d].y, o1[d].y, ss1);
        ss1 = fmaf(o1[d].z, o1[d].z, ss1); ss1 = fmaf(o1[d].w, o1[d].w, ss1);
    }
    #pragma unroll
    for (int off = 1; off < 8; off <<= 1) {
        ss0 += __shfl_xor_sync(0xffffffffu, ss0, off);
        ss1 += __shfl_xor_sync(0xffffffffu, ss1, off);
    }
    const float sc0 = rsqrtf(ss0 * (1.f / 128.f) + 1e-6f);
    const float sc1 = rsqrtf(ss1 * (1.f / 128.f) + 1e-6f);

    const float* zr0 = qkvz + ((size_t)(b * TT + t0 + ta)) * QKVZ_N + CONV_DIM + h * 128;
    const float* zr1 = qkvz + ((size_t)(b * TT + t0 + tb)) * QKVZ_N + CONV_DIM + h * 128;
    __half* gr0 = goh + ((size_t)(b * TT + t0 + ta)) * VALUE_DIM + h * 128;
    __half* gr1 = goh + ((size_t)(b * TT + t0 + tb)) * VALUE_DIM + h * 128;
    #pragma unroll
    for (int d = 0; d < 4; d++) {
        const int dvi = dvg * 4 + 32 * d;
        const float4 z0 = *(const float4*)(zr0 + dvi);
        const float4 z1 = *(const float4*)(zr1 + dvi);
        const float4 nw = *(const float4*)(nws + dvi);
        __half2 h0a = __floats2half2_rn(
            o0[d].x * sc0 * nw.x * (1.f / (1.f + expf(-z0.x))),
            o0[d].y * sc0 * nw.y * (1.f / (1.f + expf(-z0.y))));
        __half2 h0b = __floats2half2_rn(
            o0[d].z * sc0 * nw.z * (1.f / (1.f + expf(-z0.z))),
            o0[d].w * sc0 * nw.w * (1.f / (1.f + expf(-z0.w))));
        __half2 h1a = __floats2half2_rn(
            o1[d].x * sc1 * nw.x * (1.f / (1.f + expf(-z1.x))),
            o1[d].y * sc1 * nw.y * (1.f / (1.f + expf(-z1.y))));
        __half2 h1b = __floats2half2_rn(
            o1[d].z * sc1 * nw.z * (1.f / (1.f + expf(-z1.z))),
            o1[d].w * sc1 * nw.w * (1.f / (1.f + expf(-z1.w))));
        *(__half2*)(gr0 + dvi)     = h0a;
        *(__half2*)(gr0 + dvi + 2) = h0b;
        *(__half2*)(gr1 + dvi)     = h1a;
        *(__half2*)(gr1 + dvi + 2) = h1b;
    }
}

// ---------------- launch -----------------------------------------------------
extern "C" void kernel_launch(void* const* d_in, const int* in_sizes, int n_in,
                              void* d_out, int out_size)
{
    const float* x          = (const float*)d_in[0];
    const int*   input_pos  = (const int*)  d_in[1];
    const float* W_qkvz     = (const float*)d_in[2];
    const float* W_b        = (const float*)d_in[3];
    const float* W_a        = (const float*)d_in[4];
    const float* conv_w     = (const float*)d_in[5];
    const float* norm_w     = (const float*)d_in[6];
    const float* W_out      = (const float*)d_in[7];
    const float* conv_state = (const float*)d_in[8];
    const float* rec_state  = (const float*)d_in[9];
    float* out = (float*)d_out;

    float *qkvz, *y, *beta, *alpha, *attb, *sinc, *spre, *cbuf;
    __half *xh, *wqt, *wot, *goh;
    cudaGetSymbolAddress((void**)&qkvz, g_qkvz);
    cudaGetSymbolAddress((void**)&y,    g_y);
    cudaGetSymbolAddress((void**)&beta, g_beta);
    cudaGetSymbolAddress((void**)&alpha,g_alpha);
    cudaGetSymbolAddress((void**)&attb, g_att);
    cudaGetSymbolAddress((void**)&sinc, g_sinc);
    cudaGetSymbolAddress((void**)&spre, g_spre);
    cudaGetSymbolAddress((void**)&cbuf, g_cc);
    cudaGetSymbolAddress((void**)&xh,  g_xh);
    cudaGetSymbolAddress((void**)&wqt, g_wqt);
    cudaGetSymbolAddress((void**)&wot, g_wot);
    cudaGetSymbolAddress((void**)&goh, g_goh);

    static cudaStream_t s1 = nullptr, s2 = nullptr;
    static cudaEvent_t evFork = nullptr, evWq = nullptr, evBA = nullptr, evZ = nullptr;
    if (s1 == nullptr) {
        cudaStreamCreateWithFlags(&s1, cudaStreamNonBlocking);
        cudaStreamCreateWithFlags(&s2, cudaStreamNonBlocking);
        cudaEventCreateWithFlags(&evFork, cudaEventDisableTiming);
        cudaEventCreateWithFlags(&evWq, cudaEventDisableTiming);
        cudaEventCreateWithFlags(&evBA, cudaEventDisableTiming);
        cudaEventCreateWithFlags(&evZ, cudaEventDisableTiming);
        cudaFuncSetAttribute(h16gemm, cudaFuncAttributeMaxDynamicSharedMemorySize, GEMM_SMEM);
        cudaFuncSetAttribute(chunkA, cudaFuncAttributeMaxDynamicSharedMemorySize, SMA_BYTES);
        cudaFuncSetAttribute(chunkC, cudaFuncAttributeMaxDynamicSharedMemorySize, SMC_BYTES);
        cudaFuncSetAttribute(ba2_kernel, cudaFuncAttributeMaxDynamicSharedMemorySize, BA_SMEM);
        cudaFuncSetAttribute(conv2_kernel, cudaFuncAttributeMaxDynamicSharedMemorySize, CONV_SMEM);
    }

    // fork
    cudaEventRecord(evFork, 0);
    cudaStreamWaitEvent(s1, evFork, 0);
    cudaStreamWaitEvent(s2, evFork, 0);

    // s1: transpose W_qkvz (feeds GEMM1)
    transpose_half<<<dim3(QKVZ_N / 32, CC / 32), 256, 0, s1>>>(W_qkvz, wqt, CC, QKVZ_N);
    cudaEventRecord(evWq, s1);

    // s2: ba2 + transpose W_out
    ba2_kernel<<<BT / 64, 256, BA_SMEM, s2>>>(x, W_b, W_a, beta, alpha);
    transpose_half<<<dim3(CC / 32, CC / 32), 256, 0, s2>>>(W_out, wot, CC, CC);
    cudaEventRecord(evBA, s2);

    // main: to_half(x), then GEMM1a (qkv columns, N=6144)
    to_half<<<(BT * CC / 8 + 255) / 256, 256>>>(x, xh, BT * CC / 8);
    cudaStreamWaitEvent(0, evWq, 0);
    h16gemm<<<dim3(CONV_DIM / 128, BT / 128), 128, GEMM_SMEM>>>(
        xh, wqt, qkvz, QKVZ_N, CC);
    cudaEventRecord(evFork, 0);   // "GEMM1a done / xh+wqt ready"

    // s1: z-block GEMM (N=2048) concurrent with conv/chunkA
    cudaStreamWaitEvent(s1, evFork, 0);
    h16gemm<<<dim3(VALUE_DIM / 128, BT / 128), 128, GEMM_SMEM, s1>>>(
        xh, wqt + (size_t)CONV_DIM * CC, qkvz + CONV_DIM, QKVZ_N, CC);
    cudaEventRecord(evZ, s1);

    // main: conv (reads only qkv columns)
    conv2_kernel<<<dim3(8, BT / 8), 256, CONV_SMEM>>>(
        qkvz, conv_w, conv_state, input_pos, y);

    cudaStreamWaitEvent(0, evBA, 0);
    chunkA<<<dim3(NCH, BH), 256, SMA_BYTES>>>(y, beta, alpha, attb, sinc, cbuf);
    chunkB<<<dim3(8, BH), 256>>>(sinc, spre, cbuf, rec_state, input_pos);
    cudaStreamWaitEvent(0, evZ, 0);
    chunkC<<<dim3(NCH, BH), 256, SMC_BYTES>>>(y, cbuf, spre, attb, qkvz,
                                              norm_w, goh);
    h16gemm<<<dim3(CC / 128, BT / 128), 128, GEMM_SMEM>>>(
        goh, wot, out, CC, CC);
}